// round 1
// baseline (speedup 1.0000x reference)
#include <cuda_runtime.h>

// Problem constants
#define B_      16
#define QLEN    1024
#define CDIM    1280
#define LLEN    477
#define CROSSD  2048
#define NTOK    200
#define HEADS   20
#define HD      64
#define EHS_LEN 77           // 477 - 200 - 200
#define ATTN_SCALE 0.125f    // 1/sqrt(64)

// ---------------- scratch (device globals; no runtime allocation) ----------
__device__ float g_q [B_*QLEN*CDIM];    // query projection
__device__ float g_o [B_*QLEN*CDIM];    // attention output accumulator
__device__ float g_k [B_*EHS_LEN*CDIM];
__device__ float g_v [B_*EHS_LEN*CDIM];
__device__ float g_bk[B_*NTOK*CDIM];
__device__ float g_bv[B_*NTOK*CDIM];
__device__ float g_ck[B_*NTOK*CDIM];
__device__ float g_cv[B_*NTOK*CDIM];

// ---------------- GEMM: C[b,m,n] = sum_k A[b,m,k] * W[n,k] (+bias) ---------
// A: row stride ldA, batch stride bsA (pre-offset for row windows)
// W: [N,K] row-major. C: row stride N, batch stride bsC.
#define BM 128
#define BN 128
#define BKD 16

__global__ __launch_bounds__(256)
void gemm_nt_kernel(const float* __restrict__ A, int ldA, long long bsA,
                    const float* __restrict__ W,
                    const float* __restrict__ bias,
                    float* __restrict__ Cdst, long long bsC,
                    int S, int N, int K)
{
    const int b  = blockIdx.z;
    const float* Ab = A + (long long)b * bsA;
    float*       Cb = Cdst + (long long)b * bsC;
    const int m0 = blockIdx.y * BM;
    const int n0 = blockIdx.x * BN;

    __shared__ float As[BKD][BM + 4];
    __shared__ float Bs[BKD][BN + 4];

    const int tid = threadIdx.x;
    const int tx  = tid & 15;   // 0..15 -> 8 output cols each
    const int ty  = tid >> 4;   // 0..15 -> 8 output rows each

    float acc[8][8];
    #pragma unroll
    for (int i = 0; i < 8; ++i)
        #pragma unroll
        for (int j = 0; j < 8; ++j) acc[i][j] = 0.f;

    for (int k0 = 0; k0 < K; k0 += BKD) {
        // Load A tile (128x16), transposed into As[k][m]
        #pragma unroll
        for (int i = 0; i < 2; ++i) {
            int lin = tid + i * 256;
            int m  = lin >> 2;
            int kq = lin & 3;
            float4 v = make_float4(0.f, 0.f, 0.f, 0.f);
            if (m0 + m < S)
                v = *(const float4*)&Ab[(long long)(m0 + m) * ldA + k0 + kq * 4];
            As[kq*4+0][m] = v.x; As[kq*4+1][m] = v.y;
            As[kq*4+2][m] = v.z; As[kq*4+3][m] = v.w;
        }
        // Load W tile (128x16) -> Bs[k][n]   (N is a multiple of 128)
        #pragma unroll
        for (int i = 0; i < 2; ++i) {
            int lin = tid + i * 256;
            int n  = lin >> 2;
            int kq = lin & 3;
            float4 v = *(const float4*)&W[(long long)(n0 + n) * K + k0 + kq * 4];
            Bs[kq*4+0][n] = v.x; Bs[kq*4+1][n] = v.y;
            Bs[kq*4+2][n] = v.z; Bs[kq*4+3][n] = v.w;
        }
        __syncthreads();

        #pragma unroll
        for (int kk = 0; kk < BKD; ++kk) {
            float a[8], w[8];
            *(float4*)&a[0] = *(const float4*)&As[kk][ty * 8];
            *(float4*)&a[4] = *(const float4*)&As[kk][ty * 8 + 4];
            *(float4*)&w[0] = *(const float4*)&Bs[kk][tx * 8];
            *(float4*)&w[4] = *(const float4*)&Bs[kk][tx * 8 + 4];
            #pragma unroll
            for (int i = 0; i < 8; ++i)
                #pragma unroll
                for (int j = 0; j < 8; ++j)
                    acc[i][j] += a[i] * w[j];
        }
        __syncthreads();
    }

    #pragma unroll
    for (int i = 0; i < 8; ++i) {
        int m = m0 + ty * 8 + i;
        if (m >= S) continue;
        float* crow = Cb + (long long)m * N + n0 + tx * 8;
        float out[8];
        #pragma unroll
        for (int j = 0; j < 8; ++j) {
            float v = acc[i][j];
            if (bias) v += bias[n0 + tx * 8 + j];
            out[j] = v;
        }
        *(float4*)&crow[0] = *(float4*)&out[0];
        *(float4*)&crow[4] = *(float4*)&out[4];
    }
}

// ---------------- Fused attention (online softmax, small KV) ---------------
// Q,K,V,O: (B, S, C) fp32, head h = columns [h*64, h*64+64)
// out[q] = softmax(scale * Q K^T) V; accumulate==1 adds onto existing O.
#define TQ 32
#define TK 64

__global__ __launch_bounds__(256)
void attn_kernel(const float* __restrict__ Qg, const float* __restrict__ Kg,
                 const float* __restrict__ Vg, float* __restrict__ Og,
                 int Sq, int Skv, int accumulate)
{
    const int b  = blockIdx.z;
    const int h  = blockIdx.y;
    const int q0 = blockIdx.x * TQ;

    const float* Qb = Qg + ((long long)b * Sq)  * CDIM + h * HD;
    const float* Kb = Kg + ((long long)b * Skv) * CDIM + h * HD;
    const float* Vb = Vg + ((long long)b * Skv) * CDIM + h * HD;
    float*       Ob = Og + ((long long)b * Sq)  * CDIM + h * HD;

    __shared__ float Qs[TQ][HD];
    __shared__ float Ks[TK][HD + 4];
    __shared__ float Vs[TK][HD + 4];
    __shared__ float Ps[TQ][TK + 1];

    const int tid = threadIdx.x;           // 256 threads
    // Load Q tile: 32x64 floats, 2 float4 per thread
    #pragma unroll
    for (int i = 0; i < 2; ++i) {
        int lin = tid + i * 256;
        int q  = lin >> 4;
        int c4 = lin & 15;
        float4 v = make_float4(0.f, 0.f, 0.f, 0.f);
        if (q0 + q < Sq)
            v = *(const float4*)&Qb[(long long)(q0 + q) * CDIM + c4 * 4];
        *(float4*)&Qs[q][c4 * 4] = v;
    }

    const int q  = tid >> 3;   // 0..31: query within tile
    const int g  = tid & 7;    // 0..7 : lane group
    const int d0 = g * 8;      // 8 head-dim cols per thread

    float m = -1e30f, l = 0.f;
    float acc[8];
    #pragma unroll
    for (int d = 0; d < 8; ++d) acc[d] = 0.f;

    for (int kv0 = 0; kv0 < Skv; kv0 += TK) {
        __syncthreads();  // protect prior-chunk Ks/Vs reads (and Qs on iter 0)
        // Load K/V chunk: 64x64 each, 4 float4 per thread per tensor
        #pragma unroll
        for (int i = 0; i < 4; ++i) {
            int lin = tid + i * 256;       // 0..1023
            int j  = lin >> 4;             // 0..63
            int c4 = lin & 15;
            float4 kv = make_float4(0.f, 0.f, 0.f, 0.f);
            float4 vv = make_float4(0.f, 0.f, 0.f, 0.f);
            if (kv0 + j < Skv) {
                kv = *(const float4*)&Kb[(long long)(kv0 + j) * CDIM + c4 * 4];
                vv = *(const float4*)&Vb[(long long)(kv0 + j) * CDIM + c4 * 4];
            }
            *(float4*)&Ks[j][c4 * 4] = kv;
            *(float4*)&Vs[j][c4 * 4] = vv;
        }
        __syncthreads();

        // Logits: this thread covers j = jj*8 + g
        float s[8];
        #pragma unroll
        for (int jj = 0; jj < 8; ++jj) s[jj] = 0.f;
        #pragma unroll
        for (int k = 0; k < HD; k += 4) {
            float4 qv = *(const float4*)&Qs[q][k];
            #pragma unroll
            for (int jj = 0; jj < 8; ++jj) {
                float4 kv = *(const float4*)&Ks[jj * 8 + g][k];
                s[jj] += qv.x * kv.x + qv.y * kv.y + qv.z * kv.z + qv.w * kv.w;
            }
        }

        float lmax = -1e30f;
        #pragma unroll
        for (int jj = 0; jj < 8; ++jj) {
            int j = jj * 8 + g;
            if (kv0 + j < Skv) {
                s[jj] *= ATTN_SCALE;
                lmax = fmaxf(lmax, s[jj]);
            } else {
                s[jj] = -1e30f;
            }
        }
        // reduce max across the 8 lanes sharing q
        #pragma unroll
        for (int off = 4; off >= 1; off >>= 1)
            lmax = fmaxf(lmax, __shfl_xor_sync(0xffffffffu, lmax, off));

        float mnew = fmaxf(m, lmax);
        float corr = __expf(m - mnew);
        float lsum = 0.f;
        #pragma unroll
        for (int jj = 0; jj < 8; ++jj) {
            float p = __expf(s[jj] - mnew);
            lsum += p;
            Ps[q][jj * 8 + g] = p;
        }
        #pragma unroll
        for (int off = 4; off >= 1; off >>= 1)
            lsum += __shfl_xor_sync(0xffffffffu, lsum, off);

        l = l * corr + lsum;
        m = mnew;
        #pragma unroll
        for (int d = 0; d < 8; ++d) acc[d] *= corr;
        __syncwarp();

        // PV: acc[d] += sum_j p[q][j] * V[j][d]
        #pragma unroll 4
        for (int j = 0; j < TK; ++j) {
            float p = Ps[q][j];
            float4 v0 = *(const float4*)&Vs[j][d0];
            float4 v1 = *(const float4*)&Vs[j][d0 + 4];
            acc[0] += p * v0.x; acc[1] += p * v0.y;
            acc[2] += p * v0.z; acc[3] += p * v0.w;
            acc[4] += p * v1.x; acc[5] += p * v1.y;
            acc[6] += p * v1.z; acc[7] += p * v1.w;
        }
    }

    if (q0 + q < Sq) {
        float inv = 1.f / l;
        float* op = Ob + (long long)(q0 + q) * CDIM + d0;
        if (accumulate) {
            #pragma unroll
            for (int d = 0; d < 8; ++d) op[d] += acc[d] * inv;
        } else {
            float o[8];
            #pragma unroll
            for (int d = 0; d < 8; ++d) o[d] = acc[d] * inv;
            *(float4*)&op[0] = *(float4*)&o[0];
            *(float4*)&op[4] = *(float4*)&o[4];
        }
    }
}

// ---------------- host orchestration ---------------------------------------
static inline void launch_gemm(const float* A, int ldA, long long bsA,
                               const float* W, const float* bias,
                               float* C, long long bsC, int S, int N, int K)
{
    dim3 grid(N / BN, (S + BM - 1) / BM, B_);
    gemm_nt_kernel<<<grid, 256>>>(A, ldA, bsA, W, bias, C, bsC, S, N, K);
}

static inline void launch_attn(const float* Q, const float* K, const float* V,
                               float* O, int Sq, int Skv, int accumulate)
{
    dim3 grid((Sq + TQ - 1) / TQ, HEADS, B_);
    attn_kernel<<<grid, 256>>>(Q, K, V, O, Sq, Skv, accumulate);
}

extern "C" void kernel_launch(void* const* d_in, const int* in_sizes, int n_in,
                              void* d_out, int out_size)
{
    const float* hidden = (const float*)d_in[0];   // (16,1024,1280)
    const float* enc    = (const float*)d_in[1];   // (16,477,2048)
    const float* w_q    = (const float*)d_in[2];   // (1280,1280)
    const float* w_k    = (const float*)d_in[3];   // (1280,2048)
    const float* w_v    = (const float*)d_in[4];
    const float* w_kb   = (const float*)d_in[5];
    const float* w_vb   = (const float*)d_in[6];
    const float* w_kc   = (const float*)d_in[7];
    const float* w_vc   = (const float*)d_in[8];
    const float* w_out  = (const float*)d_in[9];   // (1280,1280)
    const float* b_out  = (const float*)d_in[10];  // (1280,)
    float* out = (float*)d_out;

    float *pq, *po, *pk, *pv, *pbk, *pbv, *pck, *pcv;
    cudaGetSymbolAddress((void**)&pq,  g_q);
    cudaGetSymbolAddress((void**)&po,  g_o);
    cudaGetSymbolAddress((void**)&pk,  g_k);
    cudaGetSymbolAddress((void**)&pv,  g_v);
    cudaGetSymbolAddress((void**)&pbk, g_bk);
    cudaGetSymbolAddress((void**)&pbv, g_bv);
    cudaGetSymbolAddress((void**)&pck, g_ck);
    cudaGetSymbolAddress((void**)&pcv, g_cv);

    const long long bsH   = (long long)QLEN * CDIM;
    const long long bsEnc = (long long)LLEN * CROSSD;

    // Projections
    launch_gemm(hidden, CDIM, bsH, w_q, nullptr, pq, bsH, QLEN, CDIM, CDIM);
    launch_gemm(enc,                      CROSSD, bsEnc, w_k,  nullptr, pk,  (long long)EHS_LEN*CDIM, EHS_LEN, CDIM, CROSSD);
    launch_gemm(enc,                      CROSSD, bsEnc, w_v,  nullptr, pv,  (long long)EHS_LEN*CDIM, EHS_LEN, CDIM, CROSSD);
    launch_gemm(enc + (long long)EHS_LEN*CROSSD,           CROSSD, bsEnc, w_kb, nullptr, pbk, (long long)NTOK*CDIM, NTOK, CDIM, CROSSD);
    launch_gemm(enc + (long long)EHS_LEN*CROSSD,           CROSSD, bsEnc, w_vb, nullptr, pbv, (long long)NTOK*CDIM, NTOK, CDIM, CROSSD);
    launch_gemm(enc + (long long)(EHS_LEN + NTOK)*CROSSD,  CROSSD, bsEnc, w_kc, nullptr, pck, (long long)NTOK*CDIM, NTOK, CDIM, CROSSD);
    launch_gemm(enc + (long long)(EHS_LEN + NTOK)*CROSSD,  CROSSD, bsEnc, w_vc, nullptr, pcv, (long long)NTOK*CDIM, NTOK, CDIM, CROSSD);

    // Attention chain
    launch_attn(pq,  pk,  pv,  po,  QLEN, EHS_LEN, 0);  // main cross-attn
    launch_attn(pbk, pck, pcv, pbk, NTOK, NTOK,    1);  // bk += mea(bk,ck,cv)
    launch_attn(pbv, pck, pcv, pbv, NTOK, NTOK,    1);  // bv += mea(bv,ck,cv)
    launch_attn(pq,  pbk, pbv, po,  QLEN, NTOK,    1);  // out += box attention

    // Output projection + bias
    launch_gemm(po, CDIM, bsH, w_out, b_out, out, bsH, QLEN, CDIM, CDIM);
}

// round 3
// speedup vs baseline: 1.7463x; 1.7463x over previous
#include <cuda_runtime.h>
#include <cuda_bf16.h>
#include <cstdint>

// Problem constants
#define B_      16
#define QLEN    1024
#define CDIM    1280
#define LLEN    477
#define CROSSD  2048
#define NTOK    200
#define HEADS   20
#define HD      64
#define EHS_LEN 77           // 477 - 200 - 200
#define ATTN_SCALE 0.125f    // 1/sqrt(64)

// ---------------- scratch (device globals; no runtime allocation) ----------
__device__ float g_q [B_*QLEN*CDIM];
__device__ float g_o [B_*QLEN*CDIM];
__device__ float g_k [B_*EHS_LEN*CDIM];
__device__ float g_v [B_*EHS_LEN*CDIM];
__device__ float g_bk[B_*NTOK*CDIM];
__device__ float g_bv[B_*NTOK*CDIM];
__device__ float g_ck[B_*NTOK*CDIM];
__device__ float g_cv[B_*NTOK*CDIM];

// bf16 hi/lo splits
__device__ __nv_bfloat16 s_hid_h[B_*QLEN*CDIM],  s_hid_l[B_*QLEN*CDIM];
__device__ __nv_bfloat16 s_enc_h[B_*LLEN*CROSSD], s_enc_l[B_*LLEN*CROSSD];
__device__ __nv_bfloat16 s_po_h [B_*QLEN*CDIM],  s_po_l [B_*QLEN*CDIM];
__device__ __nv_bfloat16 s_wq_h [CDIM*CDIM],   s_wq_l [CDIM*CDIM];
__device__ __nv_bfloat16 s_wk_h [CDIM*CROSSD], s_wk_l [CDIM*CROSSD];
__device__ __nv_bfloat16 s_wv_h [CDIM*CROSSD], s_wv_l [CDIM*CROSSD];
__device__ __nv_bfloat16 s_wkb_h[CDIM*CROSSD], s_wkb_l[CDIM*CROSSD];
__device__ __nv_bfloat16 s_wvb_h[CDIM*CROSSD], s_wvb_l[CDIM*CROSSD];
__device__ __nv_bfloat16 s_wkc_h[CDIM*CROSSD], s_wkc_l[CDIM*CROSSD];
__device__ __nv_bfloat16 s_wvc_h[CDIM*CROSSD], s_wvc_l[CDIM*CROSSD];
__device__ __nv_bfloat16 s_wo_h [CDIM*CDIM],   s_wo_l [CDIM*CDIM];

// ---------------- helpers ---------------------------------------------------
__device__ __forceinline__ uint32_t smem_u32(const void* p) {
    uint32_t a;
    asm("{ .reg .u64 t; cvta.to.shared.u64 t, %1; cvt.u32.u64 %0, t; }"
        : "=r"(a) : "l"(p));
    return a;
}

__device__ __forceinline__ void cp_async16(uint32_t dst, const void* src, int pred) {
    int sz = pred ? 16 : 0;
    asm volatile("cp.async.cg.shared.global [%0], [%1], 16, %2;"
                 :: "r"(dst), "l"(src), "r"(sz) : "memory");
}
__device__ __forceinline__ void cp_commit() {
    asm volatile("cp.async.commit_group;" ::: "memory");
}
template <int N>
__device__ __forceinline__ void cp_wait() {
    asm volatile("cp.async.wait_group %0;" :: "n"(N) : "memory");
}

__device__ __forceinline__ void ldm4(uint32_t& r0, uint32_t& r1, uint32_t& r2,
                                     uint32_t& r3, uint32_t addr) {
    asm volatile("ldmatrix.sync.aligned.m8n8.x4.shared.b16 {%0,%1,%2,%3}, [%4];"
                 : "=r"(r0), "=r"(r1), "=r"(r2), "=r"(r3) : "r"(addr));
}

__device__ __forceinline__ void mma16816(float* c, const uint32_t* a, const uint32_t* b) {
    asm volatile(
        "mma.sync.aligned.m16n8k16.row.col.f32.bf16.bf16.f32 "
        "{%0,%1,%2,%3}, {%4,%5,%6,%7}, {%8,%9}, {%0,%1,%2,%3};"
        : "+f"(c[0]), "+f"(c[1]), "+f"(c[2]), "+f"(c[3])
        : "r"(a[0]), "r"(a[1]), "r"(a[2]), "r"(a[3]), "r"(b[0]), "r"(b[1]));
}

// ---------------- split kernel: fp32 -> (bf16 hi, bf16 lo) -----------------
__global__ void split_kernel(const float4* __restrict__ x,
                             __nv_bfloat162* __restrict__ h,
                             __nv_bfloat162* __restrict__ l, int n4)
{
    for (int i = blockIdx.x * blockDim.x + threadIdx.x; i < n4;
         i += gridDim.x * blockDim.x) {
        float4 v = x[i];
        __nv_bfloat16 hx = __float2bfloat16_rn(v.x);
        __nv_bfloat16 hy = __float2bfloat16_rn(v.y);
        __nv_bfloat16 hz = __float2bfloat16_rn(v.z);
        __nv_bfloat16 hw = __float2bfloat16_rn(v.w);
        h[2*i]   = __halves2bfloat162(hx, hy);
        h[2*i+1] = __halves2bfloat162(hz, hw);
        l[2*i]   = __halves2bfloat162(__float2bfloat16_rn(v.x - __bfloat162float(hx)),
                                      __float2bfloat16_rn(v.y - __bfloat162float(hy)));
        l[2*i+1] = __halves2bfloat162(__float2bfloat16_rn(v.z - __bfloat162float(hz)),
                                      __float2bfloat16_rn(v.w - __bfloat162float(hw)));
    }
}

// ---------------- 3xBF16 tensor-core GEMM ----------------------------------
// C[g, n] = sum_k A[g,k] * W[n,k] (+bias).  A rows flattened across batches:
// row g -> batch b = g/RB, local row r = g%RB, element offset b*strideA + r*K.
// Block tile 128x128, K-chunk 32. smem per stage: Ah|Al|Bh|Bl, each 128x32
// bf16 (64B rows, xor-swizzled 16B chunks). Double buffered via cp.async.
#define KCH 32
#define GSTAGE 32768u
#define GEMM_SMEM 65536u

__global__ __launch_bounds__(256)
void gemm_bf16x3(const __nv_bfloat16* __restrict__ Ah,
                 const __nv_bfloat16* __restrict__ Al,
                 const __nv_bfloat16* __restrict__ Wh,
                 const __nv_bfloat16* __restrict__ Wl,
                 const float* __restrict__ bias,
                 float* __restrict__ C,
                 int Mtot, int RB, long long strideA, long long strideC,
                 int N, int K)
{
    extern __shared__ char smem[];
    const uint32_t sm = smem_u32(smem);

    const int t    = threadIdx.x;
    const int lane = t & 31;
    const int wid  = t >> 5;
    const int wm   = wid & 1;    // 2 M-warps x 64 rows
    const int wn   = wid >> 1;   // 4 N-warps x 32 cols
    const int m0   = blockIdx.y * 128;
    const int n0   = blockIdx.x * 128;

    float acc[4][4][4];
    #pragma unroll
    for (int i = 0; i < 4; ++i)
        #pragma unroll
        for (int j = 0; j < 4; ++j)
            #pragma unroll
            for (int k = 0; k < 4; ++k) acc[i][j][k] = 0.f;

    const int NC = K / KCH;

    // -------- staging: 8 cp.asyncs of 16B per thread per chunk
    auto issue = [&](int c) {
        const int k0 = c * KCH;
        const uint32_t sbase = sm + (uint32_t)(c & 1) * GSTAGE;
        #pragma unroll
        for (int i = 0; i < 2; ++i) {
            int task = t + i * 256;          // 0..511
            int gr   = task >> 2;            // tile row 0..127
            int kc   = task & 3;             // 16B chunk (8 bf16)
            uint32_t sw  = (uint32_t)(kc ^ ((gr >> 1) & 3));
            uint32_t dst = sbase + (uint32_t)gr * 64u + sw * 16u;
            // A (hi, lo)
            int grow = m0 + gr;
            int pred = grow < Mtot;
            long long off = 0;
            if (pred) {
                int b = grow / RB, r = grow % RB;
                off = (long long)b * strideA + (long long)r * K + k0 + kc * 8;
            }
            cp_async16(dst,         Ah + off, pred);
            cp_async16(dst + 8192u, Al + off, pred);
            // B (hi, lo) — N is a multiple of 128
            long long boff = (long long)(n0 + gr) * K + k0 + kc * 8;
            cp_async16(dst + 16384u, Wh + boff, 1);
            cp_async16(dst + 24576u, Wl + boff, 1);
        }
        cp_commit();
    };

    auto compute = [&](int c) {
        const uint32_t sbase = sm + (uint32_t)(c & 1) * GSTAGE;
        #pragma unroll
        for (int ks = 0; ks < 2; ++ks) {
            uint32_t af[16], bh[8], bl[8];
            // A-hi fragments (4 x m16)
            #pragma unroll
            for (int mt = 0; mt < 4; ++mt) {
                int arow = wm * 64 + mt * 16 + (lane & 15);
                int ach  = ks * 2 + (lane >> 4);
                uint32_t addr = sbase + (uint32_t)arow * 64u
                              + (uint32_t)((ach ^ ((arow >> 1) & 3)) * 16);
                ldm4(af[mt*4], af[mt*4+1], af[mt*4+2], af[mt*4+3], addr);
            }
            // B-hi fragments (2 x n16)
            #pragma unroll
            for (int nt2 = 0; nt2 < 2; ++nt2) {
                int brow = wn * 32 + nt2 * 16 + ((lane >> 4) & 1) * 8 + (lane & 7);
                int bch  = ks * 2 + ((lane >> 3) & 1);
                uint32_t addr = sbase + 16384u + (uint32_t)brow * 64u
                              + (uint32_t)((bch ^ ((brow >> 1) & 3)) * 16);
                ldm4(bh[nt2*4], bh[nt2*4+1], bh[nt2*4+2], bh[nt2*4+3], addr);
            }
            // pass 1: Ah x Bh
            #pragma unroll
            for (int mt = 0; mt < 4; ++mt)
                #pragma unroll
                for (int nt = 0; nt < 4; ++nt)
                    mma16816(acc[mt][nt], &af[mt*4], &bh[(nt >> 1)*4 + (nt & 1)*2]);
            // B-lo fragments
            #pragma unroll
            for (int nt2 = 0; nt2 < 2; ++nt2) {
                int brow = wn * 32 + nt2 * 16 + ((lane >> 4) & 1) * 8 + (lane & 7);
                int bch  = ks * 2 + ((lane >> 3) & 1);
                uint32_t addr = sbase + 24576u + (uint32_t)brow * 64u
                              + (uint32_t)((bch ^ ((brow >> 1) & 3)) * 16);
                ldm4(bl[nt2*4], bl[nt2*4+1], bl[nt2*4+2], bl[nt2*4+3], addr);
            }
            // pass 2: Ah x Bl
            #pragma unroll
            for (int mt = 0; mt < 4; ++mt)
                #pragma unroll
                for (int nt = 0; nt < 4; ++nt)
                    mma16816(acc[mt][nt], &af[mt*4], &bl[(nt >> 1)*4 + (nt & 1)*2]);
            // A-lo fragments (reuse af regs)
            #pragma unroll
            for (int mt = 0; mt < 4; ++mt) {
                int arow = wm * 64 + mt * 16 + (lane & 15);
                int ach  = ks * 2 + (lane >> 4);
                uint32_t addr = sbase + 8192u + (uint32_t)arow * 64u
                              + (uint32_t)((ach ^ ((arow >> 1) & 3)) * 16);
                ldm4(af[mt*4], af[mt*4+1], af[mt*4+2], af[mt*4+3], addr);
            }
            // pass 3: Al x Bh
            #pragma unroll
            for (int mt = 0; mt < 4; ++mt)
                #pragma unroll
                for (int nt = 0; nt < 4; ++nt)
                    mma16816(acc[mt][nt], &af[mt*4], &bh[(nt >> 1)*4 + (nt & 1)*2]);
        }
    };

    issue(0);
    for (int c = 0; c < NC; ++c) {
        if (c + 1 < NC) { issue(c + 1); cp_wait<1>(); }
        else            { cp_wait<0>(); }
        __syncthreads();
        compute(c);
        __syncthreads();
    }

    // -------- epilogue: direct global stores (float2 per mma tile row)
    const int g  = lane >> 2;
    const int q4 = lane & 3;
    #pragma unroll
    for (int mt = 0; mt < 4; ++mt) {
        #pragma unroll
        for (int half = 0; half < 2; ++half) {
            int grow = m0 + wm * 64 + mt * 16 + g + half * 8;
            if (grow < Mtot) {
                int b = grow / RB, r = grow % RB;
                float* crow = C + (long long)b * strideC + (long long)r * N
                            + n0 + wn * 32;
                #pragma unroll
                for (int nt = 0; nt < 4; ++nt) {
                    int ncol = nt * 8 + q4 * 2;
                    float2 v;
                    v.x = acc[mt][nt][half*2+0];
                    v.y = acc[mt][nt][half*2+1];
                    if (bias) {
                        v.x += bias[n0 + wn*32 + ncol];
                        v.y += bias[n0 + wn*32 + ncol + 1];
                    }
                    *(float2*)&crow[ncol] = v;
                }
            }
        }
    }
}

// ---------------- Fused attention (online softmax, small KV) ---------------
#define TQ 32
#define TK 64

__global__ __launch_bounds__(256)
void attn_kernel(const float* __restrict__ Qg, const float* __restrict__ Kg,
                 const float* __restrict__ Vg, float* __restrict__ Og,
                 int Sq, int Skv, int accumulate)
{
    const int b  = blockIdx.z;
    const int h  = blockIdx.y;
    const int q0 = blockIdx.x * TQ;

    const float* Qb = Qg + ((long long)b * Sq)  * CDIM + h * HD;
    const float* Kb = Kg + ((long long)b * Skv) * CDIM + h * HD;
    const float* Vb = Vg + ((long long)b * Skv) * CDIM + h * HD;
    float*       Ob = Og + ((long long)b * Sq)  * CDIM + h * HD;

    __shared__ float Qs[TQ][HD];
    __shared__ float Ks[TK][HD + 4];
    __shared__ float Vs[TK][HD + 4];
    __shared__ float Ps[TQ][TK + 1];

    const int tid = threadIdx.x;
    #pragma unroll
    for (int i = 0; i < 2; ++i) {
        int lin = tid + i * 256;
        int q  = lin >> 4;
        int c4 = lin & 15;
        float4 v = make_float4(0.f, 0.f, 0.f, 0.f);
        if (q0 + q < Sq)
            v = *(const float4*)&Qb[(long long)(q0 + q) * CDIM + c4 * 4];
        *(float4*)&Qs[q][c4 * 4] = v;
    }

    const int q  = tid >> 3;
    const int g  = tid & 7;
    const int d0 = g * 8;

    float m = -1e30f, l = 0.f;
    float acc[8];
    #pragma unroll
    for (int d = 0; d < 8; ++d) acc[d] = 0.f;

    for (int kv0 = 0; kv0 < Skv; kv0 += TK) {
        __syncthreads();
        #pragma unroll
        for (int i = 0; i < 4; ++i) {
            int lin = tid + i * 256;
            int j  = lin >> 4;
            int c4 = lin & 15;
            float4 kv = make_float4(0.f, 0.f, 0.f, 0.f);
            float4 vv = make_float4(0.f, 0.f, 0.f, 0.f);
            if (kv0 + j < Skv) {
                kv = *(const float4*)&Kb[(long long)(kv0 + j) * CDIM + c4 * 4];
                vv = *(const float4*)&Vb[(long long)(kv0 + j) * CDIM + c4 * 4];
            }
            *(float4*)&Ks[j][c4 * 4] = kv;
            *(float4*)&Vs[j][c4 * 4] = vv;
        }
        __syncthreads();

        float s[8];
        #pragma unroll
        for (int jj = 0; jj < 8; ++jj) s[jj] = 0.f;
        #pragma unroll
        for (int k = 0; k < HD; k += 4) {
            float4 qv = *(const float4*)&Qs[q][k];
            #pragma unroll
            for (int jj = 0; jj < 8; ++jj) {
                float4 kv = *(const float4*)&Ks[jj * 8 + g][k];
                s[jj] += qv.x * kv.x + qv.y * kv.y + qv.z * kv.z + qv.w * kv.w;
            }
        }

        float lmax = -1e30f;
        #pragma unroll
        for (int jj = 0; jj < 8; ++jj) {
            int j = jj * 8 + g;
            if (kv0 + j < Skv) {
                s[jj] *= ATTN_SCALE;
                lmax = fmaxf(lmax, s[jj]);
            } else {
                s[jj] = -1e30f;
            }
        }
        #pragma unroll
        for (int off = 4; off >= 1; off >>= 1)
            lmax = fmaxf(lmax, __shfl_xor_sync(0xffffffffu, lmax, off));

        float mnew = fmaxf(m, lmax);
        float corr = __expf(m - mnew);
        float lsum = 0.f;
        #pragma unroll
        for (int jj = 0; jj < 8; ++jj) {
            float p = __expf(s[jj] - mnew);
            lsum += p;
            Ps[q][jj * 8 + g] = p;
        }
        #pragma unroll
        for (int off = 4; off >= 1; off >>= 1)
            lsum += __shfl_xor_sync(0xffffffffu, lsum, off);

        l = l * corr + lsum;
        m = mnew;
        #pragma unroll
        for (int d = 0; d < 8; ++d) acc[d] *= corr;
        __syncwarp();

        #pragma unroll 4
        for (int j = 0; j < TK; ++j) {
            float p = Ps[q][j];
            float4 v0 = *(const float4*)&Vs[j][d0];
            float4 v1 = *(const float4*)&Vs[j][d0 + 4];
            acc[0] += p * v0.x; acc[1] += p * v0.y;
            acc[2] += p * v0.z; acc[3] += p * v0.w;
            acc[4] += p * v1.x; acc[5] += p * v1.y;
            acc[6] += p * v1.z; acc[7] += p * v1.w;
        }
    }

    if (q0 + q < Sq) {
        float inv = 1.f / l;
        float* op = Ob + (long long)(q0 + q) * CDIM + d0;
        if (accumulate) {
            #pragma unroll
            for (int d = 0; d < 8; ++d) op[d] += acc[d] * inv;
        } else {
            float o[8];
            #pragma unroll
            for (int d = 0; d < 8; ++d) o[d] = acc[d] * inv;
            *(float4*)&op[0] = *(float4*)&o[0];
            *(float4*)&op[4] = *(float4*)&o[4];
        }
    }
}

// ---------------- host orchestration ---------------------------------------
static inline void launch_split(const float* x, __nv_bfloat16* h, __nv_bfloat16* l, long long n)
{
    int n4 = (int)(n / 4);
    int blocks = (n4 + 255) / 256;
    if (blocks > 4096) blocks = 4096;
    split_kernel<<<blocks, 256>>>((const float4*)x, (__nv_bfloat162*)h,
                                  (__nv_bfloat162*)l, n4);
}

static inline void launch_gemm(const __nv_bfloat16* Ah, const __nv_bfloat16* Al,
                               const __nv_bfloat16* Wh, const __nv_bfloat16* Wl,
                               const float* bias, float* C,
                               int Mtot, int RB, long long strideA, long long strideC,
                               int N, int K)
{
    static bool attr_set = false;
    if (!attr_set) {
        cudaFuncSetAttribute(gemm_bf16x3, cudaFuncAttributeMaxDynamicSharedMemorySize,
                             GEMM_SMEM);
        attr_set = true;
    }
    dim3 grid(N / 128, (Mtot + 127) / 128);
    gemm_bf16x3<<<grid, 256, GEMM_SMEM>>>(Ah, Al, Wh, Wl, bias, C,
                                          Mtot, RB, strideA, strideC, N, K);
}

static inline void launch_attn(const float* Q, const float* K, const float* V,
                               float* O, int Sq, int Skv, int accumulate)
{
    dim3 grid((Sq + TQ - 1) / TQ, HEADS, B_);
    attn_kernel<<<grid, 256>>>(Q, K, V, O, Sq, Skv, accumulate);
}

template <typename T>
static inline T* sym(const void* s) { void* p; cudaGetSymbolAddress(&p, s); return (T*)p; }

extern "C" void kernel_launch(void* const* d_in, const int* in_sizes, int n_in,
                              void* d_out, int out_size)
{
    const float* hidden = (const float*)d_in[0];
    const float* enc    = (const float*)d_in[1];
    const float* w_q    = (const float*)d_in[2];
    const float* w_k    = (const float*)d_in[3];
    const float* w_v    = (const float*)d_in[4];
    const float* w_kb   = (const float*)d_in[5];
    const float* w_vb   = (const float*)d_in[6];
    const float* w_kc   = (const float*)d_in[7];
    const float* w_vc   = (const float*)d_in[8];
    const float* w_out  = (const float*)d_in[9];
    const float* b_out  = (const float*)d_in[10];
    float* out = (float*)d_out;

    float* pq  = sym<float>(&g_q);
    float* po  = sym<float>(&g_o);
    float* pk  = sym<float>(&g_k);
    float* pv  = sym<float>(&g_v);
    float* pbk = sym<float>(&g_bk);
    float* pbv = sym<float>(&g_bv);
    float* pck = sym<float>(&g_ck);
    float* pcv = sym<float>(&g_cv);

    __nv_bfloat16* hid_h = sym<__nv_bfloat16>(&s_hid_h);
    __nv_bfloat16* hid_l = sym<__nv_bfloat16>(&s_hid_l);
    __nv_bfloat16* enc_h = sym<__nv_bfloat16>(&s_enc_h);
    __nv_bfloat16* enc_l = sym<__nv_bfloat16>(&s_enc_l);
    __nv_bfloat16* po_h  = sym<__nv_bfloat16>(&s_po_h);
    __nv_bfloat16* po_l  = sym<__nv_bfloat16>(&s_po_l);
    __nv_bfloat16* wq_h  = sym<__nv_bfloat16>(&s_wq_h);
    __nv_bfloat16* wq_l  = sym<__nv_bfloat16>(&s_wq_l);
    __nv_bfloat16* wk_h  = sym<__nv_bfloat16>(&s_wk_h);
    __nv_bfloat16* wk_l  = sym<__nv_bfloat16>(&s_wk_l);
    __nv_bfloat16* wv_h  = sym<__nv_bfloat16>(&s_wv_h);
    __nv_bfloat16* wv_l  = sym<__nv_bfloat16>(&s_wv_l);
    __nv_bfloat16* wkb_h = sym<__nv_bfloat16>(&s_wkb_h);
    __nv_bfloat16* wkb_l = sym<__nv_bfloat16>(&s_wkb_l);
    __nv_bfloat16* wvb_h = sym<__nv_bfloat16>(&s_wvb_h);
    __nv_bfloat16* wvb_l = sym<__nv_bfloat16>(&s_wvb_l);
    __nv_bfloat16* wkc_h = sym<__nv_bfloat16>(&s_wkc_h);
    __nv_bfloat16* wkc_l = sym<__nv_bfloat16>(&s_wkc_l);
    __nv_bfloat16* wvc_h = sym<__nv_bfloat16>(&s_wvc_h);
    __nv_bfloat16* wvc_l = sym<__nv_bfloat16>(&s_wvc_l);
    __nv_bfloat16* wo_h  = sym<__nv_bfloat16>(&s_wo_h);
    __nv_bfloat16* wo_l  = sym<__nv_bfloat16>(&s_wo_l);

    const long long bsH   = (long long)QLEN * CDIM;
    const long long bsEnc = (long long)LLEN * CROSSD;
    const long long encN  = (long long)B_ * LLEN * CROSSD;
    const long long hidN  = (long long)B_ * QLEN * CDIM;

    // Split inputs & weights to bf16 hi/lo
    launch_split(hidden, hid_h, hid_l, hidN);
    launch_split(enc,    enc_h, enc_l, encN);
    launch_split(w_q,   wq_h,  wq_l,  (long long)CDIM*CDIM);
    launch_split(w_k,   wk_h,  wk_l,  (long long)CDIM*CROSSD);
    launch_split(w_v,   wv_h,  wv_l,  (long long)CDIM*CROSSD);
    launch_split(w_kb,  wkb_h, wkb_l, (long long)CDIM*CROSSD);
    launch_split(w_vb,  wvb_h, wvb_l, (long long)CDIM*CROSSD);
    launch_split(w_kc,  wkc_h, wkc_l, (long long)CDIM*CROSSD);
    launch_split(w_vc,  wvc_h, wvc_l, (long long)CDIM*CROSSD);
    launch_split(w_out, wo_h,  wo_l,  (long long)CDIM*CDIM);

    const long long boxOff = (long long)EHS_LEN * CROSSD;
    const long long clsOff = (long long)(EHS_LEN + NTOK) * CROSSD;

    // Projections (tensor cores, 3xBF16)
    launch_gemm(hid_h, hid_l, wq_h, wq_l, nullptr, pq,
                B_*QLEN, B_*QLEN, 0, 0, CDIM, CDIM);
    launch_gemm(enc_h, enc_l, wk_h, wk_l, nullptr, pk,
                B_*EHS_LEN, EHS_LEN, bsEnc, (long long)EHS_LEN*CDIM, CDIM, CROSSD);
    launch_gemm(enc_h, enc_l, wv_h, wv_l, nullptr, pv,
                B_*EHS_LEN, EHS_LEN, bsEnc, (long long)EHS_LEN*CDIM, CDIM, CROSSD);
    launch_gemm(enc_h + boxOff, enc_l + boxOff, wkb_h, wkb_l, nullptr, pbk,
                B_*NTOK, NTOK, bsEnc, (long long)NTOK*CDIM, CDIM, CROSSD);
    launch_gemm(enc_h + boxOff, enc_l + boxOff, wvb_h, wvb_l, nullptr, pbv,
                B_*NTOK, NTOK, bsEnc, (long long)NTOK*CDIM, CDIM, CROSSD);
    launch_gemm(enc_h + clsOff, enc_l + clsOff, wkc_h, wkc_l, nullptr, pck,
                B_*NTOK, NTOK, bsEnc, (long long)NTOK*CDIM, CDIM, CROSSD);
    launch_gemm(enc_h + clsOff, enc_l + clsOff, wvc_h, wvc_l, nullptr, pcv,
                B_*NTOK, NTOK, bsEnc, (long long)NTOK*CDIM, CDIM, CROSSD);

    // Attention chain (fp32)
    launch_attn(pq,  pk,  pv,  po,  QLEN, EHS_LEN, 0);
    launch_attn(pbk, pck, pcv, pbk, NTOK, NTOK,    1);
    launch_attn(pbv, pck, pcv, pbv, NTOK, NTOK,    1);
    launch_attn(pq,  pbk, pbv, po,  QLEN, NTOK,    1);

    // Split attention output, then out-projection (+bias) into d_out
    launch_split(po, po_h, po_l, hidN);
    launch_gemm(po_h, po_l, wo_h, wo_l, b_out, out,
                B_*QLEN, B_*QLEN, 0, 0, CDIM, CDIM);
}

// round 4
// speedup vs baseline: 3.9256x; 2.2480x over previous
#include <cuda_runtime.h>
#include <cuda_bf16.h>
#include <cstdint>

// Problem constants
#define B_      16
#define QLEN    1024
#define CDIM    1280
#define LLEN    477
#define CROSSD  2048
#define NTOK    200
#define HEADS   20
#define HD      64
#define EHS_LEN 77           // 477 - 200 - 200
#define ATTN_SCALE 0.125f    // 1/sqrt(64)

// ---------------- scratch (device globals; no runtime allocation) ----------
__device__ float g_q [B_*QLEN*CDIM];
__device__ float g_o [B_*QLEN*CDIM];
__device__ float g_k [B_*EHS_LEN*CDIM];
__device__ float g_v [B_*EHS_LEN*CDIM];
__device__ float g_bk[B_*NTOK*CDIM];
__device__ float g_bv[B_*NTOK*CDIM];
__device__ float g_ck[B_*NTOK*CDIM];
__device__ float g_cv[B_*NTOK*CDIM];

// bf16 hi/lo splits
__device__ __nv_bfloat16 s_hid_h[B_*QLEN*CDIM],  s_hid_l[B_*QLEN*CDIM];
__device__ __nv_bfloat16 s_enc_h[B_*LLEN*CROSSD], s_enc_l[B_*LLEN*CROSSD];
__device__ __nv_bfloat16 s_po_h [B_*QLEN*CDIM],  s_po_l [B_*QLEN*CDIM];
__device__ __nv_bfloat16 s_wq_h [CDIM*CDIM],   s_wq_l [CDIM*CDIM];
__device__ __nv_bfloat16 s_wk_h [CDIM*CROSSD], s_wk_l [CDIM*CROSSD];
__device__ __nv_bfloat16 s_wv_h [CDIM*CROSSD], s_wv_l [CDIM*CROSSD];
__device__ __nv_bfloat16 s_wkb_h[CDIM*CROSSD], s_wkb_l[CDIM*CROSSD];
__device__ __nv_bfloat16 s_wvb_h[CDIM*CROSSD], s_wvb_l[CDIM*CROSSD];
__device__ __nv_bfloat16 s_wkc_h[CDIM*CROSSD], s_wkc_l[CDIM*CROSSD];
__device__ __nv_bfloat16 s_wvc_h[CDIM*CROSSD], s_wvc_l[CDIM*CROSSD];
__device__ __nv_bfloat16 s_wo_h [CDIM*CDIM],   s_wo_l [CDIM*CDIM];

// ---------------- helpers ---------------------------------------------------
__device__ __forceinline__ uint32_t smem_u32(const void* p) {
    uint32_t a;
    asm("{ .reg .u64 t; cvta.to.shared.u64 t, %1; cvt.u32.u64 %0, t; }"
        : "=r"(a) : "l"(p));
    return a;
}

__device__ __forceinline__ void cp_async16(uint32_t dst, const void* src, int pred) {
    int sz = pred ? 16 : 0;
    asm volatile("cp.async.cg.shared.global [%0], [%1], 16, %2;"
                 :: "r"(dst), "l"(src), "r"(sz) : "memory");
}
__device__ __forceinline__ void cp_commit() {
    asm volatile("cp.async.commit_group;" ::: "memory");
}
template <int N>
__device__ __forceinline__ void cp_wait() {
    asm volatile("cp.async.wait_group %0;" :: "n"(N) : "memory");
}

__device__ __forceinline__ void ldm4(uint32_t& r0, uint32_t& r1, uint32_t& r2,
                                     uint32_t& r3, uint32_t addr) {
    asm volatile("ldmatrix.sync.aligned.m8n8.x4.shared.b16 {%0,%1,%2,%3}, [%4];"
                 : "=r"(r0), "=r"(r1), "=r"(r2), "=r"(r3) : "r"(addr));
}

__device__ __forceinline__ void mma16816(float* c, const uint32_t* a, const uint32_t* b) {
    asm volatile(
        "mma.sync.aligned.m16n8k16.row.col.f32.bf16.bf16.f32 "
        "{%0,%1,%2,%3}, {%4,%5,%6,%7}, {%8,%9}, {%0,%1,%2,%3};"
        : "+f"(c[0]), "+f"(c[1]), "+f"(c[2]), "+f"(c[3])
        : "r"(a[0]), "r"(a[1]), "r"(a[2]), "r"(a[3]), "r"(b[0]), "r"(b[1]));
}

__device__ __forceinline__ uint32_t pack_bf16(float a, float b) {
    uint32_t lo = (uint32_t)__bfloat16_as_ushort(__float2bfloat16_rn(a));
    uint32_t hi = (uint32_t)__bfloat16_as_ushort(__float2bfloat16_rn(b));
    return lo | (hi << 16);
}

// ---------------- split kernel: fp32 -> (bf16 hi, bf16 lo) -----------------
__global__ void split_kernel(const float4* __restrict__ x,
                             __nv_bfloat162* __restrict__ h,
                             __nv_bfloat162* __restrict__ l, int n4)
{
    for (int i = blockIdx.x * blockDim.x + threadIdx.x; i < n4;
         i += gridDim.x * blockDim.x) {
        float4 v = x[i];
        __nv_bfloat16 hx = __float2bfloat16_rn(v.x);
        __nv_bfloat16 hy = __float2bfloat16_rn(v.y);
        __nv_bfloat16 hz = __float2bfloat16_rn(v.z);
        __nv_bfloat16 hw = __float2bfloat16_rn(v.w);
        h[2*i]   = __halves2bfloat162(hx, hy);
        h[2*i+1] = __halves2bfloat162(hz, hw);
        l[2*i]   = __halves2bfloat162(__float2bfloat16_rn(v.x - __bfloat162float(hx)),
                                      __float2bfloat16_rn(v.y - __bfloat162float(hy)));
        l[2*i+1] = __halves2bfloat162(__float2bfloat16_rn(v.z - __bfloat162float(hz)),
                                      __float2bfloat16_rn(v.w - __bfloat162float(hw)));
    }
}

// ---------------- 3xBF16 tensor-core GEMM (3-stage cp.async pipeline) ------
#define KCH 32
#define GSTAGE 32768u
#define GEMM_SMEM (3u * GSTAGE)

__global__ __launch_bounds__(256)
void gemm_bf16x3(const __nv_bfloat16* __restrict__ Ah,
                 const __nv_bfloat16* __restrict__ Al,
                 const __nv_bfloat16* __restrict__ Wh,
                 const __nv_bfloat16* __restrict__ Wl,
                 const float* __restrict__ bias,
                 float* __restrict__ C,
                 int Mtot, int RB, long long strideA, long long strideC,
                 int N, int K)
{
    extern __shared__ char smem[];
    const uint32_t sm = smem_u32(smem);

    const int t    = threadIdx.x;
    const int lane = t & 31;
    const int wid  = t >> 5;
    const int wm   = wid & 1;
    const int wn   = wid >> 1;
    const int m0   = blockIdx.y * 128;
    const int n0   = blockIdx.x * 128;

    float acc[4][4][4];
    #pragma unroll
    for (int i = 0; i < 4; ++i)
        #pragma unroll
        for (int j = 0; j < 4; ++j)
            #pragma unroll
            for (int k = 0; k < 4; ++k) acc[i][j][k] = 0.f;

    const int NC = K / KCH;

    auto issue = [&](int c) {
        const int k0 = c * KCH;
        const uint32_t sbase = sm + (uint32_t)(c % 3) * GSTAGE;
        #pragma unroll
        for (int i = 0; i < 2; ++i) {
            int task = t + i * 256;
            int gr   = task >> 2;
            int kc   = task & 3;
            uint32_t sw  = (uint32_t)(kc ^ ((gr >> 1) & 3));
            uint32_t dst = sbase + (uint32_t)gr * 64u + sw * 16u;
            int grow = m0 + gr;
            int pred = grow < Mtot;
            long long off = 0;
            if (pred) {
                int b = grow / RB, r = grow % RB;
                off = (long long)b * strideA + (long long)r * K + k0 + kc * 8;
            }
            cp_async16(dst,         Ah + off, pred);
            cp_async16(dst + 8192u, Al + off, pred);
            long long boff = (long long)(n0 + gr) * K + k0 + kc * 8;
            cp_async16(dst + 16384u, Wh + boff, 1);
            cp_async16(dst + 24576u, Wl + boff, 1);
        }
        cp_commit();
    };

    auto compute = [&](int c) {
        const uint32_t sbase = sm + (uint32_t)(c % 3) * GSTAGE;
        #pragma unroll
        for (int ks = 0; ks < 2; ++ks) {
            uint32_t af[16], bh[8], bl[8];
            #pragma unroll
            for (int mt = 0; mt < 4; ++mt) {
                int arow = wm * 64 + mt * 16 + (lane & 15);
                int ach  = ks * 2 + (lane >> 4);
                uint32_t addr = sbase + (uint32_t)arow * 64u
                              + (uint32_t)((ach ^ ((arow >> 1) & 3)) * 16);
                ldm4(af[mt*4], af[mt*4+1], af[mt*4+2], af[mt*4+3], addr);
            }
            #pragma unroll
            for (int nt2 = 0; nt2 < 2; ++nt2) {
                int brow = wn * 32 + nt2 * 16 + ((lane >> 4) & 1) * 8 + (lane & 7);
                int bch  = ks * 2 + ((lane >> 3) & 1);
                uint32_t addr = sbase + 16384u + (uint32_t)brow * 64u
                              + (uint32_t)((bch ^ ((brow >> 1) & 3)) * 16);
                ldm4(bh[nt2*4], bh[nt2*4+1], bh[nt2*4+2], bh[nt2*4+3], addr);
            }
            #pragma unroll
            for (int mt = 0; mt < 4; ++mt)
                #pragma unroll
                for (int nt = 0; nt < 4; ++nt)
                    mma16816(acc[mt][nt], &af[mt*4], &bh[(nt >> 1)*4 + (nt & 1)*2]);
            #pragma unroll
            for (int nt2 = 0; nt2 < 2; ++nt2) {
                int brow = wn * 32 + nt2 * 16 + ((lane >> 4) & 1) * 8 + (lane & 7);
                int bch  = ks * 2 + ((lane >> 3) & 1);
                uint32_t addr = sbase + 24576u + (uint32_t)brow * 64u
                              + (uint32_t)((bch ^ ((brow >> 1) & 3)) * 16);
                ldm4(bl[nt2*4], bl[nt2*4+1], bl[nt2*4+2], bl[nt2*4+3], addr);
            }
            #pragma unroll
            for (int mt = 0; mt < 4; ++mt)
                #pragma unroll
                for (int nt = 0; nt < 4; ++nt)
                    mma16816(acc[mt][nt], &af[mt*4], &bl[(nt >> 1)*4 + (nt & 1)*2]);
            #pragma unroll
            for (int mt = 0; mt < 4; ++mt) {
                int arow = wm * 64 + mt * 16 + (lane & 15);
                int ach  = ks * 2 + (lane >> 4);
                uint32_t addr = sbase + 8192u + (uint32_t)arow * 64u
                              + (uint32_t)((ach ^ ((arow >> 1) & 3)) * 16);
                ldm4(af[mt*4], af[mt*4+1], af[mt*4+2], af[mt*4+3], addr);
            }
            #pragma unroll
            for (int mt = 0; mt < 4; ++mt)
                #pragma unroll
                for (int nt = 0; nt < 4; ++nt)
                    mma16816(acc[mt][nt], &af[mt*4], &bh[(nt >> 1)*4 + (nt & 1)*2]);
        }
    };

    issue(0);
    issue(1);
    for (int c = 0; c < NC; ++c) {
        if (c + 1 < NC) { cp_wait<1>(); } else { cp_wait<0>(); }
        __syncthreads();
        compute(c);
        if (c + 2 < NC) issue(c + 2);
    }

    const int g  = lane >> 2;
    const int q4 = lane & 3;
    #pragma unroll
    for (int mt = 0; mt < 4; ++mt) {
        #pragma unroll
        for (int half = 0; half < 2; ++half) {
            int grow = m0 + wm * 64 + mt * 16 + g + half * 8;
            if (grow < Mtot) {
                int b = grow / RB, r = grow % RB;
                float* crow = C + (long long)b * strideC + (long long)r * N
                            + n0 + wn * 32;
                #pragma unroll
                for (int nt = 0; nt < 4; ++nt) {
                    int ncol = nt * 8 + q4 * 2;
                    float2 v;
                    v.x = acc[mt][nt][half*2+0];
                    v.y = acc[mt][nt][half*2+1];
                    if (bias) {
                        v.x += bias[n0 + wn*32 + ncol];
                        v.y += bias[n0 + wn*32 + ncol + 1];
                    }
                    *(float2*)&crow[ncol] = v;
                }
            }
        }
    }
}

// ---------------- Tensor-core attention (3xBF16, whole KV in smem) ---------
// One CTA = 128 q rows of one (batch, head). 8 warps x 16 q rows.
// smem: Qh 16K | Ql 16K | Kh 32K | Kl 32K | Vh 32K | Vl 32K  (V is d-major)
#define SKV_PAD 256
#define ATT_SMEM (160u * 1024u)
#define AQH 0u
#define AQL 16384u
#define AKH 32768u
#define AKL 65536u
#define AVH 98304u
#define AVL 131072u

__global__ __launch_bounds__(256)
void attn_tc(const float* __restrict__ Qg, const float* __restrict__ Kg,
             const float* __restrict__ Vg, float* __restrict__ Og,
             int Sq, int Skv, int accumulate)
{
    extern __shared__ char smem[];
    char* smc = smem;
    const uint32_t sm = smem_u32(smem);

    const int t  = threadIdx.x;
    const int b  = blockIdx.z;
    const int h  = blockIdx.y;
    const int q0 = blockIdx.x * 128;

    const float* Qb = Qg + ((long long)b * Sq)  * CDIM + h * HD;
    const float* Kb = Kg + ((long long)b * Skv) * CDIM + h * HD;
    const float* Vb = Vg + ((long long)b * Skv) * CDIM + h * HD;
    float*       Ob = Og + ((long long)b * Sq)  * CDIM + h * HD;

    // ---- stage Q (128 x 64 fp32 -> hi/lo bf16, 128B rows, xor-8 swizzle)
    #pragma unroll
    for (int i = 0; i < 8; ++i) {
        int lin = t + i * 256;          // 0..2047
        int row = lin >> 4;             // 0..127
        int c4  = lin & 15;             // float4 index (4 d-elems)
        float4 v = make_float4(0.f, 0.f, 0.f, 0.f);
        if (q0 + row < Sq)
            v = *(const float4*)&Qb[(long long)(q0 + row) * CDIM + c4 * 4];
        __nv_bfloat16 hx = __float2bfloat16_rn(v.x), hy = __float2bfloat16_rn(v.y);
        __nv_bfloat16 hz = __float2bfloat16_rn(v.z), hw = __float2bfloat16_rn(v.w);
        uint2 hv, lv;
        hv.x = pack_bf16(__bfloat162float(hx), __bfloat162float(hy));
        hv.y = pack_bf16(__bfloat162float(hz), __bfloat162float(hw));
        lv.x = pack_bf16(v.x - __bfloat162float(hx), v.y - __bfloat162float(hy));
        lv.y = pack_bf16(v.z - __bfloat162float(hz), v.w - __bfloat162float(hw));
        int ch = c4 >> 1, halfq = c4 & 1;
        uint32_t off = (uint32_t)row * 128u + (uint32_t)((ch ^ (row & 7)) * 16)
                     + (uint32_t)halfq * 8u;
        *(uint2*)(smc + AQH + off) = hv;
        *(uint2*)(smc + AQL + off) = lv;
    }
    // ---- stage K (rows kv, 128B rows) and V transposed (rows d, 512B rows)
    #pragma unroll
    for (int i = 0; i < 16; ++i) {
        int lin = t + i * 256;          // 0..4095
        int row = lin >> 4;             // kv 0..255
        int c4  = lin & 15;
        float4 kv4 = make_float4(0.f, 0.f, 0.f, 0.f);
        float4 vv4 = make_float4(0.f, 0.f, 0.f, 0.f);
        if (row < Skv) {
            kv4 = *(const float4*)&Kb[(long long)row * CDIM + c4 * 4];
            vv4 = *(const float4*)&Vb[(long long)row * CDIM + c4 * 4];
        }
        // K
        {
            __nv_bfloat16 hx = __float2bfloat16_rn(kv4.x), hy = __float2bfloat16_rn(kv4.y);
            __nv_bfloat16 hz = __float2bfloat16_rn(kv4.z), hw = __float2bfloat16_rn(kv4.w);
            uint2 hv, lv;
            hv.x = pack_bf16(__bfloat162float(hx), __bfloat162float(hy));
            hv.y = pack_bf16(__bfloat162float(hz), __bfloat162float(hw));
            lv.x = pack_bf16(kv4.x - __bfloat162float(hx), kv4.y - __bfloat162float(hy));
            lv.y = pack_bf16(kv4.z - __bfloat162float(hz), kv4.w - __bfloat162float(hw));
            int ch = c4 >> 1, halfq = c4 & 1;
            uint32_t off = (uint32_t)row * 128u + (uint32_t)((ch ^ (row & 7)) * 16)
                         + (uint32_t)halfq * 8u;
            *(uint2*)(smc + AKH + off) = hv;
            *(uint2*)(smc + AKL + off) = lv;
        }
        // V transposed: element (kv=row, d=c4*4+j) -> Vt[d][kv]
        float ve[4] = {vv4.x, vv4.y, vv4.z, vv4.w};
        #pragma unroll
        for (int j = 0; j < 4; ++j) {
            int d = c4 * 4 + j;
            __nv_bfloat16 hb = __float2bfloat16_rn(ve[j]);
            __nv_bfloat16 lb = __float2bfloat16_rn(ve[j] - __bfloat162float(hb));
            uint32_t off = (uint32_t)d * 512u
                         + (uint32_t)((((row >> 3) ^ (d & 7)) * 16))
                         + (uint32_t)(row & 7) * 2u;
            *(__nv_bfloat16*)(smc + AVH + off) = hb;
            *(__nv_bfloat16*)(smc + AVL + off) = lb;
        }
    }
    __syncthreads();

    // ---- per-warp compute: 16 q rows
    const int lane  = t & 31;
    const int wid   = t >> 5;
    const int qbase = wid * 16;

    float O[8][4];
    #pragma unroll
    for (int nt = 0; nt < 8; ++nt)
        #pragma unroll
        for (int e = 0; e < 4; ++e) O[nt][e] = 0.f;
    float mrow[2] = {-1e30f, -1e30f};
    float lrow[2] = {0.f, 0.f};

    const int nch = (Skv + 63) / 64;
    for (int c = 0; c < nch; ++c) {
        float S[8][4];
        #pragma unroll
        for (int nt = 0; nt < 8; ++nt)
            #pragma unroll
            for (int e = 0; e < 4; ++e) S[nt][e] = 0.f;

        // QK^T (3 passes)
        #pragma unroll
        for (int ks = 0; ks < 4; ++ks) {
            uint32_t qh[4], ql[4], kh[4], kl[4];
            int arow = qbase + (lane & 15);
            int ach  = 2 * ks + (lane >> 4);
            uint32_t aoff = (uint32_t)arow * 128u + (uint32_t)((ach ^ (arow & 7)) * 16);
            ldm4(qh[0], qh[1], qh[2], qh[3], sm + AQH + aoff);
            ldm4(ql[0], ql[1], ql[2], ql[3], sm + AQL + aoff);
            #pragma unroll
            for (int nt2 = 0; nt2 < 4; ++nt2) {
                int brow = c * 64 + nt2 * 16 + ((lane >> 4) & 1) * 8 + (lane & 7);
                int bch  = 2 * ks + ((lane >> 3) & 1);
                uint32_t boff = (uint32_t)brow * 128u
                              + (uint32_t)((bch ^ (brow & 7)) * 16);
                ldm4(kh[0], kh[1], kh[2], kh[3], sm + AKH + boff);
                ldm4(kl[0], kl[1], kl[2], kl[3], sm + AKL + boff);
                #pragma unroll
                for (int sub = 0; sub < 2; ++sub) {
                    int nt = nt2 * 2 + sub;
                    mma16816(S[nt], qh, &kh[sub*2]);
                    mma16816(S[nt], qh, &kl[sub*2]);
                    mma16816(S[nt], ql, &kh[sub*2]);
                }
            }
        }

        // scale + mask
        #pragma unroll
        for (int nt = 0; nt < 8; ++nt) {
            int col0 = c * 64 + nt * 8 + 2 * (lane & 3);
            #pragma unroll
            for (int e = 0; e < 4; ++e) {
                int col = col0 + (e & 1);
                float v = S[nt][e] * ATTN_SCALE;
                S[nt][e] = (col < Skv) ? v : -1e30f;
            }
        }

        // row max (halves: e{0,1} -> row lane>>2, e{2,3} -> row+8)
        float mx[2] = {-1e30f, -1e30f};
        #pragma unroll
        for (int nt = 0; nt < 8; ++nt) {
            mx[0] = fmaxf(mx[0], fmaxf(S[nt][0], S[nt][1]));
            mx[1] = fmaxf(mx[1], fmaxf(S[nt][2], S[nt][3]));
        }
        #pragma unroll
        for (int off = 1; off <= 2; off <<= 1) {
            mx[0] = fmaxf(mx[0], __shfl_xor_sync(0xffffffffu, mx[0], off));
            mx[1] = fmaxf(mx[1], __shfl_xor_sync(0xffffffffu, mx[1], off));
        }
        float mnew0 = fmaxf(mrow[0], mx[0]);
        float mnew1 = fmaxf(mrow[1], mx[1]);
        float corr0 = __expf(mrow[0] - mnew0);
        float corr1 = __expf(mrow[1] - mnew1);

        float ls[2] = {0.f, 0.f};
        #pragma unroll
        for (int nt = 0; nt < 8; ++nt) {
            S[nt][0] = __expf(S[nt][0] - mnew0); ls[0] += S[nt][0];
            S[nt][1] = __expf(S[nt][1] - mnew0); ls[0] += S[nt][1];
            S[nt][2] = __expf(S[nt][2] - mnew1); ls[1] += S[nt][2];
            S[nt][3] = __expf(S[nt][3] - mnew1); ls[1] += S[nt][3];
        }
        #pragma unroll
        for (int off = 1; off <= 2; off <<= 1) {
            ls[0] += __shfl_xor_sync(0xffffffffu, ls[0], off);
            ls[1] += __shfl_xor_sync(0xffffffffu, ls[1], off);
        }
        lrow[0] = lrow[0] * corr0 + ls[0];
        lrow[1] = lrow[1] * corr1 + ls[1];
        mrow[0] = mnew0; mrow[1] = mnew1;
        #pragma unroll
        for (int nt = 0; nt < 8; ++nt) {
            O[nt][0] *= corr0; O[nt][1] *= corr0;
            O[nt][2] *= corr1; O[nt][3] *= corr1;
        }

        // P V (3 passes); P A-frags built from S fragments
        #pragma unroll
        for (int ks = 0; ks < 4; ++ks) {
            uint32_t aph[4], apl[4];
            {
                int T0 = 2 * ks, T1 = 2 * ks + 1;
                float p0 = S[T0][0], p1 = S[T0][1], p2 = S[T0][2], p3 = S[T0][3];
                float r0 = S[T1][0], r1 = S[T1][1], r2 = S[T1][2], r3 = S[T1][3];
                float h0 = __bfloat162float(__float2bfloat16_rn(p0));
                float h1 = __bfloat162float(__float2bfloat16_rn(p1));
                float h2 = __bfloat162float(__float2bfloat16_rn(p2));
                float h3 = __bfloat162float(__float2bfloat16_rn(p3));
                float g0 = __bfloat162float(__float2bfloat16_rn(r0));
                float g1 = __bfloat162float(__float2bfloat16_rn(r1));
                float g2 = __bfloat162float(__float2bfloat16_rn(r2));
                float g3 = __bfloat162float(__float2bfloat16_rn(r3));
                aph[0] = pack_bf16(h0, h1); aph[1] = pack_bf16(h2, h3);
                aph[2] = pack_bf16(g0, g1); aph[3] = pack_bf16(g2, g3);
                apl[0] = pack_bf16(p0 - h0, p1 - h1);
                apl[1] = pack_bf16(p2 - h2, p3 - h3);
                apl[2] = pack_bf16(r0 - g0, r1 - g1);
                apl[3] = pack_bf16(r2 - g2, r3 - g3);
            }
            #pragma unroll
            for (int nt2 = 0; nt2 < 4; ++nt2) {
                uint32_t vh[4], vl[4];
                int vrow = nt2 * 16 + ((lane >> 4) & 1) * 8 + (lane & 7);   // d
                int vch  = c * 8 + 2 * ks + ((lane >> 3) & 1);              // kv chunk
                uint32_t voff = (uint32_t)vrow * 512u
                              + (uint32_t)(((vch ^ (vrow & 7))) * 16);
                ldm4(vh[0], vh[1], vh[2], vh[3], sm + AVH + voff);
                ldm4(vl[0], vl[1], vl[2], vl[3], sm + AVL + voff);
                #pragma unroll
                for (int sub = 0; sub < 2; ++sub) {
                    int nt = nt2 * 2 + sub;
                    mma16816(O[nt], aph, &vh[sub*2]);
                    mma16816(O[nt], aph, &vl[sub*2]);
                    mma16816(O[nt], apl, &vh[sub*2]);
                }
            }
        }
    }

    // ---- epilogue
    float inv0 = 1.f / lrow[0];
    float inv1 = 1.f / lrow[1];
    #pragma unroll
    for (int halfq = 0; halfq < 2; ++halfq) {
        int row = q0 + qbase + (lane >> 2) + halfq * 8;
        if (row < Sq) {
            float inv = halfq ? inv1 : inv0;
            float* op = Ob + (long long)row * CDIM;
            #pragma unroll
            for (int nt = 0; nt < 8; ++nt) {
                int d = nt * 8 + 2 * (lane & 3);
                float2 v;
                v.x = O[nt][halfq*2+0] * inv;
                v.y = O[nt][halfq*2+1] * inv;
                if (accumulate) {
                    float2 old = *(float2*)&op[d];
                    v.x += old.x; v.y += old.y;
                }
                *(float2*)&op[d] = v;
            }
        }
    }
}

// ---------------- host orchestration ---------------------------------------
static inline void launch_split(const float* x, __nv_bfloat16* h, __nv_bfloat16* l, long long n)
{
    int n4 = (int)(n / 4);
    int blocks = (n4 + 255) / 256;
    if (blocks > 4096) blocks = 4096;
    split_kernel<<<blocks, 256>>>((const float4*)x, (__nv_bfloat162*)h,
                                  (__nv_bfloat162*)l, n4);
}

static inline void launch_gemm(const __nv_bfloat16* Ah, const __nv_bfloat16* Al,
                               const __nv_bfloat16* Wh, const __nv_bfloat16* Wl,
                               const float* bias, float* C,
                               int Mtot, int RB, long long strideA, long long strideC,
                               int N, int K)
{
    cudaFuncSetAttribute(gemm_bf16x3, cudaFuncAttributeMaxDynamicSharedMemorySize,
                         GEMM_SMEM);
    dim3 grid(N / 128, (Mtot + 127) / 128);
    gemm_bf16x3<<<grid, 256, GEMM_SMEM>>>(Ah, Al, Wh, Wl, bias, C,
                                          Mtot, RB, strideA, strideC, N, K);
}

static inline void launch_attn(const float* Q, const float* K, const float* V,
                               float* O, int Sq, int Skv, int accumulate)
{
    cudaFuncSetAttribute(attn_tc, cudaFuncAttributeMaxDynamicSharedMemorySize,
                         ATT_SMEM);
    dim3 grid((Sq + 127) / 128, HEADS, B_);
    attn_tc<<<grid, 256, ATT_SMEM>>>(Q, K, V, O, Sq, Skv, accumulate);
}

template <typename T>
static inline T* sym(const void* s) { void* p; cudaGetSymbolAddress(&p, s); return (T*)p; }

extern "C" void kernel_launch(void* const* d_in, const int* in_sizes, int n_in,
                              void* d_out, int out_size)
{
    const float* hidden = (const float*)d_in[0];
    const float* enc    = (const float*)d_in[1];
    const float* w_q    = (const float*)d_in[2];
    const float* w_k    = (const float*)d_in[3];
    const float* w_v    = (const float*)d_in[4];
    const float* w_kb   = (const float*)d_in[5];
    const float* w_vb   = (const float*)d_in[6];
    const float* w_kc   = (const float*)d_in[7];
    const float* w_vc   = (const float*)d_in[8];
    const float* w_out  = (const float*)d_in[9];
    const float* b_out  = (const float*)d_in[10];
    float* out = (float*)d_out;

    float* pq  = sym<float>(&g_q);
    float* po  = sym<float>(&g_o);
    float* pk  = sym<float>(&g_k);
    float* pv  = sym<float>(&g_v);
    float* pbk = sym<float>(&g_bk);
    float* pbv = sym<float>(&g_bv);
    float* pck = sym<float>(&g_ck);
    float* pcv = sym<float>(&g_cv);

    __nv_bfloat16* hid_h = sym<__nv_bfloat16>(&s_hid_h);
    __nv_bfloat16* hid_l = sym<__nv_bfloat16>(&s_hid_l);
    __nv_bfloat16* enc_h = sym<__nv_bfloat16>(&s_enc_h);
    __nv_bfloat16* enc_l = sym<__nv_bfloat16>(&s_enc_l);
    __nv_bfloat16* po_h  = sym<__nv_bfloat16>(&s_po_h);
    __nv_bfloat16* po_l  = sym<__nv_bfloat16>(&s_po_l);
    __nv_bfloat16* wq_h  = sym<__nv_bfloat16>(&s_wq_h);
    __nv_bfloat16* wq_l  = sym<__nv_bfloat16>(&s_wq_l);
    __nv_bfloat16* wk_h  = sym<__nv_bfloat16>(&s_wk_h);
    __nv_bfloat16* wk_l  = sym<__nv_bfloat16>(&s_wk_l);
    __nv_bfloat16* wv_h  = sym<__nv_bfloat16>(&s_wv_h);
    __nv_bfloat16* wv_l  = sym<__nv_bfloat16>(&s_wv_l);
    __nv_bfloat16* wkb_h = sym<__nv_bfloat16>(&s_wkb_h);
    __nv_bfloat16* wkb_l = sym<__nv_bfloat16>(&s_wkb_l);
    __nv_bfloat16* wvb_h = sym<__nv_bfloat16>(&s_wvb_h);
    __nv_bfloat16* wvb_l = sym<__nv_bfloat16>(&s_wvb_l);
    __nv_bfloat16* wkc_h = sym<__nv_bfloat16>(&s_wkc_h);
    __nv_bfloat16* wkc_l = sym<__nv_bfloat16>(&s_wkc_l);
    __nv_bfloat16* wvc_h = sym<__nv_bfloat16>(&s_wvc_h);
    __nv_bfloat16* wvc_l = sym<__nv_bfloat16>(&s_wvc_l);
    __nv_bfloat16* wo_h  = sym<__nv_bfloat16>(&s_wo_h);
    __nv_bfloat16* wo_l  = sym<__nv_bfloat16>(&s_wo_l);

    const long long bsEnc = (long long)LLEN * CROSSD;
    const long long encN  = (long long)B_ * LLEN * CROSSD;
    const long long hidN  = (long long)B_ * QLEN * CDIM;

    // Split inputs & weights to bf16 hi/lo
    launch_split(hidden, hid_h, hid_l, hidN);
    launch_split(enc,    enc_h, enc_l, encN);
    launch_split(w_q,   wq_h,  wq_l,  (long long)CDIM*CDIM);
    launch_split(w_k,   wk_h,  wk_l,  (long long)CDIM*CROSSD);
    launch_split(w_v,   wv_h,  wv_l,  (long long)CDIM*CROSSD);
    launch_split(w_kb,  wkb_h, wkb_l, (long long)CDIM*CROSSD);
    launch_split(w_vb,  wvb_h, wvb_l, (long long)CDIM*CROSSD);
    launch_split(w_kc,  wkc_h, wkc_l, (long long)CDIM*CROSSD);
    launch_split(w_vc,  wvc_h, wvc_l, (long long)CDIM*CROSSD);
    launch_split(w_out, wo_h,  wo_l,  (long long)CDIM*CDIM);

    const long long boxOff = (long long)EHS_LEN * CROSSD;
    const long long clsOff = (long long)(EHS_LEN + NTOK) * CROSSD;

    // Projections (tensor cores, 3xBF16)
    launch_gemm(hid_h, hid_l, wq_h, wq_l, nullptr, pq,
                B_*QLEN, B_*QLEN, 0, 0, CDIM, CDIM);
    launch_gemm(enc_h, enc_l, wk_h, wk_l, nullptr, pk,
                B_*EHS_LEN, EHS_LEN, bsEnc, (long long)EHS_LEN*CDIM, CDIM, CROSSD);
    launch_gemm(enc_h, enc_l, wv_h, wv_l, nullptr, pv,
                B_*EHS_LEN, EHS_LEN, bsEnc, (long long)EHS_LEN*CDIM, CDIM, CROSSD);
    launch_gemm(enc_h + boxOff, enc_l + boxOff, wkb_h, wkb_l, nullptr, pbk,
                B_*NTOK, NTOK, bsEnc, (long long)NTOK*CDIM, CDIM, CROSSD);
    launch_gemm(enc_h + boxOff, enc_l + boxOff, wvb_h, wvb_l, nullptr, pbv,
                B_*NTOK, NTOK, bsEnc, (long long)NTOK*CDIM, CDIM, CROSSD);
    launch_gemm(enc_h + clsOff, enc_l + clsOff, wkc_h, wkc_l, nullptr, pck,
                B_*NTOK, NTOK, bsEnc, (long long)NTOK*CDIM, CDIM, CROSSD);
    launch_gemm(enc_h + clsOff, enc_l + clsOff, wvc_h, wvc_l, nullptr, pcv,
                B_*NTOK, NTOK, bsEnc, (long long)NTOK*CDIM, CDIM, CROSSD);

    // Attention chain (tensor cores, 3xBF16)
    launch_attn(pq,  pk,  pv,  po,  QLEN, EHS_LEN, 0);
    launch_attn(pbk, pck, pcv, pbk, NTOK, NTOK,    1);
    launch_attn(pbv, pck, pcv, pbv, NTOK, NTOK,    1);
    launch_attn(pq,  pbk, pbv, po,  QLEN, NTOK,    1);

    // Split attention output, then out-projection (+bias) into d_out
    launch_split(po, po_h, po_l, hidN);
    launch_gemm(po_h, po_l, wo_h, wo_l, b_out, out,
                B_*QLEN, B_*QLEN, 0, 0, CDIM, CDIM);
}

// round 5
// speedup vs baseline: 5.1329x; 1.3075x over previous
#include <cuda_runtime.h>
#include <cuda_bf16.h>
#include <cuda_fp16.h>
#include <cstdint>

// Problem constants
#define B_      16
#define QLEN    1024
#define CDIM    1280
#define LLEN    477
#define CROSSD  2048
#define NTOK    200
#define HEADS   20
#define HD      64
#define EHS_LEN 77           // 477 - 200 - 200
#define ATTN_SCALE 0.125f    // 1/sqrt(64)
#define WSCALE     64.0f
#define INV_WSCALE 0.015625f

// ---------------- scratch (device globals; no runtime allocation) ----------
__device__ float g_q [B_*QLEN*CDIM];
__device__ float g_o [B_*QLEN*CDIM];
__device__ float g_k [B_*EHS_LEN*CDIM];
__device__ float g_v [B_*EHS_LEN*CDIM];
__device__ float g_bk[B_*NTOK*CDIM];
__device__ float g_bv[B_*NTOK*CDIM];
__device__ float g_ck[B_*NTOK*CDIM];
__device__ float g_cv[B_*NTOK*CDIM];

// fp16 activations (hi only) and scaled hi/lo weights
__device__ __half a_hid[B_*QLEN*CDIM];
__device__ __half a_enc[B_*LLEN*CROSSD];
__device__ __half a_po [B_*QLEN*CDIM];
__device__ __half w_q_h [CDIM*CDIM],   w_q_l [CDIM*CDIM];
__device__ __half w_k_h [CDIM*CROSSD], w_k_l [CDIM*CROSSD];
__device__ __half w_v_h [CDIM*CROSSD], w_v_l [CDIM*CROSSD];
__device__ __half w_kb_h[CDIM*CROSSD], w_kb_l[CDIM*CROSSD];
__device__ __half w_vb_h[CDIM*CROSSD], w_vb_l[CDIM*CROSSD];
__device__ __half w_kc_h[CDIM*CROSSD], w_kc_l[CDIM*CROSSD];
__device__ __half w_vc_h[CDIM*CROSSD], w_vc_l[CDIM*CROSSD];
__device__ __half w_o_h [CDIM*CDIM],   w_o_l [CDIM*CDIM];

// ---------------- helpers ---------------------------------------------------
__device__ __forceinline__ uint32_t smem_u32(const void* p) {
    uint32_t a;
    asm("{ .reg .u64 t; cvta.to.shared.u64 t, %1; cvt.u32.u64 %0, t; }"
        : "=r"(a) : "l"(p));
    return a;
}

__device__ __forceinline__ void cp_async16(uint32_t dst, const void* src, int pred) {
    int sz = pred ? 16 : 0;
    asm volatile("cp.async.cg.shared.global [%0], [%1], 16, %2;"
                 :: "r"(dst), "l"(src), "r"(sz) : "memory");
}
__device__ __forceinline__ void cp_commit() {
    asm volatile("cp.async.commit_group;" ::: "memory");
}
template <int N>
__device__ __forceinline__ void cp_wait() {
    asm volatile("cp.async.wait_group %0;" :: "n"(N) : "memory");
}

__device__ __forceinline__ void ldm4(uint32_t& r0, uint32_t& r1, uint32_t& r2,
                                     uint32_t& r3, uint32_t addr) {
    asm volatile("ldmatrix.sync.aligned.m8n8.x4.shared.b16 {%0,%1,%2,%3}, [%4];"
                 : "=r"(r0), "=r"(r1), "=r"(r2), "=r"(r3) : "r"(addr));
}

__device__ __forceinline__ void mma_h(float* c, const uint32_t* a, const uint32_t* b) {
    asm volatile(
        "mma.sync.aligned.m16n8k16.row.col.f32.f16.f16.f32 "
        "{%0,%1,%2,%3}, {%4,%5,%6,%7}, {%8,%9}, {%0,%1,%2,%3};"
        : "+f"(c[0]), "+f"(c[1]), "+f"(c[2]), "+f"(c[3])
        : "r"(a[0]), "r"(a[1]), "r"(a[2]), "r"(a[3]), "r"(b[0]), "r"(b[1]));
}

__device__ __forceinline__ void mma_bf(float* c, const uint32_t* a, const uint32_t* b) {
    asm volatile(
        "mma.sync.aligned.m16n8k16.row.col.f32.bf16.bf16.f32 "
        "{%0,%1,%2,%3}, {%4,%5,%6,%7}, {%8,%9}, {%0,%1,%2,%3};"
        : "+f"(c[0]), "+f"(c[1]), "+f"(c[2]), "+f"(c[3])
        : "r"(a[0]), "r"(a[1]), "r"(a[2]), "r"(a[3]), "r"(b[0]), "r"(b[1]));
}

__device__ __forceinline__ uint32_t pack_bf16(float a, float b) {
    uint32_t lo = (uint32_t)__bfloat16_as_ushort(__float2bfloat16_rn(a));
    uint32_t hi = (uint32_t)__bfloat16_as_ushort(__float2bfloat16_rn(b));
    return lo | (hi << 16);
}

// ---------------- conversion kernels ---------------------------------------
__global__ void cvt_half_kernel(const float4* __restrict__ x,
                                __half2* __restrict__ h, int n4)
{
    for (int i = blockIdx.x * blockDim.x + threadIdx.x; i < n4;
         i += gridDim.x * blockDim.x) {
        float4 v = x[i];
        h[2*i]   = __floats2half2_rn(v.x, v.y);
        h[2*i+1] = __floats2half2_rn(v.z, v.w);
    }
}

__global__ void wsplit_kernel(const float4* __restrict__ x,
                              __half2* __restrict__ h,
                              __half2* __restrict__ l, int n4)
{
    for (int i = blockIdx.x * blockDim.x + threadIdx.x; i < n4;
         i += gridDim.x * blockDim.x) {
        float4 v = x[i];
        float sx = v.x * WSCALE, sy = v.y * WSCALE;
        float sz = v.z * WSCALE, sw = v.w * WSCALE;
        __half hx = __float2half_rn(sx), hy = __float2half_rn(sy);
        __half hz = __float2half_rn(sz), hw = __float2half_rn(sw);
        h[2*i]   = __halves2half2(hx, hy);
        h[2*i+1] = __halves2half2(hz, hw);
        l[2*i]   = __floats2half2_rn(sx - __half2float(hx), sy - __half2float(hy));
        l[2*i+1] = __floats2half2_rn(sz - __half2float(hz), sw - __half2float(hw));
    }
}

// ---------------- fp16 2-pass tensor-core GEMM ------------------------------
// C = (1/64) * Ah @ (Wh + Wl)^T + bias. Tiles 128x128, K chunk 32, 3-stage.
#define KCH 32
#define GSTAGE 24576u        // 3 tiles x 8KB
#define GEMM_SMEM (3u * GSTAGE)

struct GDesc {
    const __half* A;
    const __half* Wh;
    const __half* Wl;
    const float*  bias;
    float* C;
    int Mtot, RB;
    long long sA, sC;
    int N, K;
};
struct GDesc6 { GDesc d[6]; };

__device__ __forceinline__ void gemm_core(const GDesc g)
{
    extern __shared__ char smem[];
    const uint32_t sm = smem_u32(smem);

    const int t    = threadIdx.x;
    const int lane = t & 31;
    const int wid  = t >> 5;
    const int wm   = wid & 1;
    const int wn   = wid >> 1;
    const int m0   = blockIdx.y * 128;
    const int n0   = blockIdx.x * 128;
    if (m0 >= g.Mtot) return;

    float acc[4][4][4];
    #pragma unroll
    for (int i = 0; i < 4; ++i)
        #pragma unroll
        for (int j = 0; j < 4; ++j)
            #pragma unroll
            for (int k = 0; k < 4; ++k) acc[i][j][k] = 0.f;

    const int NC = g.K / KCH;

    auto issue = [&](int c) {
        const int k0 = c * KCH;
        const uint32_t sbase = sm + (uint32_t)(c % 3) * GSTAGE;
        #pragma unroll
        for (int i = 0; i < 2; ++i) {
            int task = t + i * 256;
            int gr   = task >> 2;
            int kc   = task & 3;
            uint32_t sw  = (uint32_t)(kc ^ ((gr >> 1) & 3));
            uint32_t dst = sbase + (uint32_t)gr * 64u + sw * 16u;
            int grow = m0 + gr;
            int pred = grow < g.Mtot;
            long long off = 0;
            if (pred) {
                int b = grow / g.RB, r = grow % g.RB;
                off = (long long)b * g.sA + (long long)r * g.K + k0 + kc * 8;
            }
            cp_async16(dst, g.A + off, pred);
            long long boff = (long long)(n0 + gr) * g.K + k0 + kc * 8;
            cp_async16(dst + 8192u,  g.Wh + boff, 1);
            cp_async16(dst + 16384u, g.Wl + boff, 1);
        }
        cp_commit();
    };

    auto compute = [&](int c) {
        const uint32_t sbase = sm + (uint32_t)(c % 3) * GSTAGE;
        #pragma unroll
        for (int ks = 0; ks < 2; ++ks) {
            uint32_t af[16], bh[8], bl[8];
            #pragma unroll
            for (int mt = 0; mt < 4; ++mt) {
                int arow = wm * 64 + mt * 16 + (lane & 15);
                int ach  = ks * 2 + (lane >> 4);
                uint32_t addr = sbase + (uint32_t)arow * 64u
                              + (uint32_t)((ach ^ ((arow >> 1) & 3)) * 16);
                ldm4(af[mt*4], af[mt*4+1], af[mt*4+2], af[mt*4+3], addr);
            }
            #pragma unroll
            for (int nt2 = 0; nt2 < 2; ++nt2) {
                int brow = wn * 32 + nt2 * 16 + ((lane >> 4) & 1) * 8 + (lane & 7);
                int bch  = ks * 2 + ((lane >> 3) & 1);
                uint32_t addr = sbase + 8192u + (uint32_t)brow * 64u
                              + (uint32_t)((bch ^ ((brow >> 1) & 3)) * 16);
                ldm4(bh[nt2*4], bh[nt2*4+1], bh[nt2*4+2], bh[nt2*4+3], addr);
            }
            #pragma unroll
            for (int mt = 0; mt < 4; ++mt)
                #pragma unroll
                for (int nt = 0; nt < 4; ++nt)
                    mma_h(acc[mt][nt], &af[mt*4], &bh[(nt >> 1)*4 + (nt & 1)*2]);
            #pragma unroll
            for (int nt2 = 0; nt2 < 2; ++nt2) {
                int brow = wn * 32 + nt2 * 16 + ((lane >> 4) & 1) * 8 + (lane & 7);
                int bch  = ks * 2 + ((lane >> 3) & 1);
                uint32_t addr = sbase + 16384u + (uint32_t)brow * 64u
                              + (uint32_t)((bch ^ ((brow >> 1) & 3)) * 16);
                ldm4(bl[nt2*4], bl[nt2*4+1], bl[nt2*4+2], bl[nt2*4+3], addr);
            }
            #pragma unroll
            for (int mt = 0; mt < 4; ++mt)
                #pragma unroll
                for (int nt = 0; nt < 4; ++nt)
                    mma_h(acc[mt][nt], &af[mt*4], &bl[(nt >> 1)*4 + (nt & 1)*2]);
        }
    };

    issue(0);
    issue(1);
    for (int c = 0; c < NC; ++c) {
        if (c + 1 < NC) { cp_wait<1>(); } else { cp_wait<0>(); }
        __syncthreads();
        compute(c);
        if (c + 2 < NC) issue(c + 2);
    }

    const int gg = lane >> 2;
    const int q4 = lane & 3;
    #pragma unroll
    for (int mt = 0; mt < 4; ++mt) {
        #pragma unroll
        for (int half = 0; half < 2; ++half) {
            int grow = m0 + wm * 64 + mt * 16 + gg + half * 8;
            if (grow < g.Mtot) {
                int b = grow / g.RB, r = grow % g.RB;
                float* crow = g.C + (long long)b * g.sC + (long long)r * g.N
                            + n0 + wn * 32;
                #pragma unroll
                for (int nt = 0; nt < 4; ++nt) {
                    int ncol = nt * 8 + q4 * 2;
                    float2 v;
                    v.x = acc[mt][nt][half*2+0] * INV_WSCALE;
                    v.y = acc[mt][nt][half*2+1] * INV_WSCALE;
                    if (g.bias) {
                        v.x += g.bias[n0 + wn*32 + ncol];
                        v.y += g.bias[n0 + wn*32 + ncol + 1];
                    }
                    *(float2*)&crow[ncol] = v;
                }
            }
        }
    }
}

__global__ __launch_bounds__(256)
void gemm_one(GDesc g) { gemm_core(g); }

__global__ __launch_bounds__(256)
void gemm_multi(GDesc6 ds) { gemm_core(ds.d[blockIdx.z]); }

// ---------------- Tensor-core attention (3xBF16, whole KV in smem) ---------
#define ATT_SMEM (160u * 1024u)
#define AQH 0u
#define AQL 16384u
#define AKH 32768u
#define AKL 65536u
#define AVH 98304u
#define AVL 131072u

__global__ __launch_bounds__(256)
void attn_tc(const float* __restrict__ Qg, const float* __restrict__ Kg,
             const float* __restrict__ Vg, float* __restrict__ Og,
             int Sq, int Skv, int accumulate)
{
    extern __shared__ char smem[];
    char* smc = smem;
    const uint32_t sm = smem_u32(smem);

    const int t  = threadIdx.x;
    const int b  = blockIdx.z;
    const int h  = blockIdx.y;
    const int q0 = blockIdx.x * 128;

    const float* Qb = Qg + ((long long)b * Sq)  * CDIM + h * HD;
    const float* Kb = Kg + ((long long)b * Skv) * CDIM + h * HD;
    const float* Vb = Vg + ((long long)b * Skv) * CDIM + h * HD;
    float*       Ob = Og + ((long long)b * Sq)  * CDIM + h * HD;

    #pragma unroll
    for (int i = 0; i < 8; ++i) {
        int lin = t + i * 256;
        int row = lin >> 4;
        int c4  = lin & 15;
        float4 v = make_float4(0.f, 0.f, 0.f, 0.f);
        if (q0 + row < Sq)
            v = *(const float4*)&Qb[(long long)(q0 + row) * CDIM + c4 * 4];
        __nv_bfloat16 hx = __float2bfloat16_rn(v.x), hy = __float2bfloat16_rn(v.y);
        __nv_bfloat16 hz = __float2bfloat16_rn(v.z), hw = __float2bfloat16_rn(v.w);
        uint2 hv, lv;
        hv.x = pack_bf16(__bfloat162float(hx), __bfloat162float(hy));
        hv.y = pack_bf16(__bfloat162float(hz), __bfloat162float(hw));
        lv.x = pack_bf16(v.x - __bfloat162float(hx), v.y - __bfloat162float(hy));
        lv.y = pack_bf16(v.z - __bfloat162float(hz), v.w - __bfloat162float(hw));
        int ch = c4 >> 1, halfq = c4 & 1;
        uint32_t off = (uint32_t)row * 128u + (uint32_t)((ch ^ (row & 7)) * 16)
                     + (uint32_t)halfq * 8u;
        *(uint2*)(smc + AQH + off) = hv;
        *(uint2*)(smc + AQL + off) = lv;
    }
    #pragma unroll
    for (int i = 0; i < 16; ++i) {
        int lin = t + i * 256;
        int row = lin >> 4;
        int c4  = lin & 15;
        float4 kv4 = make_float4(0.f, 0.f, 0.f, 0.f);
        float4 vv4 = make_float4(0.f, 0.f, 0.f, 0.f);
        if (row < Skv) {
            kv4 = *(const float4*)&Kb[(long long)row * CDIM + c4 * 4];
            vv4 = *(const float4*)&Vb[(long long)row * CDIM + c4 * 4];
        }
        {
            __nv_bfloat16 hx = __float2bfloat16_rn(kv4.x), hy = __float2bfloat16_rn(kv4.y);
            __nv_bfloat16 hz = __float2bfloat16_rn(kv4.z), hw = __float2bfloat16_rn(kv4.w);
            uint2 hv, lv;
            hv.x = pack_bf16(__bfloat162float(hx), __bfloat162float(hy));
            hv.y = pack_bf16(__bfloat162float(hz), __bfloat162float(hw));
            lv.x = pack_bf16(kv4.x - __bfloat162float(hx), kv4.y - __bfloat162float(hy));
            lv.y = pack_bf16(kv4.z - __bfloat162float(hz), kv4.w - __bfloat162float(hw));
            int ch = c4 >> 1, halfq = c4 & 1;
            uint32_t off = (uint32_t)row * 128u + (uint32_t)((ch ^ (row & 7)) * 16)
                         + (uint32_t)halfq * 8u;
            *(uint2*)(smc + AKH + off) = hv;
            *(uint2*)(smc + AKL + off) = lv;
        }
        float ve[4] = {vv4.x, vv4.y, vv4.z, vv4.w};
        #pragma unroll
        for (int j = 0; j < 4; ++j) {
            int d = c4 * 4 + j;
            __nv_bfloat16 hb = __float2bfloat16_rn(ve[j]);
            __nv_bfloat16 lb = __float2bfloat16_rn(ve[j] - __bfloat162float(hb));
            uint32_t off = (uint32_t)d * 512u
                         + (uint32_t)((((row >> 3) ^ (d & 7)) * 16))
                         + (uint32_t)(row & 7) * 2u;
            *(__nv_bfloat16*)(smc + AVH + off) = hb;
            *(__nv_bfloat16*)(smc + AVL + off) = lb;
        }
    }
    __syncthreads();

    const int lane  = t & 31;
    const int wid   = t >> 5;
    const int qbase = wid * 16;

    float O[8][4];
    #pragma unroll
    for (int nt = 0; nt < 8; ++nt)
        #pragma unroll
        for (int e = 0; e < 4; ++e) O[nt][e] = 0.f;
    float mrow[2] = {-1e30f, -1e30f};
    float lrow[2] = {0.f, 0.f};

    const int nch = (Skv + 63) / 64;
    for (int c = 0; c < nch; ++c) {
        float S[8][4];
        #pragma unroll
        for (int nt = 0; nt < 8; ++nt)
            #pragma unroll
            for (int e = 0; e < 4; ++e) S[nt][e] = 0.f;

        #pragma unroll
        for (int ks = 0; ks < 4; ++ks) {
            uint32_t qh[4], ql[4], kh[4], kl[4];
            int arow = qbase + (lane & 15);
            int ach  = 2 * ks + (lane >> 4);
            uint32_t aoff = (uint32_t)arow * 128u + (uint32_t)((ach ^ (arow & 7)) * 16);
            ldm4(qh[0], qh[1], qh[2], qh[3], sm + AQH + aoff);
            ldm4(ql[0], ql[1], ql[2], ql[3], sm + AQL + aoff);
            #pragma unroll
            for (int nt2 = 0; nt2 < 4; ++nt2) {
                int brow = c * 64 + nt2 * 16 + ((lane >> 4) & 1) * 8 + (lane & 7);
                int bch  = 2 * ks + ((lane >> 3) & 1);
                uint32_t boff = (uint32_t)brow * 128u
                              + (uint32_t)((bch ^ (brow & 7)) * 16);
                ldm4(kh[0], kh[1], kh[2], kh[3], sm + AKH + boff);
                ldm4(kl[0], kl[1], kl[2], kl[3], sm + AKL + boff);
                #pragma unroll
                for (int sub = 0; sub < 2; ++sub) {
                    int nt = nt2 * 2 + sub;
                    mma_bf(S[nt], qh, &kh[sub*2]);
                    mma_bf(S[nt], qh, &kl[sub*2]);
                    mma_bf(S[nt], ql, &kh[sub*2]);
                }
            }
        }

        #pragma unroll
        for (int nt = 0; nt < 8; ++nt) {
            int col0 = c * 64 + nt * 8 + 2 * (lane & 3);
            #pragma unroll
            for (int e = 0; e < 4; ++e) {
                int col = col0 + (e & 1);
                float v = S[nt][e] * ATTN_SCALE;
                S[nt][e] = (col < Skv) ? v : -1e30f;
            }
        }

        float mx[2] = {-1e30f, -1e30f};
        #pragma unroll
        for (int nt = 0; nt < 8; ++nt) {
            mx[0] = fmaxf(mx[0], fmaxf(S[nt][0], S[nt][1]));
            mx[1] = fmaxf(mx[1], fmaxf(S[nt][2], S[nt][3]));
        }
        #pragma unroll
        for (int off = 1; off <= 2; off <<= 1) {
            mx[0] = fmaxf(mx[0], __shfl_xor_sync(0xffffffffu, mx[0], off));
            mx[1] = fmaxf(mx[1], __shfl_xor_sync(0xffffffffu, mx[1], off));
        }
        float mnew0 = fmaxf(mrow[0], mx[0]);
        float mnew1 = fmaxf(mrow[1], mx[1]);
        float corr0 = __expf(mrow[0] - mnew0);
        float corr1 = __expf(mrow[1] - mnew1);

        float ls[2] = {0.f, 0.f};
        #pragma unroll
        for (int nt = 0; nt < 8; ++nt) {
            S[nt][0] = __expf(S[nt][0] - mnew0); ls[0] += S[nt][0];
            S[nt][1] = __expf(S[nt][1] - mnew0); ls[0] += S[nt][1];
            S[nt][2] = __expf(S[nt][2] - mnew1); ls[1] += S[nt][2];
            S[nt][3] = __expf(S[nt][3] - mnew1); ls[1] += S[nt][3];
        }
        #pragma unroll
        for (int off = 1; off <= 2; off <<= 1) {
            ls[0] += __shfl_xor_sync(0xffffffffu, ls[0], off);
            ls[1] += __shfl_xor_sync(0xffffffffu, ls[1], off);
        }
        lrow[0] = lrow[0] * corr0 + ls[0];
        lrow[1] = lrow[1] * corr1 + ls[1];
        mrow[0] = mnew0; mrow[1] = mnew1;
        #pragma unroll
        for (int nt = 0; nt < 8; ++nt) {
            O[nt][0] *= corr0; O[nt][1] *= corr0;
            O[nt][2] *= corr1; O[nt][3] *= corr1;
        }

        #pragma unroll
        for (int ks = 0; ks < 4; ++ks) {
            uint32_t aph[4], apl[4];
            {
                int T0 = 2 * ks, T1 = 2 * ks + 1;
                float p0 = S[T0][0], p1 = S[T0][1], p2 = S[T0][2], p3 = S[T0][3];
                float r0 = S[T1][0], r1 = S[T1][1], r2 = S[T1][2], r3 = S[T1][3];
                float h0 = __bfloat162float(__float2bfloat16_rn(p0));
                float h1 = __bfloat162float(__float2bfloat16_rn(p1));
                float h2 = __bfloat162float(__float2bfloat16_rn(p2));
                float h3 = __bfloat162float(__float2bfloat16_rn(p3));
                float g0 = __bfloat162float(__float2bfloat16_rn(r0));
                float g1 = __bfloat162float(__float2bfloat16_rn(r1));
                float g2 = __bfloat162float(__float2bfloat16_rn(r2));
                float g3 = __bfloat162float(__float2bfloat16_rn(r3));
                aph[0] = pack_bf16(h0, h1); aph[1] = pack_bf16(h2, h3);
                aph[2] = pack_bf16(g0, g1); aph[3] = pack_bf16(g2, g3);
                apl[0] = pack_bf16(p0 - h0, p1 - h1);
                apl[1] = pack_bf16(p2 - h2, p3 - h3);
                apl[2] = pack_bf16(r0 - g0, r1 - g1);
                apl[3] = pack_bf16(r2 - g2, r3 - g3);
            }
            #pragma unroll
            for (int nt2 = 0; nt2 < 4; ++nt2) {
                uint32_t vh[4], vl[4];
                int vrow = nt2 * 16 + ((lane >> 4) & 1) * 8 + (lane & 7);
                int vch  = c * 8 + 2 * ks + ((lane >> 3) & 1);
                uint32_t voff = (uint32_t)vrow * 512u
                              + (uint32_t)(((vch ^ (vrow & 7))) * 16);
                ldm4(vh[0], vh[1], vh[2], vh[3], sm + AVH + voff);
                ldm4(vl[0], vl[1], vl[2], vl[3], sm + AVL + voff);
                #pragma unroll
                for (int sub = 0; sub < 2; ++sub) {
                    int nt = nt2 * 2 + sub;
                    mma_bf(O[nt], aph, &vh[sub*2]);
                    mma_bf(O[nt], aph, &vl[sub*2]);
                    mma_bf(O[nt], apl, &vh[sub*2]);
                }
            }
        }
    }

    float inv0 = 1.f / lrow[0];
    float inv1 = 1.f / lrow[1];
    #pragma unroll
    for (int halfq = 0; halfq < 2; ++halfq) {
        int row = q0 + qbase + (lane >> 2) + halfq * 8;
        if (row < Sq) {
            float inv = halfq ? inv1 : inv0;
            float* op = Ob + (long long)row * CDIM;
            #pragma unroll
            for (int nt = 0; nt < 8; ++nt) {
                int d = nt * 8 + 2 * (lane & 3);
                float2 v;
                v.x = O[nt][halfq*2+0] * inv;
                v.y = O[nt][halfq*2+1] * inv;
                if (accumulate) {
                    float2 old = *(float2*)&op[d];
                    v.x += old.x; v.y += old.y;
                }
                *(float2*)&op[d] = v;
            }
        }
    }
}

// ---------------- host orchestration ---------------------------------------
static inline void launch_cvt(const float* x, __half* h, long long n)
{
    int n4 = (int)(n / 4);
    int blocks = (n4 + 255) / 256;
    if (blocks > 4096) blocks = 4096;
    cvt_half_kernel<<<blocks, 256>>>((const float4*)x, (__half2*)h, n4);
}

static inline void launch_wsplit(const float* x, __half* h, __half* l, long long n)
{
    int n4 = (int)(n / 4);
    int blocks = (n4 + 255) / 256;
    if (blocks > 4096) blocks = 4096;
    wsplit_kernel<<<blocks, 256>>>((const float4*)x, (__half2*)h, (__half2*)l, n4);
}

static inline void launch_attn(const float* Q, const float* K, const float* V,
                               float* O, int Sq, int Skv, int accumulate)
{
    cudaFuncSetAttribute(attn_tc, cudaFuncAttributeMaxDynamicSharedMemorySize,
                         ATT_SMEM);
    dim3 grid((Sq + 127) / 128, HEADS, B_);
    attn_tc<<<grid, 256, ATT_SMEM>>>(Q, K, V, O, Sq, Skv, accumulate);
}

template <typename T>
static inline T* sym(const void* s) { void* p; cudaGetSymbolAddress(&p, s); return (T*)p; }

extern "C" void kernel_launch(void* const* d_in, const int* in_sizes, int n_in,
                              void* d_out, int out_size)
{
    const float* hidden = (const float*)d_in[0];
    const float* enc    = (const float*)d_in[1];
    const float* w_q    = (const float*)d_in[2];
    const float* w_k    = (const float*)d_in[3];
    const float* w_v    = (const float*)d_in[4];
    const float* w_kb   = (const float*)d_in[5];
    const float* w_vb   = (const float*)d_in[6];
    const float* w_kc   = (const float*)d_in[7];
    const float* w_vc   = (const float*)d_in[8];
    const float* w_out  = (const float*)d_in[9];
    const float* b_out  = (const float*)d_in[10];
    float* out = (float*)d_out;

    float* pq  = sym<float>(&g_q);
    float* po  = sym<float>(&g_o);
    float* pk  = sym<float>(&g_k);
    float* pv  = sym<float>(&g_v);
    float* pbk = sym<float>(&g_bk);
    float* pbv = sym<float>(&g_bv);
    float* pck = sym<float>(&g_ck);
    float* pcv = sym<float>(&g_cv);

    __half* hidh = sym<__half>(&a_hid);
    __half* ench = sym<__half>(&a_enc);
    __half* poh  = sym<__half>(&a_po);
    __half* wqh  = sym<__half>(&w_q_h),  *wql  = sym<__half>(&w_q_l);
    __half* wkh  = sym<__half>(&w_k_h),  *wkl  = sym<__half>(&w_k_l);
    __half* wvh  = sym<__half>(&w_v_h),  *wvl  = sym<__half>(&w_v_l);
    __half* wkbh = sym<__half>(&w_kb_h), *wkbl = sym<__half>(&w_kb_l);
    __half* wvbh = sym<__half>(&w_vb_h), *wvbl = sym<__half>(&w_vb_l);
    __half* wkch = sym<__half>(&w_kc_h), *wkcl = sym<__half>(&w_kc_l);
    __half* wvch = sym<__half>(&w_vc_h), *wvcl = sym<__half>(&w_vc_l);
    __half* woh  = sym<__half>(&w_o_h),  *wol  = sym<__half>(&w_o_l);

    const long long bsEnc = (long long)LLEN * CROSSD;
    const long long encN  = (long long)B_ * LLEN * CROSSD;
    const long long hidN  = (long long)B_ * QLEN * CDIM;
    const long long boxOff = (long long)EHS_LEN * CROSSD;
    const long long clsOff = (long long)(EHS_LEN + NTOK) * CROSSD;

    cudaFuncSetAttribute(gemm_one,   cudaFuncAttributeMaxDynamicSharedMemorySize, GEMM_SMEM);
    cudaFuncSetAttribute(gemm_multi, cudaFuncAttributeMaxDynamicSharedMemorySize, GEMM_SMEM);

    // Launches 1-5: conversions needed by the q-projection
    launch_cvt(hidden, hidh, hidN);
    launch_wsplit(w_q, wqh, wql, (long long)CDIM*CDIM);
    launch_cvt(enc, ench, encN);
    launch_wsplit(w_k, wkh, wkl, (long long)CDIM*CROSSD);
    launch_wsplit(w_v, wvh, wvl, (long long)CDIM*CROSSD);

    // Launch 6 (ncu -s 5 -c 1 profiles this): q-projection GEMM
    {
        GDesc g = { hidh, wqh, wql, nullptr, pq,
                    B_*QLEN, B_*QLEN, 0, 0, CDIM, CDIM };
        dim3 grid(CDIM/128, (B_*QLEN + 127)/128, 1);
        gemm_one<<<grid, 256, GEMM_SMEM>>>(g);
    }

    // Remaining weight splits
    launch_wsplit(w_kb,  wkbh, wkbl, (long long)CDIM*CROSSD);
    launch_wsplit(w_vb,  wvbh, wvbl, (long long)CDIM*CROSSD);
    launch_wsplit(w_kc,  wkch, wkcl, (long long)CDIM*CROSSD);
    launch_wsplit(w_vc,  wvch, wvcl, (long long)CDIM*CROSSD);
    launch_wsplit(w_out, woh,  wol,  (long long)CDIM*CDIM);

    // Merged 6-way encoder projection launch
    {
        GDesc6 ds;
        const long long sEk = (long long)EHS_LEN*CDIM;
        const long long sNk = (long long)NTOK*CDIM;
        ds.d[0] = { ench,          wkh,  wkl,  nullptr, pk,  B_*EHS_LEN, EHS_LEN, bsEnc, sEk, CDIM, CROSSD };
        ds.d[1] = { ench,          wvh,  wvl,  nullptr, pv,  B_*EHS_LEN, EHS_LEN, bsEnc, sEk, CDIM, CROSSD };
        ds.d[2] = { ench + boxOff, wkbh, wkbl, nullptr, pbk, B_*NTOK,    NTOK,    bsEnc, sNk, CDIM, CROSSD };
        ds.d[3] = { ench + boxOff, wvbh, wvbl, nullptr, pbv, B_*NTOK,    NTOK,    bsEnc, sNk, CDIM, CROSSD };
        ds.d[4] = { ench + clsOff, wkch, wkcl, nullptr, pck, B_*NTOK,    NTOK,    bsEnc, sNk, CDIM, CROSSD };
        ds.d[5] = { ench + clsOff, wvch, wvcl, nullptr, pcv, B_*NTOK,    NTOK,    bsEnc, sNk, CDIM, CROSSD };
        dim3 grid(CDIM/128, (B_*NTOK + 127)/128, 6);   // grid.y = 25 covers all
        gemm_multi<<<grid, 256, GEMM_SMEM>>>(ds);
    }

    // Attention chain (tensor cores, 3xBF16)
    launch_attn(pq,  pk,  pv,  po,  QLEN, EHS_LEN, 0);
    launch_attn(pbk, pck, pcv, pbk, NTOK, NTOK,    1);
    launch_attn(pbv, pck, pcv, pbv, NTOK, NTOK,    1);
    launch_attn(pq,  pbk, pbv, po,  QLEN, NTOK,    1);

    // Out-projection (+bias) into d_out
    launch_cvt(po, poh, hidN);
    {
        GDesc g = { poh, woh, wol, b_out, out,
                    B_*QLEN, B_*QLEN, 0, 0, CDIM, CDIM };
        dim3 grid(CDIM/128, (B_*QLEN + 127)/128, 1);
        gemm_one<<<grid, 256, GEMM_SMEM>>>(g);
    }
}

// round 6
// speedup vs baseline: 5.1535x; 1.0040x over previous
#include <cuda_runtime.h>
#include <cuda_bf16.h>
#include <cuda_fp16.h>
#include <cstdint>

// Problem constants
#define B_      16
#define QLEN    1024
#define CDIM    1280
#define LLEN    477
#define CROSSD  2048
#define NTOK    200
#define HEADS   20
#define HD      64
#define EHS_LEN 77           // 477 - 200 - 200
#define ATTN_SCALE 0.125f    // 1/sqrt(64)
#define WSCALE     64.0f
#define INV_WSCALE 0.015625f

// ---------------- scratch (device globals; no runtime allocation) ----------
__device__ float g_q [B_*QLEN*CDIM];
__device__ float g_o [B_*QLEN*CDIM];
__device__ float g_k [B_*EHS_LEN*CDIM];
__device__ float g_v [B_*EHS_LEN*CDIM];
__device__ float g_bk[B_*NTOK*CDIM];
__device__ float g_bv[B_*NTOK*CDIM];
__device__ float g_ck[B_*NTOK*CDIM];
__device__ float g_cv[B_*NTOK*CDIM];

// fp16 activations (hi only) and scaled hi/lo weights
__device__ __half a_hid[B_*QLEN*CDIM];
__device__ __half a_enc[B_*LLEN*CROSSD];
__device__ __half a_po [B_*QLEN*CDIM];
__device__ __half w_q_h [CDIM*CDIM],   w_q_l [CDIM*CDIM];
__device__ __half w_k_h [CDIM*CROSSD], w_k_l [CDIM*CROSSD];
__device__ __half w_v_h [CDIM*CROSSD], w_v_l [CDIM*CROSSD];
__device__ __half w_kb_h[CDIM*CROSSD], w_kb_l[CDIM*CROSSD];
__device__ __half w_vb_h[CDIM*CROSSD], w_vb_l[CDIM*CROSSD];
__device__ __half w_kc_h[CDIM*CROSSD], w_kc_l[CDIM*CROSSD];
__device__ __half w_vc_h[CDIM*CROSSD], w_vc_l[CDIM*CROSSD];
__device__ __half w_o_h [CDIM*CDIM],   w_o_l [CDIM*CDIM];

// ---------------- helpers ---------------------------------------------------
__device__ __forceinline__ uint32_t smem_u32(const void* p) {
    uint32_t a;
    asm("{ .reg .u64 t; cvta.to.shared.u64 t, %1; cvt.u32.u64 %0, t; }"
        : "=r"(a) : "l"(p));
    return a;
}

__device__ __forceinline__ void cp_async16(uint32_t dst, const void* src, int pred) {
    int sz = pred ? 16 : 0;
    asm volatile("cp.async.cg.shared.global [%0], [%1], 16, %2;"
                 :: "r"(dst), "l"(src), "r"(sz) : "memory");
}
__device__ __forceinline__ void cp_commit() {
    asm volatile("cp.async.commit_group;" ::: "memory");
}
template <int N>
__device__ __forceinline__ void cp_wait() {
    asm volatile("cp.async.wait_group %0;" :: "n"(N) : "memory");
}

__device__ __forceinline__ void ldm4(uint32_t& r0, uint32_t& r1, uint32_t& r2,
                                     uint32_t& r3, uint32_t addr) {
    asm volatile("ldmatrix.sync.aligned.m8n8.x4.shared.b16 {%0,%1,%2,%3}, [%4];"
                 : "=r"(r0), "=r"(r1), "=r"(r2), "=r"(r3) : "r"(addr));
}

__device__ __forceinline__ void mma_h(float* c, const uint32_t* a, const uint32_t* b) {
    asm volatile(
        "mma.sync.aligned.m16n8k16.row.col.f32.f16.f16.f32 "
        "{%0,%1,%2,%3}, {%4,%5,%6,%7}, {%8,%9}, {%0,%1,%2,%3};"
        : "+f"(c[0]), "+f"(c[1]), "+f"(c[2]), "+f"(c[3])
        : "r"(a[0]), "r"(a[1]), "r"(a[2]), "r"(a[3]), "r"(b[0]), "r"(b[1]));
}

__device__ __forceinline__ void mma_bf(float* c, const uint32_t* a, const uint32_t* b) {
    asm volatile(
        "mma.sync.aligned.m16n8k16.row.col.f32.bf16.bf16.f32 "
        "{%0,%1,%2,%3}, {%4,%5,%6,%7}, {%8,%9}, {%0,%1,%2,%3};"
        : "+f"(c[0]), "+f"(c[1]), "+f"(c[2]), "+f"(c[3])
        : "r"(a[0]), "r"(a[1]), "r"(a[2]), "r"(a[3]), "r"(b[0]), "r"(b[1]));
}

__device__ __forceinline__ uint32_t pack_bf16(float a, float b) {
    uint32_t lo = (uint32_t)__bfloat16_as_ushort(__float2bfloat16_rn(a));
    uint32_t hi = (uint32_t)__bfloat16_as_ushort(__float2bfloat16_rn(b));
    return lo | (hi << 16);
}

// ---------------- conversion kernels ---------------------------------------
__global__ void cvt_half_kernel(const float4* __restrict__ x,
                                __half2* __restrict__ h, int n4)
{
    for (int i = blockIdx.x * blockDim.x + threadIdx.x; i < n4;
         i += gridDim.x * blockDim.x) {
        float4 v = x[i];
        h[2*i]   = __floats2half2_rn(v.x, v.y);
        h[2*i+1] = __floats2half2_rn(v.z, v.w);
    }
}

__device__ __forceinline__ void wsplit_body(const float4* x, __half2* h, __half2* l,
                                            int n4)
{
    for (int i = blockIdx.x * blockDim.x + threadIdx.x; i < n4;
         i += gridDim.x * blockDim.x) {
        float4 v = x[i];
        float sx = v.x * WSCALE, sy = v.y * WSCALE;
        float sz = v.z * WSCALE, sw = v.w * WSCALE;
        __half hx = __float2half_rn(sx), hy = __float2half_rn(sy);
        __half hz = __float2half_rn(sz), hw = __float2half_rn(sw);
        h[2*i]   = __halves2half2(hx, hy);
        h[2*i+1] = __halves2half2(hz, hw);
        l[2*i]   = __floats2half2_rn(sx - __half2float(hx), sy - __half2float(hy));
        l[2*i+1] = __floats2half2_rn(sz - __half2float(hz), sw - __half2float(hw));
    }
}

__global__ void wsplit_kernel(const float4* __restrict__ x,
                              __half2* __restrict__ h,
                              __half2* __restrict__ l, int n4)
{ wsplit_body(x, h, l, n4); }

struct WDesc { const float4* x; __half2* h; __half2* l; };
struct WPack6 { WDesc d[6]; };

__global__ void wsplit_multi(WPack6 p, int n4)
{
    WDesc d = p.d[blockIdx.z];
    wsplit_body(d.x, d.h, d.l, n4);
}

// ---------------- fp16 2-pass tensor-core GEMM ------------------------------
#define KCH 32
#define GSTAGE 24576u
#define GEMM_SMEM (3u * GSTAGE)

struct GDesc {
    const __half* A;
    const __half* Wh;
    const __half* Wl;
    const float*  bias;
    float* C;
    int Mtot, RB;
    long long sA, sC;
    int N, K;
};
struct GPack {
    GDesc d[7];
    int start[8];      // tile-range prefix; ntiles_n = N/128 = 10 for all
};

__device__ __forceinline__ void gemm_core(const GDesc& g, int m0, int n0)
{
    extern __shared__ char smem[];
    const uint32_t sm = smem_u32(smem);

    const int t    = threadIdx.x;
    const int lane = t & 31;
    const int wid  = t >> 5;
    const int wm   = wid & 1;
    const int wn   = wid >> 1;

    float acc[4][4][4];
    #pragma unroll
    for (int i = 0; i < 4; ++i)
        #pragma unroll
        for (int j = 0; j < 4; ++j)
            #pragma unroll
            for (int k = 0; k < 4; ++k) acc[i][j][k] = 0.f;

    const int NC = g.K / KCH;

    auto issue = [&](int c) {
        const int k0 = c * KCH;
        const uint32_t sbase = sm + (uint32_t)(c % 3) * GSTAGE;
        #pragma unroll
        for (int i = 0; i < 2; ++i) {
            int task = t + i * 256;
            int gr   = task >> 2;
            int kc   = task & 3;
            uint32_t sw  = (uint32_t)(kc ^ ((gr >> 1) & 3));
            uint32_t dst = sbase + (uint32_t)gr * 64u + sw * 16u;
            int grow = m0 + gr;
            int pred = grow < g.Mtot;
            long long off = 0;
            if (pred) {
                int b = grow / g.RB, r = grow % g.RB;
                off = (long long)b * g.sA + (long long)r * g.K + k0 + kc * 8;
            }
            cp_async16(dst, g.A + off, pred);
            long long boff = (long long)(n0 + gr) * g.K + k0 + kc * 8;
            cp_async16(dst + 8192u,  g.Wh + boff, 1);
            cp_async16(dst + 16384u, g.Wl + boff, 1);
        }
        cp_commit();
    };

    auto compute = [&](int c) {
        const uint32_t sbase = sm + (uint32_t)(c % 3) * GSTAGE;
        #pragma unroll
        for (int ks = 0; ks < 2; ++ks) {
            uint32_t af[16], bh[8], bl[8];
            #pragma unroll
            for (int mt = 0; mt < 4; ++mt) {
                int arow = wm * 64 + mt * 16 + (lane & 15);
                int ach  = ks * 2 + (lane >> 4);
                uint32_t addr = sbase + (uint32_t)arow * 64u
                              + (uint32_t)((ach ^ ((arow >> 1) & 3)) * 16);
                ldm4(af[mt*4], af[mt*4+1], af[mt*4+2], af[mt*4+3], addr);
            }
            #pragma unroll
            for (int nt2 = 0; nt2 < 2; ++nt2) {
                int brow = wn * 32 + nt2 * 16 + ((lane >> 4) & 1) * 8 + (lane & 7);
                int bch  = ks * 2 + ((lane >> 3) & 1);
                uint32_t addr = sbase + 8192u + (uint32_t)brow * 64u
                              + (uint32_t)((bch ^ ((brow >> 1) & 3)) * 16);
                ldm4(bh[nt2*4], bh[nt2*4+1], bh[nt2*4+2], bh[nt2*4+3], addr);
            }
            #pragma unroll
            for (int mt = 0; mt < 4; ++mt)
                #pragma unroll
                for (int nt = 0; nt < 4; ++nt)
                    mma_h(acc[mt][nt], &af[mt*4], &bh[(nt >> 1)*4 + (nt & 1)*2]);
            #pragma unroll
            for (int nt2 = 0; nt2 < 2; ++nt2) {
                int brow = wn * 32 + nt2 * 16 + ((lane >> 4) & 1) * 8 + (lane & 7);
                int bch  = ks * 2 + ((lane >> 3) & 1);
                uint32_t addr = sbase + 16384u + (uint32_t)brow * 64u
                              + (uint32_t)((bch ^ ((brow >> 1) & 3)) * 16);
                ldm4(bl[nt2*4], bl[nt2*4+1], bl[nt2*4+2], bl[nt2*4+3], addr);
            }
            #pragma unroll
            for (int mt = 0; mt < 4; ++mt)
                #pragma unroll
                for (int nt = 0; nt < 4; ++nt)
                    mma_h(acc[mt][nt], &af[mt*4], &bl[(nt >> 1)*4 + (nt & 1)*2]);
        }
    };

    issue(0);
    issue(1);
    for (int c = 0; c < NC; ++c) {
        if (c + 1 < NC) { cp_wait<1>(); } else { cp_wait<0>(); }
        __syncthreads();
        compute(c);
        if (c + 2 < NC) issue(c + 2);
    }

    const int gg = lane >> 2;
    const int q4 = lane & 3;
    #pragma unroll
    for (int mt = 0; mt < 4; ++mt) {
        #pragma unroll
        for (int half = 0; half < 2; ++half) {
            int grow = m0 + wm * 64 + mt * 16 + gg + half * 8;
            if (grow < g.Mtot) {
                int b = grow / g.RB, r = grow % g.RB;
                float* crow = g.C + (long long)b * g.sC + (long long)r * g.N
                            + n0 + wn * 32;
                #pragma unroll
                for (int nt = 0; nt < 4; ++nt) {
                    int ncol = nt * 8 + q4 * 2;
                    float2 v;
                    v.x = acc[mt][nt][half*2+0] * INV_WSCALE;
                    v.y = acc[mt][nt][half*2+1] * INV_WSCALE;
                    if (g.bias) {
                        v.x += g.bias[n0 + wn*32 + ncol];
                        v.y += g.bias[n0 + wn*32 + ncol + 1];
                    }
                    *(float2*)&crow[ncol] = v;
                }
            }
        }
    }
}

__global__ __launch_bounds__(256)
void gemm_one(GDesc g)
{
    gemm_core(g, blockIdx.y * 128, blockIdx.x * 128);
}

__global__ __launch_bounds__(256)
void gemm_pack(GPack p)
{
    const int bx = blockIdx.x;
    int di = 0;
    #pragma unroll
    for (int i = 0; i < 7; ++i)
        if (bx >= p.start[i] && bx < p.start[i+1]) di = i;
    const int local = bx - p.start[di];
    gemm_core(p.d[di], (local / 10) * 128, (local % 10) * 128);
}

// ---------------- Tensor-core attention (3xBF16) ----------------------------
#define ATT_SMEM (160u * 1024u)
#define AQH 0u
#define AQL 16384u
#define AKH 32768u
#define AKL 65536u
#define AVH 98304u
#define AVL 131072u

__device__ __forceinline__ void att_stage_q(char* smc, const float* Qb,
                                            int Sq, int q0, int t)
{
    #pragma unroll
    for (int i = 0; i < 8; ++i) {
        int lin = t + i * 256;
        int row = lin >> 4;
        int c4  = lin & 15;
        float4 v = make_float4(0.f, 0.f, 0.f, 0.f);
        if (q0 + row < Sq)
            v = *(const float4*)&Qb[(long long)(q0 + row) * CDIM + c4 * 4];
        __nv_bfloat16 hx = __float2bfloat16_rn(v.x), hy = __float2bfloat16_rn(v.y);
        __nv_bfloat16 hz = __float2bfloat16_rn(v.z), hw = __float2bfloat16_rn(v.w);
        uint2 hv, lv;
        hv.x = pack_bf16(__bfloat162float(hx), __bfloat162float(hy));
        hv.y = pack_bf16(__bfloat162float(hz), __bfloat162float(hw));
        lv.x = pack_bf16(v.x - __bfloat162float(hx), v.y - __bfloat162float(hy));
        lv.y = pack_bf16(v.z - __bfloat162float(hz), v.w - __bfloat162float(hw));
        int ch = c4 >> 1, halfq = c4 & 1;
        uint32_t off = (uint32_t)row * 128u + (uint32_t)((ch ^ (row & 7)) * 16)
                     + (uint32_t)halfq * 8u;
        *(uint2*)(smc + AQH + off) = hv;
        *(uint2*)(smc + AQL + off) = lv;
    }
}

__device__ __forceinline__ void att_stage_kv(char* smc, const float* Kb,
                                             const float* Vb, int Skv, int nkv, int t)
{
    for (int lin = t; lin < nkv * 16; lin += 256) {
        int row = lin >> 4;
        int c4  = lin & 15;
        float4 kv4 = make_float4(0.f, 0.f, 0.f, 0.f);
        float4 vv4 = make_float4(0.f, 0.f, 0.f, 0.f);
        if (row < Skv) {
            kv4 = *(const float4*)&Kb[(long long)row * CDIM + c4 * 4];
            vv4 = *(const float4*)&Vb[(long long)row * CDIM + c4 * 4];
        }
        {
            __nv_bfloat16 hx = __float2bfloat16_rn(kv4.x), hy = __float2bfloat16_rn(kv4.y);
            __nv_bfloat16 hz = __float2bfloat16_rn(kv4.z), hw = __float2bfloat16_rn(kv4.w);
            uint2 hv, lv;
            hv.x = pack_bf16(__bfloat162float(hx), __bfloat162float(hy));
            hv.y = pack_bf16(__bfloat162float(hz), __bfloat162float(hw));
            lv.x = pack_bf16(kv4.x - __bfloat162float(hx), kv4.y - __bfloat162float(hy));
            lv.y = pack_bf16(kv4.z - __bfloat162float(hz), kv4.w - __bfloat162float(hw));
            int ch = c4 >> 1, halfq = c4 & 1;
            uint32_t off = (uint32_t)row * 128u + (uint32_t)((ch ^ (row & 7)) * 16)
                         + (uint32_t)halfq * 8u;
            *(uint2*)(smc + AKH + off) = hv;
            *(uint2*)(smc + AKL + off) = lv;
        }
        float ve[4] = {vv4.x, vv4.y, vv4.z, vv4.w};
        #pragma unroll
        for (int j = 0; j < 4; ++j) {
            int d = c4 * 4 + j;
            __nv_bfloat16 hb = __float2bfloat16_rn(ve[j]);
            __nv_bfloat16 lb = __float2bfloat16_rn(ve[j] - __bfloat162float(hb));
            uint32_t off = (uint32_t)d * 512u
                         + (uint32_t)((((row >> 3) ^ (d & 7)) * 16))
                         + (uint32_t)(row & 7) * 2u;
            *(__nv_bfloat16*)(smc + AVH + off) = hb;
            *(__nv_bfloat16*)(smc + AVL + off) = lb;
        }
    }
}

// online-softmax attention over staged KV; updates (mrow, lrow, O)
__device__ __forceinline__ void att_phase(uint32_t sm, int Skv, int lane, int qbase,
                                          float* mrow, float* lrow, float O[8][4])
{
    const int nch = (Skv + 63) / 64;
    for (int c = 0; c < nch; ++c) {
        float S[8][4];
        #pragma unroll
        for (int nt = 0; nt < 8; ++nt)
            #pragma unroll
            for (int e = 0; e < 4; ++e) S[nt][e] = 0.f;

        #pragma unroll
        for (int ks = 0; ks < 4; ++ks) {
            uint32_t qh[4], ql[4], kh[4], kl[4];
            int arow = qbase + (lane & 15);
            int ach  = 2 * ks + (lane >> 4);
            uint32_t aoff = (uint32_t)arow * 128u + (uint32_t)((ach ^ (arow & 7)) * 16);
            ldm4(qh[0], qh[1], qh[2], qh[3], sm + AQH + aoff);
            ldm4(ql[0], ql[1], ql[2], ql[3], sm + AQL + aoff);
            #pragma unroll
            for (int nt2 = 0; nt2 < 4; ++nt2) {
                int brow = c * 64 + nt2 * 16 + ((lane >> 4) & 1) * 8 + (lane & 7);
                int bch  = 2 * ks + ((lane >> 3) & 1);
                uint32_t boff = (uint32_t)brow * 128u
                              + (uint32_t)((bch ^ (brow & 7)) * 16);
                ldm4(kh[0], kh[1], kh[2], kh[3], sm + AKH + boff);
                ldm4(kl[0], kl[1], kl[2], kl[3], sm + AKL + boff);
                #pragma unroll
                for (int sub = 0; sub < 2; ++sub) {
                    int nt = nt2 * 2 + sub;
                    mma_bf(S[nt], qh, &kh[sub*2]);
                    mma_bf(S[nt], qh, &kl[sub*2]);
                    mma_bf(S[nt], ql, &kh[sub*2]);
                }
            }
        }

        #pragma unroll
        for (int nt = 0; nt < 8; ++nt) {
            int col0 = c * 64 + nt * 8 + 2 * (lane & 3);
            #pragma unroll
            for (int e = 0; e < 4; ++e) {
                int col = col0 + (e & 1);
                float v = S[nt][e] * ATTN_SCALE;
                S[nt][e] = (col < Skv) ? v : -1e30f;
            }
        }

        float mx[2] = {-1e30f, -1e30f};
        #pragma unroll
        for (int nt = 0; nt < 8; ++nt) {
            mx[0] = fmaxf(mx[0], fmaxf(S[nt][0], S[nt][1]));
            mx[1] = fmaxf(mx[1], fmaxf(S[nt][2], S[nt][3]));
        }
        #pragma unroll
        for (int off = 1; off <= 2; off <<= 1) {
            mx[0] = fmaxf(mx[0], __shfl_xor_sync(0xffffffffu, mx[0], off));
            mx[1] = fmaxf(mx[1], __shfl_xor_sync(0xffffffffu, mx[1], off));
        }
        float mnew0 = fmaxf(mrow[0], mx[0]);
        float mnew1 = fmaxf(mrow[1], mx[1]);
        float corr0 = __expf(mrow[0] - mnew0);
        float corr1 = __expf(mrow[1] - mnew1);

        float ls[2] = {0.f, 0.f};
        #pragma unroll
        for (int nt = 0; nt < 8; ++nt) {
            S[nt][0] = __expf(S[nt][0] - mnew0); ls[0] += S[nt][0];
            S[nt][1] = __expf(S[nt][1] - mnew0); ls[0] += S[nt][1];
            S[nt][2] = __expf(S[nt][2] - mnew1); ls[1] += S[nt][2];
            S[nt][3] = __expf(S[nt][3] - mnew1); ls[1] += S[nt][3];
        }
        #pragma unroll
        for (int off = 1; off <= 2; off <<= 1) {
            ls[0] += __shfl_xor_sync(0xffffffffu, ls[0], off);
            ls[1] += __shfl_xor_sync(0xffffffffu, ls[1], off);
        }
        lrow[0] = lrow[0] * corr0 + ls[0];
        lrow[1] = lrow[1] * corr1 + ls[1];
        mrow[0] = mnew0; mrow[1] = mnew1;
        #pragma unroll
        for (int nt = 0; nt < 8; ++nt) {
            O[nt][0] *= corr0; O[nt][1] *= corr0;
            O[nt][2] *= corr1; O[nt][3] *= corr1;
        }

        #pragma unroll
        for (int ks = 0; ks < 4; ++ks) {
            uint32_t aph[4], apl[4];
            {
                int T0 = 2 * ks, T1 = 2 * ks + 1;
                float p0 = S[T0][0], p1 = S[T0][1], p2 = S[T0][2], p3 = S[T0][3];
                float r0 = S[T1][0], r1 = S[T1][1], r2 = S[T1][2], r3 = S[T1][3];
                float h0 = __bfloat162float(__float2bfloat16_rn(p0));
                float h1 = __bfloat162float(__float2bfloat16_rn(p1));
                float h2 = __bfloat162float(__float2bfloat16_rn(p2));
                float h3 = __bfloat162float(__float2bfloat16_rn(p3));
                float g0 = __bfloat162float(__float2bfloat16_rn(r0));
                float g1 = __bfloat162float(__float2bfloat16_rn(r1));
                float g2 = __bfloat162float(__float2bfloat16_rn(r2));
                float g3 = __bfloat162float(__float2bfloat16_rn(r3));
                aph[0] = pack_bf16(h0, h1); aph[1] = pack_bf16(h2, h3);
                aph[2] = pack_bf16(g0, g1); aph[3] = pack_bf16(g2, g3);
                apl[0] = pack_bf16(p0 - h0, p1 - h1);
                apl[1] = pack_bf16(p2 - h2, p3 - h3);
                apl[2] = pack_bf16(r0 - g0, r1 - g1);
                apl[3] = pack_bf16(r2 - g2, r3 - g3);
            }
            #pragma unroll
            for (int nt2 = 0; nt2 < 4; ++nt2) {
                uint32_t vh[4], vl[4];
                int vrow = nt2 * 16 + ((lane >> 4) & 1) * 8 + (lane & 7);
                int vch  = c * 8 + 2 * ks + ((lane >> 3) & 1);
                uint32_t voff = (uint32_t)vrow * 512u
                              + (uint32_t)(((vch ^ (vrow & 7))) * 16);
                ldm4(vh[0], vh[1], vh[2], vh[3], sm + AVH + voff);
                ldm4(vl[0], vl[1], vl[2], vl[3], sm + AVL + voff);
                #pragma unroll
                for (int sub = 0; sub < 2; ++sub) {
                    int nt = nt2 * 2 + sub;
                    mma_bf(O[nt], aph, &vh[sub*2]);
                    mma_bf(O[nt], aph, &vl[sub*2]);
                    mma_bf(O[nt], apl, &vh[sub*2]);
                }
            }
        }
    }
}

// attn2+attn3 merged: X += softmax(X Kc^T) Vc  for X in {bk, bv}
__global__ __launch_bounds__(256)
void attn_pair(float* __restrict__ bk, float* __restrict__ bv,
               const float* __restrict__ ck, const float* __restrict__ cv)
{
    extern __shared__ char smem[];
    char* smc = smem;
    const uint32_t sm = smem_u32(smem);

    const int t  = threadIdx.x;
    const int z  = blockIdx.z;
    const int b  = z >> 1;
    float* Xg = (z & 1) ? bv : bk;
    const int h  = blockIdx.y;
    const int q0 = blockIdx.x * 128;

    const float* Qb = Xg + ((long long)b * NTOK) * CDIM + h * HD;
    const float* Kb = ck + ((long long)b * NTOK) * CDIM + h * HD;
    const float* Vb = cv + ((long long)b * NTOK) * CDIM + h * HD;
    float*       Ob = Xg + ((long long)b * NTOK) * CDIM + h * HD;

    att_stage_q(smc, Qb, NTOK, q0, t);
    att_stage_kv(smc, Kb, Vb, NTOK, 256, t);
    __syncthreads();

    const int lane  = t & 31;
    const int wid   = t >> 5;
    const int qbase = wid * 16;

    float O[8][4];
    #pragma unroll
    for (int nt = 0; nt < 8; ++nt)
        #pragma unroll
        for (int e = 0; e < 4; ++e) O[nt][e] = 0.f;
    float mrow[2] = {-1e30f, -1e30f};
    float lrow[2] = {0.f, 0.f};

    att_phase(sm, NTOK, lane, qbase, mrow, lrow, O);

    float inv0 = 1.f / lrow[0];
    float inv1 = 1.f / lrow[1];
    #pragma unroll
    for (int halfq = 0; halfq < 2; ++halfq) {
        int row = q0 + qbase + (lane >> 2) + halfq * 8;
        if (row < NTOK) {
            float inv = halfq ? inv1 : inv0;
            float* op = Ob + (long long)row * CDIM;
            #pragma unroll
            for (int nt = 0; nt < 8; ++nt) {
                int d = nt * 8 + 2 * (lane & 3);
                float2 old = *(float2*)&op[d];
                float2 v;
                v.x = old.x + O[nt][halfq*2+0] * inv;
                v.y = old.y + O[nt][halfq*2+1] * inv;
                *(float2*)&op[d] = v;
            }
        }
    }
}

// fused main attention: O = softmax(Q K^T)V + softmax(Q bK^T)bV
__global__ __launch_bounds__(256)
void attn_fused(const float* __restrict__ Qg, const float* __restrict__ Kg,
                const float* __restrict__ Vg, const float* __restrict__ bKg,
                const float* __restrict__ bVg, float* __restrict__ Og)
{
    extern __shared__ char smem[];
    char* smc = smem;
    const uint32_t sm = smem_u32(smem);

    const int t  = threadIdx.x;
    const int b  = blockIdx.z;
    const int h  = blockIdx.y;
    const int q0 = blockIdx.x * 128;

    const float* Qb  = Qg  + ((long long)b * QLEN)    * CDIM + h * HD;
    const float* Kb  = Kg  + ((long long)b * EHS_LEN) * CDIM + h * HD;
    const float* Vb  = Vg  + ((long long)b * EHS_LEN) * CDIM + h * HD;
    const float* bKb = bKg + ((long long)b * NTOK)    * CDIM + h * HD;
    const float* bVb = bVg + ((long long)b * NTOK)    * CDIM + h * HD;
    float*       Ob  = Og  + ((long long)b * QLEN)    * CDIM + h * HD;

    att_stage_q(smc, Qb, QLEN, q0, t);
    att_stage_kv(smc, Kb, Vb, EHS_LEN, 128, t);
    __syncthreads();

    const int lane  = t & 31;
    const int wid   = t >> 5;
    const int qbase = wid * 16;

    float O[8][4];
    float mrow[2], lrow[2];
    #pragma unroll
    for (int nt = 0; nt < 8; ++nt)
        #pragma unroll
        for (int e = 0; e < 4; ++e) O[nt][e] = 0.f;
    mrow[0] = mrow[1] = -1e30f;
    lrow[0] = lrow[1] = 0.f;

    // phase 1: ehs attention
    att_phase(sm, EHS_LEN, lane, qbase, mrow, lrow, O);

    float Oacc[8][4];
    {
        float inv0 = 1.f / lrow[0];
        float inv1 = 1.f / lrow[1];
        #pragma unroll
        for (int nt = 0; nt < 8; ++nt) {
            Oacc[nt][0] = O[nt][0] * inv0;
            Oacc[nt][1] = O[nt][1] * inv0;
            Oacc[nt][2] = O[nt][2] * inv1;
            Oacc[nt][3] = O[nt][3] * inv1;
            O[nt][0] = O[nt][1] = O[nt][2] = O[nt][3] = 0.f;
        }
        mrow[0] = mrow[1] = -1e30f;
        lrow[0] = lrow[1] = 0.f;
    }

    // phase 2: box attention (restage KV region)
    __syncthreads();
    att_stage_kv(smc, bKb, bVb, NTOK, 256, t);
    __syncthreads();
    att_phase(sm, NTOK, lane, qbase, mrow, lrow, O);

    float inv0 = 1.f / lrow[0];
    float inv1 = 1.f / lrow[1];
    #pragma unroll
    for (int halfq = 0; halfq < 2; ++halfq) {
        int row = q0 + qbase + (lane >> 2) + halfq * 8;
        if (row < QLEN) {
            float inv = halfq ? inv1 : inv0;
            float* op = Ob + (long long)row * CDIM;
            #pragma unroll
            for (int nt = 0; nt < 8; ++nt) {
                int d = nt * 8 + 2 * (lane & 3);
                float2 v;
                v.x = Oacc[nt][halfq*2+0] + O[nt][halfq*2+0] * inv;
                v.y = Oacc[nt][halfq*2+1] + O[nt][halfq*2+1] * inv;
                *(float2*)&op[d] = v;
            }
        }
    }
}

// ---------------- host orchestration ---------------------------------------
static inline void launch_cvt(const float* x, __half* h, long long n)
{
    int n4 = (int)(n / 4);
    int blocks = (n4 + 255) / 256;
    if (blocks > 4096) blocks = 4096;
    cvt_half_kernel<<<blocks, 256>>>((const float4*)x, (__half2*)h, n4);
}

template <typename T>
static inline T* sym(const void* s) { void* p; cudaGetSymbolAddress(&p, s); return (T*)p; }

extern "C" void kernel_launch(void* const* d_in, const int* in_sizes, int n_in,
                              void* d_out, int out_size)
{
    const float* hidden = (const float*)d_in[0];
    const float* enc    = (const float*)d_in[1];
    const float* w_q    = (const float*)d_in[2];
    const float* w_k    = (const float*)d_in[3];
    const float* w_v    = (const float*)d_in[4];
    const float* w_kb   = (const float*)d_in[5];
    const float* w_vb   = (const float*)d_in[6];
    const float* w_kc   = (const float*)d_in[7];
    const float* w_vc   = (const float*)d_in[8];
    const float* w_out  = (const float*)d_in[9];
    const float* b_out  = (const float*)d_in[10];
    float* out = (float*)d_out;

    float* pq  = sym<float>(&g_q);
    float* po  = sym<float>(&g_o);
    float* pk  = sym<float>(&g_k);
    float* pv  = sym<float>(&g_v);
    float* pbk = sym<float>(&g_bk);
    float* pbv = sym<float>(&g_bv);
    float* pck = sym<float>(&g_ck);
    float* pcv = sym<float>(&g_cv);

    __half* hidh = sym<__half>(&a_hid);
    __half* ench = sym<__half>(&a_enc);
    __half* poh  = sym<__half>(&a_po);
    __half* wqh  = sym<__half>(&w_q_h),  *wql  = sym<__half>(&w_q_l);
    __half* wkh  = sym<__half>(&w_k_h),  *wkl  = sym<__half>(&w_k_l);
    __half* wvh  = sym<__half>(&w_v_h),  *wvl  = sym<__half>(&w_v_l);
    __half* wkbh = sym<__half>(&w_kb_h), *wkbl = sym<__half>(&w_kb_l);
    __half* wvbh = sym<__half>(&w_vb_h), *wvbl = sym<__half>(&w_vb_l);
    __half* wkch = sym<__half>(&w_kc_h), *wkcl = sym<__half>(&w_kc_l);
    __half* wvch = sym<__half>(&w_vc_h), *wvcl = sym<__half>(&w_vc_l);
    __half* woh  = sym<__half>(&w_o_h),  *wol  = sym<__half>(&w_o_l);

    const long long bsEnc = (long long)LLEN * CROSSD;
    const long long encN  = (long long)B_ * LLEN * CROSSD;
    const long long hidN  = (long long)B_ * QLEN * CDIM;
    const long long boxOff = (long long)EHS_LEN * CROSSD;
    const long long clsOff = (long long)(EHS_LEN + NTOK) * CROSSD;

    cudaFuncSetAttribute(gemm_one,  cudaFuncAttributeMaxDynamicSharedMemorySize, GEMM_SMEM);
    cudaFuncSetAttribute(gemm_pack, cudaFuncAttributeMaxDynamicSharedMemorySize, GEMM_SMEM);
    cudaFuncSetAttribute(attn_pair, cudaFuncAttributeMaxDynamicSharedMemorySize, ATT_SMEM);
    cudaFuncSetAttribute(attn_fused, cudaFuncAttributeMaxDynamicSharedMemorySize, ATT_SMEM);

    // 1-2: activation conversions
    launch_cvt(hidden, hidh, hidN);
    launch_cvt(enc, ench, encN);

    // 3: w_q split
    {
        int n4 = CDIM * CDIM / 4;
        wsplit_kernel<<<(n4 + 255) / 256 > 4096 ? 4096 : (n4 + 255) / 256, 256>>>(
            (const float4*)w_q, (__half2*)wqh, (__half2*)wql, n4);
    }
    // 4: 6-way CROSSD weight split
    {
        WPack6 wp;
        wp.d[0] = { (const float4*)w_k,  (__half2*)wkh,  (__half2*)wkl  };
        wp.d[1] = { (const float4*)w_v,  (__half2*)wvh,  (__half2*)wvl  };
        wp.d[2] = { (const float4*)w_kb, (__half2*)wkbh, (__half2*)wkbl };
        wp.d[3] = { (const float4*)w_vb, (__half2*)wvbh, (__half2*)wvbl };
        wp.d[4] = { (const float4*)w_kc, (__half2*)wkch, (__half2*)wkcl };
        wp.d[5] = { (const float4*)w_vc, (__half2*)wvch, (__half2*)wvcl };
        int n4 = CDIM * CROSSD / 4;
        dim3 grid(1024, 1, 6);
        wsplit_multi<<<grid, 256>>>(wp, n4);
    }
    // 5: w_out split
    {
        int n4 = CDIM * CDIM / 4;
        wsplit_kernel<<<(n4 + 255) / 256 > 4096 ? 4096 : (n4 + 255) / 256, 256>>>(
            (const float4*)w_out, (__half2*)woh, (__half2*)wol, n4);
    }

    // 6: packed 7-way GEMM (q-proj + 6 encoder projections)
    {
        GPack p;
        const long long sEk = (long long)EHS_LEN*CDIM;
        const long long sNk = (long long)NTOK*CDIM;
        p.d[0] = { hidh,          wqh,  wql,  nullptr, pq,  B_*QLEN,    B_*QLEN, 0,     0,   CDIM, CDIM   };
        p.d[1] = { ench,          wkh,  wkl,  nullptr, pk,  B_*EHS_LEN, EHS_LEN, bsEnc, sEk, CDIM, CROSSD };
        p.d[2] = { ench,          wvh,  wvl,  nullptr, pv,  B_*EHS_LEN, EHS_LEN, bsEnc, sEk, CDIM, CROSSD };
        p.d[3] = { ench + boxOff, wkbh, wkbl, nullptr, pbk, B_*NTOK,    NTOK,    bsEnc, sNk, CDIM, CROSSD };
        p.d[4] = { ench + boxOff, wvbh, wvbl, nullptr, pbv, B_*NTOK,    NTOK,    bsEnc, sNk, CDIM, CROSSD };
        p.d[5] = { ench + clsOff, wkch, wkcl, nullptr, pck, B_*NTOK,    NTOK,    bsEnc, sNk, CDIM, CROSSD };
        p.d[6] = { ench + clsOff, wvch, wvcl, nullptr, pcv, B_*NTOK,    NTOK,    bsEnc, sNk, CDIM, CROSSD };
        int acc = 0;
        for (int i = 0; i < 7; ++i) {
            p.start[i] = acc;
            int mt = (p.d[i].Mtot + 127) / 128;
            acc += mt * 10;              // N/128 = 10 for all
        }
        p.start[7] = acc;
        gemm_pack<<<acc, 256, GEMM_SMEM>>>(p);
    }

    // 7: merged cls attention updates: bk += mea(bk,ck,cv); bv += mea(bv,ck,cv)
    {
        dim3 grid((NTOK + 127) / 128, HEADS, 2 * B_);
        attn_pair<<<grid, 256, ATT_SMEM>>>(pbk, pbv, pck, pcv);
    }

    // 8: fused main + box attention -> po
    {
        dim3 grid(QLEN / 128, HEADS, B_);
        attn_fused<<<grid, 256, ATT_SMEM>>>(pq, pk, pv, pbk, pbv, po);
    }

    // 9-10: convert po, out-projection (+bias) into d_out
    launch_cvt(po, poh, hidN);
    {
        GDesc g = { poh, woh, wol, b_out, out,
                    B_*QLEN, B_*QLEN, 0, 0, CDIM, CDIM };
        dim3 grid(CDIM / 128, (B_*QLEN + 127) / 128, 1);
        gemm_one<<<grid, 256, GEMM_SMEM>>>(g);
    }
}

// round 7
// speedup vs baseline: 6.1561x; 1.1945x over previous
#include <cuda_runtime.h>
#include <cuda_bf16.h>
#include <cuda_fp16.h>
#include <cstdint>

// Problem constants
#define B_      16
#define QLEN    1024
#define CDIM    1280
#define LLEN    477
#define CROSSD  2048
#define NTOK    200
#define HEADS   20
#define HD      64
#define EHS_LEN 77           // 477 - 200 - 200
#define ATTN_SCALE 0.125f    // 1/sqrt(64)
#define WSCALE     64.0f
#define INV_WSCALE 0.015625f

// ---------------- scratch (device globals; no runtime allocation) ----------
__device__ float g_q [B_*QLEN*CDIM];
__device__ float g_k [B_*EHS_LEN*CDIM];
__device__ float g_v [B_*EHS_LEN*CDIM];
__device__ float g_bk[B_*NTOK*CDIM];
__device__ float g_bv[B_*NTOK*CDIM];
__device__ float g_ck[B_*NTOK*CDIM];
__device__ float g_cv[B_*NTOK*CDIM];

// fp16 activations / weights
__device__ __half a_hid[B_*QLEN*CDIM];
__device__ __half a_enc[B_*LLEN*CROSSD];
__device__ __half a_po [B_*QLEN*CDIM];       // attn output, written fp16 by attn_fused
__device__ __half w_q_h [CDIM*CDIM];
__device__ __half w_k_h [CDIM*CROSSD];
__device__ __half w_v_h [CDIM*CROSSD];
__device__ __half w_kb_h[CDIM*CROSSD];
__device__ __half w_vb_h[CDIM*CROSSD];
__device__ __half w_kc_h[CDIM*CROSSD];
__device__ __half w_vc_h[CDIM*CROSSD];
__device__ __half w_o_h [CDIM*CDIM], w_o_l[CDIM*CDIM];   // out-proj: scaled hi/lo

// ---------------- helpers ---------------------------------------------------
__device__ __forceinline__ uint32_t smem_u32(const void* p) {
    uint32_t a;
    asm("{ .reg .u64 t; cvta.to.shared.u64 t, %1; cvt.u32.u64 %0, t; }"
        : "=r"(a) : "l"(p));
    return a;
}

__device__ __forceinline__ void cp_async16(uint32_t dst, const void* src, int pred) {
    int sz = pred ? 16 : 0;
    asm volatile("cp.async.cg.shared.global [%0], [%1], 16, %2;"
                 :: "r"(dst), "l"(src), "r"(sz) : "memory");
}
__device__ __forceinline__ void cp_commit() {
    asm volatile("cp.async.commit_group;" ::: "memory");
}
template <int N>
__device__ __forceinline__ void cp_wait() {
    asm volatile("cp.async.wait_group %0;" :: "n"(N) : "memory");
}

__device__ __forceinline__ void ldm4(uint32_t& r0, uint32_t& r1, uint32_t& r2,
                                     uint32_t& r3, uint32_t addr) {
    asm volatile("ldmatrix.sync.aligned.m8n8.x4.shared.b16 {%0,%1,%2,%3}, [%4];"
                 : "=r"(r0), "=r"(r1), "=r"(r2), "=r"(r3) : "r"(addr));
}

__device__ __forceinline__ void mma_h(float* c, const uint32_t* a, const uint32_t* b) {
    asm volatile(
        "mma.sync.aligned.m16n8k16.row.col.f32.f16.f16.f32 "
        "{%0,%1,%2,%3}, {%4,%5,%6,%7}, {%8,%9}, {%0,%1,%2,%3};"
        : "+f"(c[0]), "+f"(c[1]), "+f"(c[2]), "+f"(c[3])
        : "r"(a[0]), "r"(a[1]), "r"(a[2]), "r"(a[3]), "r"(b[0]), "r"(b[1]));
}

__device__ __forceinline__ void mma_bf(float* c, const uint32_t* a, const uint32_t* b) {
    asm volatile(
        "mma.sync.aligned.m16n8k16.row.col.f32.bf16.bf16.f32 "
        "{%0,%1,%2,%3}, {%4,%5,%6,%7}, {%8,%9}, {%0,%1,%2,%3};"
        : "+f"(c[0]), "+f"(c[1]), "+f"(c[2]), "+f"(c[3])
        : "r"(a[0]), "r"(a[1]), "r"(a[2]), "r"(a[3]), "r"(b[0]), "r"(b[1]));
}

__device__ __forceinline__ uint32_t pack_bf16(float a, float b) {
    uint32_t lo = (uint32_t)__bfloat16_as_ushort(__float2bfloat16_rn(a));
    uint32_t hi = (uint32_t)__bfloat16_as_ushort(__float2bfloat16_rn(b));
    return lo | (hi << 16);
}

// ---------------- conversion kernels ---------------------------------------
__global__ void cvt_half_kernel(const float4* __restrict__ x,
                                __half2* __restrict__ h, int n4)
{
    for (int i = blockIdx.x * blockDim.x + threadIdx.x; i < n4;
         i += gridDim.x * blockDim.x) {
        float4 v = x[i];
        h[2*i]   = __floats2half2_rn(v.x, v.y);
        h[2*i+1] = __floats2half2_rn(v.z, v.w);
    }
}

struct CDescM { const float4* x; __half2* h; };
struct CPack6 { CDescM d[6]; };

__global__ void cvt_multi(CPack6 p, int n4)
{
    CDescM d = p.d[blockIdx.z];
    for (int i = blockIdx.x * blockDim.x + threadIdx.x; i < n4;
         i += gridDim.x * blockDim.x) {
        float4 v = d.x[i];
        d.h[2*i]   = __floats2half2_rn(v.x, v.y);
        d.h[2*i+1] = __floats2half2_rn(v.z, v.w);
    }
}

__global__ void wsplit_kernel(const float4* __restrict__ x,
                              __half2* __restrict__ h,
                              __half2* __restrict__ l, int n4)
{
    for (int i = blockIdx.x * blockDim.x + threadIdx.x; i < n4;
         i += gridDim.x * blockDim.x) {
        float4 v = x[i];
        float sx = v.x * WSCALE, sy = v.y * WSCALE;
        float sz = v.z * WSCALE, sw = v.w * WSCALE;
        __half hx = __float2half_rn(sx), hy = __float2half_rn(sy);
        __half hz = __float2half_rn(sz), hw = __float2half_rn(sw);
        h[2*i]   = __halves2half2(hx, hy);
        h[2*i+1] = __halves2half2(hz, hw);
        l[2*i]   = __floats2half2_rn(sx - __half2float(hx), sy - __half2float(hy));
        l[2*i+1] = __floats2half2_rn(sz - __half2float(hz), sw - __half2float(hw));
    }
}

// ---------------- fp16 tensor-core GEMM (1-pass or 2-pass weights) ----------
#define KCH 32
#define GSTAGE 24576u
#define GEMM_SMEM (3u * GSTAGE)

struct GDesc {
    const __half* A;
    const __half* Wh;
    const __half* Wl;      // used only when twoPass
    const float*  bias;
    float* C;
    int Mtot, RB;
    long long sA, sC;
    int N, K;
    int twoPass;
    float oscale;
};
struct GPack {
    GDesc d[7];
    int start[8];
};

__device__ __forceinline__ void gemm_core(const GDesc& g, int m0, int n0)
{
    extern __shared__ char smem[];
    const uint32_t sm = smem_u32(smem);

    const int t    = threadIdx.x;
    const int lane = t & 31;
    const int wid  = t >> 5;
    const int wm   = wid & 1;
    const int wn   = wid >> 1;

    float acc[4][4][4];
    #pragma unroll
    for (int i = 0; i < 4; ++i)
        #pragma unroll
        for (int j = 0; j < 4; ++j)
            #pragma unroll
            for (int k = 0; k < 4; ++k) acc[i][j][k] = 0.f;

    const int NC = g.K / KCH;

    auto issue = [&](int c) {
        const int k0 = c * KCH;
        const uint32_t sbase = sm + (uint32_t)(c % 3) * GSTAGE;
        #pragma unroll
        for (int i = 0; i < 2; ++i) {
            int task = t + i * 256;
            int gr   = task >> 2;
            int kc   = task & 3;
            uint32_t sw  = (uint32_t)(kc ^ ((gr >> 1) & 3));
            uint32_t dst = sbase + (uint32_t)gr * 64u + sw * 16u;
            int grow = m0 + gr;
            int pred = grow < g.Mtot;
            long long off = 0;
            if (pred) {
                int b = grow / g.RB, r = grow % g.RB;
                off = (long long)b * g.sA + (long long)r * g.K + k0 + kc * 8;
            }
            cp_async16(dst, g.A + off, pred);
            long long boff = (long long)(n0 + gr) * g.K + k0 + kc * 8;
            cp_async16(dst + 8192u, g.Wh + boff, 1);
            if (g.twoPass)
                cp_async16(dst + 16384u, g.Wl + boff, 1);
        }
        cp_commit();
    };

    auto compute = [&](int c) {
        const uint32_t sbase = sm + (uint32_t)(c % 3) * GSTAGE;
        #pragma unroll
        for (int ks = 0; ks < 2; ++ks) {
            uint32_t af[16], bh[8], bl[8];
            #pragma unroll
            for (int mt = 0; mt < 4; ++mt) {
                int arow = wm * 64 + mt * 16 + (lane & 15);
                int ach  = ks * 2 + (lane >> 4);
                uint32_t addr = sbase + (uint32_t)arow * 64u
                              + (uint32_t)((ach ^ ((arow >> 1) & 3)) * 16);
                ldm4(af[mt*4], af[mt*4+1], af[mt*4+2], af[mt*4+3], addr);
            }
            #pragma unroll
            for (int nt2 = 0; nt2 < 2; ++nt2) {
                int brow = wn * 32 + nt2 * 16 + ((lane >> 4) & 1) * 8 + (lane & 7);
                int bch  = ks * 2 + ((lane >> 3) & 1);
                uint32_t addr = sbase + 8192u + (uint32_t)brow * 64u
                              + (uint32_t)((bch ^ ((brow >> 1) & 3)) * 16);
                ldm4(bh[nt2*4], bh[nt2*4+1], bh[nt2*4+2], bh[nt2*4+3], addr);
            }
            #pragma unroll
            for (int mt = 0; mt < 4; ++mt)
                #pragma unroll
                for (int nt = 0; nt < 4; ++nt)
                    mma_h(acc[mt][nt], &af[mt*4], &bh[(nt >> 1)*4 + (nt & 1)*2]);
            if (g.twoPass) {
                #pragma unroll
                for (int nt2 = 0; nt2 < 2; ++nt2) {
                    int brow = wn * 32 + nt2 * 16 + ((lane >> 4) & 1) * 8 + (lane & 7);
                    int bch  = ks * 2 + ((lane >> 3) & 1);
                    uint32_t addr = sbase + 16384u + (uint32_t)brow * 64u
                                  + (uint32_t)((bch ^ ((brow >> 1) & 3)) * 16);
                    ldm4(bl[nt2*4], bl[nt2*4+1], bl[nt2*4+2], bl[nt2*4+3], addr);
                }
                #pragma unroll
                for (int mt = 0; mt < 4; ++mt)
                    #pragma unroll
                    for (int nt = 0; nt < 4; ++nt)
                        mma_h(acc[mt][nt], &af[mt*4], &bl[(nt >> 1)*4 + (nt & 1)*2]);
            }
        }
    };

    issue(0);
    issue(1);
    for (int c = 0; c < NC; ++c) {
        if (c + 1 < NC) { cp_wait<1>(); } else { cp_wait<0>(); }
        __syncthreads();
        compute(c);
        if (c + 2 < NC) issue(c + 2);
    }

    const int gg = lane >> 2;
    const int q4 = lane & 3;
    #pragma unroll
    for (int mt = 0; mt < 4; ++mt) {
        #pragma unroll
        for (int half = 0; half < 2; ++half) {
            int grow = m0 + wm * 64 + mt * 16 + gg + half * 8;
            if (grow < g.Mtot) {
                int b = grow / g.RB, r = grow % g.RB;
                float* crow = g.C + (long long)b * g.sC + (long long)r * g.N
                            + n0 + wn * 32;
                #pragma unroll
                for (int nt = 0; nt < 4; ++nt) {
                    int ncol = nt * 8 + q4 * 2;
                    float2 v;
                    v.x = acc[mt][nt][half*2+0] * g.oscale;
                    v.y = acc[mt][nt][half*2+1] * g.oscale;
                    if (g.bias) {
                        v.x += g.bias[n0 + wn*32 + ncol];
                        v.y += g.bias[n0 + wn*32 + ncol + 1];
                    }
                    *(float2*)&crow[ncol] = v;
                }
            }
        }
    }
}

__global__ __launch_bounds__(256)
void gemm_one(GDesc g)
{
    gemm_core(g, blockIdx.y * 128, blockIdx.x * 128);
}

__global__ __launch_bounds__(256)
void gemm_pack(GPack p)
{
    const int bx = blockIdx.x;
    int di = 0;
    #pragma unroll
    for (int i = 0; i < 7; ++i)
        if (bx >= p.start[i] && bx < p.start[i+1]) di = i;
    const int local = bx - p.start[di];
    gemm_core(p.d[di], (local / 10) * 128, (local % 10) * 128);
}

// ---------------- Tensor-core attention (3xBF16) ----------------------------
#define ATT_SMEM (160u * 1024u)
#define AQH 0u
#define AQL 16384u
#define AKH 32768u
#define AKL 65536u
#define AVH 98304u
#define AVL 131072u

__device__ __forceinline__ void att_stage_q(char* smc, const float* Qb,
                                            int Sq, int q0, int t)
{
    #pragma unroll
    for (int i = 0; i < 8; ++i) {
        int lin = t + i * 256;
        int row = lin >> 4;
        int c4  = lin & 15;
        float4 v = make_float4(0.f, 0.f, 0.f, 0.f);
        if (q0 + row < Sq)
            v = *(const float4*)&Qb[(long long)(q0 + row) * CDIM + c4 * 4];
        __nv_bfloat16 hx = __float2bfloat16_rn(v.x), hy = __float2bfloat16_rn(v.y);
        __nv_bfloat16 hz = __float2bfloat16_rn(v.z), hw = __float2bfloat16_rn(v.w);
        uint2 hv, lv;
        hv.x = pack_bf16(__bfloat162float(hx), __bfloat162float(hy));
        hv.y = pack_bf16(__bfloat162float(hz), __bfloat162float(hw));
        lv.x = pack_bf16(v.x - __bfloat162float(hx), v.y - __bfloat162float(hy));
        lv.y = pack_bf16(v.z - __bfloat162float(hz), v.w - __bfloat162float(hw));
        int ch = c4 >> 1, halfq = c4 & 1;
        uint32_t off = (uint32_t)row * 128u + (uint32_t)((ch ^ (row & 7)) * 16)
                     + (uint32_t)halfq * 8u;
        *(uint2*)(smc + AQH + off) = hv;
        *(uint2*)(smc + AQL + off) = lv;
    }
}

__device__ __forceinline__ void att_stage_kv(char* smc, const float* Kb,
                                             const float* Vb, int Skv, int nkv, int t)
{
    for (int lin = t; lin < nkv * 16; lin += 256) {
        int row = lin >> 4;
        int c4  = lin & 15;
        float4 kv4 = make_float4(0.f, 0.f, 0.f, 0.f);
        float4 vv4 = make_float4(0.f, 0.f, 0.f, 0.f);
        if (row < Skv) {
            kv4 = *(const float4*)&Kb[(long long)row * CDIM + c4 * 4];
            vv4 = *(const float4*)&Vb[(long long)row * CDIM + c4 * 4];
        }
        {
            __nv_bfloat16 hx = __float2bfloat16_rn(kv4.x), hy = __float2bfloat16_rn(kv4.y);
            __nv_bfloat16 hz = __float2bfloat16_rn(kv4.z), hw = __float2bfloat16_rn(kv4.w);
            uint2 hv, lv;
            hv.x = pack_bf16(__bfloat162float(hx), __bfloat162float(hy));
            hv.y = pack_bf16(__bfloat162float(hz), __bfloat162float(hw));
            lv.x = pack_bf16(kv4.x - __bfloat162float(hx), kv4.y - __bfloat162float(hy));
            lv.y = pack_bf16(kv4.z - __bfloat162float(hz), kv4.w - __bfloat162float(hw));
            int ch = c4 >> 1, halfq = c4 & 1;
            uint32_t off = (uint32_t)row * 128u + (uint32_t)((ch ^ (row & 7)) * 16)
                         + (uint32_t)halfq * 8u;
            *(uint2*)(smc + AKH + off) = hv;
            *(uint2*)(smc + AKL + off) = lv;
        }
        float ve[4] = {vv4.x, vv4.y, vv4.z, vv4.w};
        #pragma unroll
        for (int j = 0; j < 4; ++j) {
            int d = c4 * 4 + j;
            __nv_bfloat16 hb = __float2bfloat16_rn(ve[j]);
            __nv_bfloat16 lb = __float2bfloat16_rn(ve[j] - __bfloat162float(hb));
            uint32_t off = (uint32_t)d * 512u
                         + (uint32_t)((((row >> 3) ^ (d & 7)) * 16))
                         + (uint32_t)(row & 7) * 2u;
            *(__nv_bfloat16*)(smc + AVH + off) = hb;
            *(__nv_bfloat16*)(smc + AVL + off) = lb;
        }
    }
}

__device__ __forceinline__ void att_phase(uint32_t sm, int Skv, int lane, int qbase,
                                          float* mrow, float* lrow, float O[8][4])
{
    const int nch = (Skv + 63) / 64;
    for (int c = 0; c < nch; ++c) {
        float S[8][4];
        #pragma unroll
        for (int nt = 0; nt < 8; ++nt)
            #pragma unroll
            for (int e = 0; e < 4; ++e) S[nt][e] = 0.f;

        #pragma unroll
        for (int ks = 0; ks < 4; ++ks) {
            uint32_t qh[4], ql[4], kh[4], kl[4];
            int arow = qbase + (lane & 15);
            int ach  = 2 * ks + (lane >> 4);
            uint32_t aoff = (uint32_t)arow * 128u + (uint32_t)((ach ^ (arow & 7)) * 16);
            ldm4(qh[0], qh[1], qh[2], qh[3], sm + AQH + aoff);
            ldm4(ql[0], ql[1], ql[2], ql[3], sm + AQL + aoff);
            #pragma unroll
            for (int nt2 = 0; nt2 < 4; ++nt2) {
                int brow = c * 64 + nt2 * 16 + ((lane >> 4) & 1) * 8 + (lane & 7);
                int bch  = 2 * ks + ((lane >> 3) & 1);
                uint32_t boff = (uint32_t)brow * 128u
                              + (uint32_t)((bch ^ (brow & 7)) * 16);
                ldm4(kh[0], kh[1], kh[2], kh[3], sm + AKH + boff);
                ldm4(kl[0], kl[1], kl[2], kl[3], sm + AKL + boff);
                #pragma unroll
                for (int sub = 0; sub < 2; ++sub) {
                    int nt = nt2 * 2 + sub;
                    mma_bf(S[nt], qh, &kh[sub*2]);
                    mma_bf(S[nt], qh, &kl[sub*2]);
                    mma_bf(S[nt], ql, &kh[sub*2]);
                }
            }
        }

        #pragma unroll
        for (int nt = 0; nt < 8; ++nt) {
            int col0 = c * 64 + nt * 8 + 2 * (lane & 3);
            #pragma unroll
            for (int e = 0; e < 4; ++e) {
                int col = col0 + (e & 1);
                float v = S[nt][e] * ATTN_SCALE;
                S[nt][e] = (col < Skv) ? v : -1e30f;
            }
        }

        float mx[2] = {-1e30f, -1e30f};
        #pragma unroll
        for (int nt = 0; nt < 8; ++nt) {
            mx[0] = fmaxf(mx[0], fmaxf(S[nt][0], S[nt][1]));
            mx[1] = fmaxf(mx[1], fmaxf(S[nt][2], S[nt][3]));
        }
        #pragma unroll
        for (int off = 1; off <= 2; off <<= 1) {
            mx[0] = fmaxf(mx[0], __shfl_xor_sync(0xffffffffu, mx[0], off));
            mx[1] = fmaxf(mx[1], __shfl_xor_sync(0xffffffffu, mx[1], off));
        }
        float mnew0 = fmaxf(mrow[0], mx[0]);
        float mnew1 = fmaxf(mrow[1], mx[1]);
        float corr0 = __expf(mrow[0] - mnew0);
        float corr1 = __expf(mrow[1] - mnew1);

        float ls[2] = {0.f, 0.f};
        #pragma unroll
        for (int nt = 0; nt < 8; ++nt) {
            S[nt][0] = __expf(S[nt][0] - mnew0); ls[0] += S[nt][0];
            S[nt][1] = __expf(S[nt][1] - mnew0); ls[0] += S[nt][1];
            S[nt][2] = __expf(S[nt][2] - mnew1); ls[1] += S[nt][2];
            S[nt][3] = __expf(S[nt][3] - mnew1); ls[1] += S[nt][3];
        }
        #pragma unroll
        for (int off = 1; off <= 2; off <<= 1) {
            ls[0] += __shfl_xor_sync(0xffffffffu, ls[0], off);
            ls[1] += __shfl_xor_sync(0xffffffffu, ls[1], off);
        }
        lrow[0] = lrow[0] * corr0 + ls[0];
        lrow[1] = lrow[1] * corr1 + ls[1];
        mrow[0] = mnew0; mrow[1] = mnew1;
        #pragma unroll
        for (int nt = 0; nt < 8; ++nt) {
            O[nt][0] *= corr0; O[nt][1] *= corr0;
            O[nt][2] *= corr1; O[nt][3] *= corr1;
        }

        #pragma unroll
        for (int ks = 0; ks < 4; ++ks) {
            uint32_t aph[4], apl[4];
            {
                int T0 = 2 * ks, T1 = 2 * ks + 1;
                float p0 = S[T0][0], p1 = S[T0][1], p2 = S[T0][2], p3 = S[T0][3];
                float r0 = S[T1][0], r1 = S[T1][1], r2 = S[T1][2], r3 = S[T1][3];
                float h0 = __bfloat162float(__float2bfloat16_rn(p0));
                float h1 = __bfloat162float(__float2bfloat16_rn(p1));
                float h2 = __bfloat162float(__float2bfloat16_rn(p2));
                float h3 = __bfloat162float(__float2bfloat16_rn(p3));
                float g0 = __bfloat162float(__float2bfloat16_rn(r0));
                float g1 = __bfloat162float(__float2bfloat16_rn(r1));
                float g2 = __bfloat162float(__float2bfloat16_rn(r2));
                float g3 = __bfloat162float(__float2bfloat16_rn(r3));
                aph[0] = pack_bf16(h0, h1); aph[1] = pack_bf16(h2, h3);
                aph[2] = pack_bf16(g0, g1); aph[3] = pack_bf16(g2, g3);
                apl[0] = pack_bf16(p0 - h0, p1 - h1);
                apl[1] = pack_bf16(p2 - h2, p3 - h3);
                apl[2] = pack_bf16(r0 - g0, r1 - g1);
                apl[3] = pack_bf16(r2 - g2, r3 - g3);
            }
            #pragma unroll
            for (int nt2 = 0; nt2 < 4; ++nt2) {
                uint32_t vh[4], vl[4];
                int vrow = nt2 * 16 + ((lane >> 4) & 1) * 8 + (lane & 7);
                int vch  = c * 8 + 2 * ks + ((lane >> 3) & 1);
                uint32_t voff = (uint32_t)vrow * 512u
                              + (uint32_t)(((vch ^ (vrow & 7))) * 16);
                ldm4(vh[0], vh[1], vh[2], vh[3], sm + AVH + voff);
                ldm4(vl[0], vl[1], vl[2], vl[3], sm + AVL + voff);
                #pragma unroll
                for (int sub = 0; sub < 2; ++sub) {
                    int nt = nt2 * 2 + sub;
                    mma_bf(O[nt], aph, &vh[sub*2]);
                    mma_bf(O[nt], aph, &vl[sub*2]);
                    mma_bf(O[nt], apl, &vh[sub*2]);
                }
            }
        }
    }
}

// attn2+attn3 merged: X += softmax(X Kc^T) Vc  for X in {bk, bv}
__global__ __launch_bounds__(256)
void attn_pair(float* __restrict__ bk, float* __restrict__ bv,
               const float* __restrict__ ck, const float* __restrict__ cv)
{
    extern __shared__ char smem[];
    char* smc = smem;
    const uint32_t sm = smem_u32(smem);

    const int t  = threadIdx.x;
    const int z  = blockIdx.z;
    const int b  = z >> 1;
    float* Xg = (z & 1) ? bv : bk;
    const int h  = blockIdx.y;
    const int q0 = blockIdx.x * 128;

    const float* Qb = Xg + ((long long)b * NTOK) * CDIM + h * HD;
    const float* Kb = ck + ((long long)b * NTOK) * CDIM + h * HD;
    const float* Vb = cv + ((long long)b * NTOK) * CDIM + h * HD;
    float*       Ob = Xg + ((long long)b * NTOK) * CDIM + h * HD;

    att_stage_q(smc, Qb, NTOK, q0, t);
    att_stage_kv(smc, Kb, Vb, NTOK, 256, t);
    __syncthreads();

    const int lane  = t & 31;
    const int wid   = t >> 5;
    const int qbase = wid * 16;

    float O[8][4];
    #pragma unroll
    for (int nt = 0; nt < 8; ++nt)
        #pragma unroll
        for (int e = 0; e < 4; ++e) O[nt][e] = 0.f;
    float mrow[2] = {-1e30f, -1e30f};
    float lrow[2] = {0.f, 0.f};

    att_phase(sm, NTOK, lane, qbase, mrow, lrow, O);

    float inv0 = 1.f / lrow[0];
    float inv1 = 1.f / lrow[1];
    #pragma unroll
    for (int halfq = 0; halfq < 2; ++halfq) {
        int row = q0 + qbase + (lane >> 2) + halfq * 8;
        if (row < NTOK) {
            float inv = halfq ? inv1 : inv0;
            float* op = Ob + (long long)row * CDIM;
            #pragma unroll
            for (int nt = 0; nt < 8; ++nt) {
                int d = nt * 8 + 2 * (lane & 3);
                float2 old = *(float2*)&op[d];
                float2 v;
                v.x = old.x + O[nt][halfq*2+0] * inv;
                v.y = old.y + O[nt][halfq*2+1] * inv;
                *(float2*)&op[d] = v;
            }
        }
    }
}

// fused main attention: writes fp16 (softmax(QK^T)V + softmax(Q bK^T) bV)
__global__ __launch_bounds__(256)
void attn_fused(const float* __restrict__ Qg, const float* __restrict__ Kg,
                const float* __restrict__ Vg, const float* __restrict__ bKg,
                const float* __restrict__ bVg, __half* __restrict__ Og)
{
    extern __shared__ char smem[];
    char* smc = smem;
    const uint32_t sm = smem_u32(smem);

    const int t  = threadIdx.x;
    const int b  = blockIdx.z;
    const int h  = blockIdx.y;
    const int q0 = blockIdx.x * 128;

    const float* Qb  = Qg  + ((long long)b * QLEN)    * CDIM + h * HD;
    const float* Kb  = Kg  + ((long long)b * EHS_LEN) * CDIM + h * HD;
    const float* Vb  = Vg  + ((long long)b * EHS_LEN) * CDIM + h * HD;
    const float* bKb = bKg + ((long long)b * NTOK)    * CDIM + h * HD;
    const float* bVb = bVg + ((long long)b * NTOK)    * CDIM + h * HD;
    __half*      Ob  = Og  + ((long long)b * QLEN)    * CDIM + h * HD;

    att_stage_q(smc, Qb, QLEN, q0, t);
    att_stage_kv(smc, Kb, Vb, EHS_LEN, 128, t);
    __syncthreads();

    const int lane  = t & 31;
    const int wid   = t >> 5;
    const int qbase = wid * 16;

    float O[8][4];
    float mrow[2], lrow[2];
    #pragma unroll
    for (int nt = 0; nt < 8; ++nt)
        #pragma unroll
        for (int e = 0; e < 4; ++e) O[nt][e] = 0.f;
    mrow[0] = mrow[1] = -1e30f;
    lrow[0] = lrow[1] = 0.f;

    att_phase(sm, EHS_LEN, lane, qbase, mrow, lrow, O);

    float Oacc[8][4];
    {
        float inv0 = 1.f / lrow[0];
        float inv1 = 1.f / lrow[1];
        #pragma unroll
        for (int nt = 0; nt < 8; ++nt) {
            Oacc[nt][0] = O[nt][0] * inv0;
            Oacc[nt][1] = O[nt][1] * inv0;
            Oacc[nt][2] = O[nt][2] * inv1;
            Oacc[nt][3] = O[nt][3] * inv1;
            O[nt][0] = O[nt][1] = O[nt][2] = O[nt][3] = 0.f;
        }
        mrow[0] = mrow[1] = -1e30f;
        lrow[0] = lrow[1] = 0.f;
    }

    __syncthreads();
    att_stage_kv(smc, bKb, bVb, NTOK, 256, t);
    __syncthreads();
    att_phase(sm, NTOK, lane, qbase, mrow, lrow, O);

    float inv0 = 1.f / lrow[0];
    float inv1 = 1.f / lrow[1];
    #pragma unroll
    for (int halfq = 0; halfq < 2; ++halfq) {
        int row = q0 + qbase + (lane >> 2) + halfq * 8;
        if (row < QLEN) {
            float inv = halfq ? inv1 : inv0;
            __half* op = Ob + (long long)row * CDIM;
            #pragma unroll
            for (int nt = 0; nt < 8; ++nt) {
                int d = nt * 8 + 2 * (lane & 3);
                float vx = Oacc[nt][halfq*2+0] + O[nt][halfq*2+0] * inv;
                float vy = Oacc[nt][halfq*2+1] + O[nt][halfq*2+1] * inv;
                *(__half2*)&op[d] = __floats2half2_rn(vx, vy);
            }
        }
    }
}

// ---------------- host orchestration ---------------------------------------
static inline void launch_cvt(const float* x, __half* h, long long n)
{
    int n4 = (int)(n / 4);
    int blocks = (n4 + 255) / 256;
    if (blocks > 4096) blocks = 4096;
    cvt_half_kernel<<<blocks, 256>>>((const float4*)x, (__half2*)h, n4);
}

template <typename T>
static inline T* sym(const void* s) { void* p; cudaGetSymbolAddress(&p, s); return (T*)p; }

extern "C" void kernel_launch(void* const* d_in, const int* in_sizes, int n_in,
                              void* d_out, int out_size)
{
    const float* hidden = (const float*)d_in[0];
    const float* enc    = (const float*)d_in[1];
    const float* w_q    = (const float*)d_in[2];
    const float* w_k    = (const float*)d_in[3];
    const float* w_v    = (const float*)d_in[4];
    const float* w_kb   = (const float*)d_in[5];
    const float* w_vb   = (const float*)d_in[6];
    const float* w_kc   = (const float*)d_in[7];
    const float* w_vc   = (const float*)d_in[8];
    const float* w_out  = (const float*)d_in[9];
    const float* b_out  = (const float*)d_in[10];
    float* out = (float*)d_out;

    float* pq  = sym<float>(&g_q);
    float* pk  = sym<float>(&g_k);
    float* pv  = sym<float>(&g_v);
    float* pbk = sym<float>(&g_bk);
    float* pbv = sym<float>(&g_bv);
    float* pck = sym<float>(&g_ck);
    float* pcv = sym<float>(&g_cv);

    __half* hidh = sym<__half>(&a_hid);
    __half* ench = sym<__half>(&a_enc);
    __half* poh  = sym<__half>(&a_po);
    __half* wqh  = sym<__half>(&w_q_h);
    __half* wkh  = sym<__half>(&w_k_h);
    __half* wvh  = sym<__half>(&w_v_h);
    __half* wkbh = sym<__half>(&w_kb_h);
    __half* wvbh = sym<__half>(&w_vb_h);
    __half* wkch = sym<__half>(&w_kc_h);
    __half* wvch = sym<__half>(&w_vc_h);
    __half* woh  = sym<__half>(&w_o_h), *wol = sym<__half>(&w_o_l);

    const long long bsEnc = (long long)LLEN * CROSSD;
    const long long encN  = (long long)B_ * LLEN * CROSSD;
    const long long hidN  = (long long)B_ * QLEN * CDIM;
    const long long boxOff = (long long)EHS_LEN * CROSSD;
    const long long clsOff = (long long)(EHS_LEN + NTOK) * CROSSD;

    cudaFuncSetAttribute(gemm_one,  cudaFuncAttributeMaxDynamicSharedMemorySize, GEMM_SMEM);
    cudaFuncSetAttribute(gemm_pack, cudaFuncAttributeMaxDynamicSharedMemorySize, GEMM_SMEM);
    cudaFuncSetAttribute(attn_pair, cudaFuncAttributeMaxDynamicSharedMemorySize, ATT_SMEM);
    cudaFuncSetAttribute(attn_fused, cudaFuncAttributeMaxDynamicSharedMemorySize, ATT_SMEM);

    // 1-2: activation conversions
    launch_cvt(hidden, hidh, hidN);
    launch_cvt(enc, ench, encN);

    // 3: w_q -> fp16
    launch_cvt(w_q, wqh, (long long)CDIM*CDIM);

    // 4: 6 encoder weights -> fp16 (single pass, no split)
    {
        CPack6 cp;
        cp.d[0] = { (const float4*)w_k,  (__half2*)wkh  };
        cp.d[1] = { (const float4*)w_v,  (__half2*)wvh  };
        cp.d[2] = { (const float4*)w_kb, (__half2*)wkbh };
        cp.d[3] = { (const float4*)w_vb, (__half2*)wvbh };
        cp.d[4] = { (const float4*)w_kc, (__half2*)wkch };
        cp.d[5] = { (const float4*)w_vc, (__half2*)wvch };
        dim3 grid(1024, 1, 6);
        cvt_multi<<<grid, 256>>>(cp, CDIM * CROSSD / 4);
    }

    // 5: w_out -> scaled hi/lo split (out-proj stays 2-pass)
    {
        int n4 = CDIM * CDIM / 4;
        wsplit_kernel<<<(n4 + 255) / 256, 256>>>(
            (const float4*)w_out, (__half2*)woh, (__half2*)wol, n4);
    }

    // 6: packed 7-way GEMM (1-pass fp16)  [profiled by ncu -s 5 -c 1]
    {
        GPack p;
        const long long sEk = (long long)EHS_LEN*CDIM;
        const long long sNk = (long long)NTOK*CDIM;
        p.d[0] = { hidh,          wqh,  nullptr, nullptr, pq,  B_*QLEN,    B_*QLEN, 0,     0,   CDIM, CDIM,   0, 1.f };
        p.d[1] = { ench,          wkh,  nullptr, nullptr, pk,  B_*EHS_LEN, EHS_LEN, bsEnc, sEk, CDIM, CROSSD, 0, 1.f };
        p.d[2] = { ench,          wvh,  nullptr, nullptr, pv,  B_*EHS_LEN, EHS_LEN, bsEnc, sEk, CDIM, CROSSD, 0, 1.f };
        p.d[3] = { ench + boxOff, wkbh, nullptr, nullptr, pbk, B_*NTOK,    NTOK,    bsEnc, sNk, CDIM, CROSSD, 0, 1.f };
        p.d[4] = { ench + boxOff, wvbh, nullptr, nullptr, pbv, B_*NTOK,    NTOK,    bsEnc, sNk, CDIM, CROSSD, 0, 1.f };
        p.d[5] = { ench + clsOff, wkch, nullptr, nullptr, pck, B_*NTOK,    NTOK,    bsEnc, sNk, CDIM, CROSSD, 0, 1.f };
        p.d[6] = { ench + clsOff, wvch, nullptr, nullptr, pcv, B_*NTOK,    NTOK,    bsEnc, sNk, CDIM, CROSSD, 0, 1.f };
        int acc = 0;
        for (int i = 0; i < 7; ++i) {
            p.start[i] = acc;
            int mt = (p.d[i].Mtot + 127) / 128;
            acc += mt * 10;
        }
        p.start[7] = acc;
        gemm_pack<<<acc, 256, GEMM_SMEM>>>(p);
    }

    // 7: merged cls attention updates
    {
        dim3 grid((NTOK + 127) / 128, HEADS, 2 * B_);
        attn_pair<<<grid, 256, ATT_SMEM>>>(pbk, pbv, pck, pcv);
    }

    // 8: fused main + box attention -> fp16 a_po
    {
        dim3 grid(QLEN / 128, HEADS, B_);
        attn_fused<<<grid, 256, ATT_SMEM>>>(pq, pk, pv, pbk, pbv, poh);
    }

    // 9: out-projection (2-pass, +bias) into d_out
    {
        GDesc g = { poh, woh, wol, b_out, out,
                    B_*QLEN, B_*QLEN, 0, 0, CDIM, CDIM, 1, INV_WSCALE };
        dim3 grid(CDIM / 128, (B_*QLEN + 127) / 128, 1);
        gemm_one<<<grid, 256, GEMM_SMEM>>>(g);
    }
}

// round 8
// speedup vs baseline: 6.2896x; 1.0217x over previous
#include <cuda_runtime.h>
#include <cuda_bf16.h>
#include <cuda_fp16.h>
#include <cstdint>

// Problem constants
#define B_      16
#define QLEN    1024
#define CDIM    1280
#define LLEN    477
#define CROSSD  2048
#define NTOK    200
#define HEADS   20
#define HD      64
#define EHS_LEN 77           // 477 - 200 - 200
#define ATTN_SCALE 0.125f    // 1/sqrt(64)

// ---------------- scratch (device globals; no runtime allocation) ----------
__device__ float g_q [B_*QLEN*CDIM];
__device__ float g_k [B_*EHS_LEN*CDIM];
__device__ float g_v [B_*EHS_LEN*CDIM];
__device__ float g_bk[B_*NTOK*CDIM];
__device__ float g_bv[B_*NTOK*CDIM];
__device__ float g_ck[B_*NTOK*CDIM];
__device__ float g_cv[B_*NTOK*CDIM];

// fp16 activations / weights
__device__ __half a_hid[B_*QLEN*CDIM];
__device__ __half a_enc[B_*LLEN*CROSSD];
__device__ __half a_po [B_*QLEN*CDIM];
__device__ __half w_q_h [CDIM*CDIM];
__device__ __half w_k_h [CDIM*CROSSD];
__device__ __half w_v_h [CDIM*CROSSD];
__device__ __half w_kb_h[CDIM*CROSSD];
__device__ __half w_vb_h[CDIM*CROSSD];
__device__ __half w_kc_h[CDIM*CROSSD];
__device__ __half w_vc_h[CDIM*CROSSD];
__device__ __half w_o_h [CDIM*CDIM];

// ---------------- helpers ---------------------------------------------------
__device__ __forceinline__ uint32_t smem_u32(const void* p) {
    uint32_t a;
    asm("{ .reg .u64 t; cvta.to.shared.u64 t, %1; cvt.u32.u64 %0, t; }"
        : "=r"(a) : "l"(p));
    return a;
}

__device__ __forceinline__ void cp_async16(uint32_t dst, const void* src, int pred) {
    int sz = pred ? 16 : 0;
    asm volatile("cp.async.cg.shared.global [%0], [%1], 16, %2;"
                 :: "r"(dst), "l"(src), "r"(sz) : "memory");
}
__device__ __forceinline__ void cp_commit() {
    asm volatile("cp.async.commit_group;" ::: "memory");
}
template <int N>
__device__ __forceinline__ void cp_wait() {
    asm volatile("cp.async.wait_group %0;" :: "n"(N) : "memory");
}

__device__ __forceinline__ void ldm4(uint32_t& r0, uint32_t& r1, uint32_t& r2,
                                     uint32_t& r3, uint32_t addr) {
    asm volatile("ldmatrix.sync.aligned.m8n8.x4.shared.b16 {%0,%1,%2,%3}, [%4];"
                 : "=r"(r0), "=r"(r1), "=r"(r2), "=r"(r3) : "r"(addr));
}

__device__ __forceinline__ void mma_h(float* c, const uint32_t* a, const uint32_t* b) {
    asm volatile(
        "mma.sync.aligned.m16n8k16.row.col.f32.f16.f16.f32 "
        "{%0,%1,%2,%3}, {%4,%5,%6,%7}, {%8,%9}, {%0,%1,%2,%3};"
        : "+f"(c[0]), "+f"(c[1]), "+f"(c[2]), "+f"(c[3])
        : "r"(a[0]), "r"(a[1]), "r"(a[2]), "r"(a[3]), "r"(b[0]), "r"(b[1]));
}

__device__ __forceinline__ void mma_bf(float* c, const uint32_t* a, const uint32_t* b) {
    asm volatile(
        "mma.sync.aligned.m16n8k16.row.col.f32.bf16.bf16.f32 "
        "{%0,%1,%2,%3}, {%4,%5,%6,%7}, {%8,%9}, {%0,%1,%2,%3};"
        : "+f"(c[0]), "+f"(c[1]), "+f"(c[2]), "+f"(c[3])
        : "r"(a[0]), "r"(a[1]), "r"(a[2]), "r"(a[3]), "r"(b[0]), "r"(b[1]));
}

__device__ __forceinline__ uint32_t pack_bf16(float a, float b) {
    uint32_t lo = (uint32_t)__bfloat16_as_ushort(__float2bfloat16_rn(a));
    uint32_t hi = (uint32_t)__bfloat16_as_ushort(__float2bfloat16_rn(b));
    return lo | (hi << 16);
}

// ---------------- conversion kernels ---------------------------------------
__global__ void cvt_half_kernel(const float4* __restrict__ x,
                                __half2* __restrict__ h, int n4)
{
    for (int i = blockIdx.x * blockDim.x + threadIdx.x; i < n4;
         i += gridDim.x * blockDim.x) {
        float4 v = x[i];
        h[2*i]   = __floats2half2_rn(v.x, v.y);
        h[2*i+1] = __floats2half2_rn(v.z, v.w);
    }
}

struct CDescM { const float4* x; __half2* h; };
struct CPack6 { CDescM d[6]; };

__global__ void cvt_multi(CPack6 p, int n4)
{
    CDescM d = p.d[blockIdx.z];
    for (int i = blockIdx.x * blockDim.x + threadIdx.x; i < n4;
         i += gridDim.x * blockDim.x) {
        float4 v = d.x[i];
        d.h[2*i]   = __floats2half2_rn(v.x, v.y);
        d.h[2*i+1] = __floats2half2_rn(v.z, v.w);
    }
}

// ---------------- fp16 tensor-core GEMM, 128x256 tiles ----------------------
// Per-stage smem: A (8KB) | W0 (8KB) | W1 (8KB). 3 stages = 72KB.
#define KCH 32
#define GSTAGE 24576u
#define GEMM_SMEM (3u * GSTAGE)

struct GDesc {
    const __half* A;
    const __half* W;
    const float*  bias;
    float* C;
    int Mtot, RB;
    long long sA, sC;
    int N, K;
};
struct GPack {
    GDesc d[7];
    int start[8];
};

__device__ __forceinline__ void gemm_core(const GDesc& g, int m0, int n0)
{
    extern __shared__ char smem[];
    const uint32_t sm = smem_u32(smem);

    const int t    = threadIdx.x;
    const int lane = t & 31;
    const int wid  = t >> 5;
    const int wm   = wid & 1;
    const int wn   = wid >> 1;

    float acc[2][4][4][4];
    #pragma unroll
    for (int w = 0; w < 2; ++w)
        #pragma unroll
        for (int i = 0; i < 4; ++i)
            #pragma unroll
            for (int j = 0; j < 4; ++j)
                #pragma unroll
                for (int k = 0; k < 4; ++k) acc[w][i][j][k] = 0.f;

    const int NC = g.K / KCH;

    auto issue = [&](int c) {
        const int k0 = c * KCH;
        const uint32_t sbase = sm + (uint32_t)(c % 3) * GSTAGE;
        #pragma unroll
        for (int i = 0; i < 2; ++i) {
            int task = t + i * 256;
            int gr   = task >> 2;
            int kc   = task & 3;
            uint32_t sw  = (uint32_t)(kc ^ ((gr >> 1) & 3));
            uint32_t dst = sbase + (uint32_t)gr * 64u + sw * 16u;
            int grow = m0 + gr;
            int pred = grow < g.Mtot;
            long long off = 0;
            if (pred) {
                int b = grow / g.RB, r = grow % g.RB;
                off = (long long)b * g.sA + (long long)r * g.K + k0 + kc * 8;
            }
            cp_async16(dst, g.A + off, pred);
            long long boff0 = (long long)(n0 + gr) * g.K + k0 + kc * 8;
            long long boff1 = (long long)(n0 + 128 + gr) * g.K + k0 + kc * 8;
            cp_async16(dst + 8192u,  g.W + boff0, 1);
            cp_async16(dst + 16384u, g.W + boff1, 1);
        }
        cp_commit();
    };

    auto compute = [&](int c) {
        const uint32_t sbase = sm + (uint32_t)(c % 3) * GSTAGE;
        #pragma unroll
        for (int ks = 0; ks < 2; ++ks) {
            uint32_t af[16];
            #pragma unroll
            for (int mt = 0; mt < 4; ++mt) {
                int arow = wm * 64 + mt * 16 + (lane & 15);
                int ach  = ks * 2 + (lane >> 4);
                uint32_t addr = sbase + (uint32_t)arow * 64u
                              + (uint32_t)((ach ^ ((arow >> 1) & 3)) * 16);
                ldm4(af[mt*4], af[mt*4+1], af[mt*4+2], af[mt*4+3], addr);
            }
            #pragma unroll
            for (int w = 0; w < 2; ++w) {
                uint32_t bh[8];
                #pragma unroll
                for (int nt2 = 0; nt2 < 2; ++nt2) {
                    int brow = wn * 32 + nt2 * 16 + ((lane >> 4) & 1) * 8 + (lane & 7);
                    int bch  = ks * 2 + ((lane >> 3) & 1);
                    uint32_t addr = sbase + 8192u + (uint32_t)w * 8192u
                                  + (uint32_t)brow * 64u
                                  + (uint32_t)((bch ^ ((brow >> 1) & 3)) * 16);
                    ldm4(bh[nt2*4], bh[nt2*4+1], bh[nt2*4+2], bh[nt2*4+3], addr);
                }
                #pragma unroll
                for (int mt = 0; mt < 4; ++mt)
                    #pragma unroll
                    for (int nt = 0; nt < 4; ++nt)
                        mma_h(acc[w][mt][nt], &af[mt*4], &bh[(nt >> 1)*4 + (nt & 1)*2]);
            }
        }
    };

    issue(0);
    issue(1);
    for (int c = 0; c < NC; ++c) {
        if (c + 1 < NC) { cp_wait<1>(); } else { cp_wait<0>(); }
        __syncthreads();
        compute(c);
        if (c + 2 < NC) issue(c + 2);
    }

    const int gg = lane >> 2;
    const int q4 = lane & 3;
    #pragma unroll
    for (int w = 0; w < 2; ++w) {
        int nbase = n0 + w * 128 + wn * 32;
        #pragma unroll
        for (int mt = 0; mt < 4; ++mt) {
            #pragma unroll
            for (int half = 0; half < 2; ++half) {
                int grow = m0 + wm * 64 + mt * 16 + gg + half * 8;
                if (grow < g.Mtot) {
                    int b = grow / g.RB, r = grow % g.RB;
                    float* crow = g.C + (long long)b * g.sC + (long long)r * g.N + nbase;
                    #pragma unroll
                    for (int nt = 0; nt < 4; ++nt) {
                        int ncol = nt * 8 + q4 * 2;
                        float2 v;
                        v.x = acc[w][mt][nt][half*2+0];
                        v.y = acc[w][mt][nt][half*2+1];
                        if (g.bias) {
                            v.x += g.bias[nbase + ncol];
                            v.y += g.bias[nbase + ncol + 1];
                        }
                        *(float2*)&crow[ncol] = v;
                    }
                }
            }
        }
    }
}

__global__ __launch_bounds__(256)
void gemm_one(GDesc g)
{
    gemm_core(g, blockIdx.y * 128, blockIdx.x * 256);
}

__global__ __launch_bounds__(256)
void gemm_pack(GPack p)
{
    const int bx = blockIdx.x;
    int di = 0;
    #pragma unroll
    for (int i = 0; i < 7; ++i)
        if (bx >= p.start[i] && bx < p.start[i+1]) di = i;
    const int local = bx - p.start[di];
    gemm_core(p.d[di], (local / 5) * 128, (local % 5) * 256);
}

// ---------------- Tensor-core attention (3xBF16) ----------------------------
#define ATT_SMEM (160u * 1024u)
#define AQH 0u
#define AQL 16384u
#define AKH 32768u
#define AKL 65536u
#define AVH 98304u
#define AVL 131072u

__device__ __forceinline__ void att_stage_q(char* smc, const float* Qb,
                                            int Sq, int q0, int t)
{
    #pragma unroll
    for (int i = 0; i < 8; ++i) {
        int lin = t + i * 256;
        int row = lin >> 4;
        int c4  = lin & 15;
        float4 v = make_float4(0.f, 0.f, 0.f, 0.f);
        if (q0 + row < Sq)
            v = *(const float4*)&Qb[(long long)(q0 + row) * CDIM + c4 * 4];
        __nv_bfloat16 hx = __float2bfloat16_rn(v.x), hy = __float2bfloat16_rn(v.y);
        __nv_bfloat16 hz = __float2bfloat16_rn(v.z), hw = __float2bfloat16_rn(v.w);
        uint2 hv, lv;
        hv.x = pack_bf16(__bfloat162float(hx), __bfloat162float(hy));
        hv.y = pack_bf16(__bfloat162float(hz), __bfloat162float(hw));
        lv.x = pack_bf16(v.x - __bfloat162float(hx), v.y - __bfloat162float(hy));
        lv.y = pack_bf16(v.z - __bfloat162float(hz), v.w - __bfloat162float(hw));
        int ch = c4 >> 1, halfq = c4 & 1;
        uint32_t off = (uint32_t)row * 128u + (uint32_t)((ch ^ (row & 7)) * 16)
                     + (uint32_t)halfq * 8u;
        *(uint2*)(smc + AQH + off) = hv;
        *(uint2*)(smc + AQL + off) = lv;
    }
}

__device__ __forceinline__ void att_stage_kv(char* smc, const float* Kb,
                                             const float* Vb, int Skv, int nkv, int t)
{
    for (int lin = t; lin < nkv * 16; lin += 256) {
        int row = lin >> 4;
        int c4  = lin & 15;
        float4 kv4 = make_float4(0.f, 0.f, 0.f, 0.f);
        float4 vv4 = make_float4(0.f, 0.f, 0.f, 0.f);
        if (row < Skv) {
            kv4 = *(const float4*)&Kb[(long long)row * CDIM + c4 * 4];
            vv4 = *(const float4*)&Vb[(long long)row * CDIM + c4 * 4];
        }
        {
            __nv_bfloat16 hx = __float2bfloat16_rn(kv4.x), hy = __float2bfloat16_rn(kv4.y);
            __nv_bfloat16 hz = __float2bfloat16_rn(kv4.z), hw = __float2bfloat16_rn(kv4.w);
            uint2 hv, lv;
            hv.x = pack_bf16(__bfloat162float(hx), __bfloat162float(hy));
            hv.y = pack_bf16(__bfloat162float(hz), __bfloat162float(hw));
            lv.x = pack_bf16(kv4.x - __bfloat162float(hx), kv4.y - __bfloat162float(hy));
            lv.y = pack_bf16(kv4.z - __bfloat162float(hz), kv4.w - __bfloat162float(hw));
            int ch = c4 >> 1, halfq = c4 & 1;
            uint32_t off = (uint32_t)row * 128u + (uint32_t)((ch ^ (row & 7)) * 16)
                         + (uint32_t)halfq * 8u;
            *(uint2*)(smc + AKH + off) = hv;
            *(uint2*)(smc + AKL + off) = lv;
        }
        float ve[4] = {vv4.x, vv4.y, vv4.z, vv4.w};
        #pragma unroll
        for (int j = 0; j < 4; ++j) {
            int d = c4 * 4 + j;
            __nv_bfloat16 hb = __float2bfloat16_rn(ve[j]);
            __nv_bfloat16 lb = __float2bfloat16_rn(ve[j] - __bfloat162float(hb));
            uint32_t off = (uint32_t)d * 512u
                         + (uint32_t)((((row >> 3) ^ (d & 7)) * 16))
                         + (uint32_t)(row & 7) * 2u;
            *(__nv_bfloat16*)(smc + AVH + off) = hb;
            *(__nv_bfloat16*)(smc + AVL + off) = lb;
        }
    }
}

__device__ __forceinline__ void att_phase(uint32_t sm, int Skv, int lane, int qbase,
                                          float* mrow, float* lrow, float O[8][4])
{
    const int nch = (Skv + 63) / 64;
    for (int c = 0; c < nch; ++c) {
        float S[8][4];
        #pragma unroll
        for (int nt = 0; nt < 8; ++nt)
            #pragma unroll
            for (int e = 0; e < 4; ++e) S[nt][e] = 0.f;

        #pragma unroll
        for (int ks = 0; ks < 4; ++ks) {
            uint32_t qh[4], ql[4], kh[4], kl[4];
            int arow = qbase + (lane & 15);
            int ach  = 2 * ks + (lane >> 4);
            uint32_t aoff = (uint32_t)arow * 128u + (uint32_t)((ach ^ (arow & 7)) * 16);
            ldm4(qh[0], qh[1], qh[2], qh[3], sm + AQH + aoff);
            ldm4(ql[0], ql[1], ql[2], ql[3], sm + AQL + aoff);
            #pragma unroll
            for (int nt2 = 0; nt2 < 4; ++nt2) {
                int brow = c * 64 + nt2 * 16 + ((lane >> 4) & 1) * 8 + (lane & 7);
                int bch  = 2 * ks + ((lane >> 3) & 1);
                uint32_t boff = (uint32_t)brow * 128u
                              + (uint32_t)((bch ^ (brow & 7)) * 16);
                ldm4(kh[0], kh[1], kh[2], kh[3], sm + AKH + boff);
                ldm4(kl[0], kl[1], kl[2], kl[3], sm + AKL + boff);
                #pragma unroll
                for (int sub = 0; sub < 2; ++sub) {
                    int nt = nt2 * 2 + sub;
                    mma_bf(S[nt], qh, &kh[sub*2]);
                    mma_bf(S[nt], qh, &kl[sub*2]);
                    mma_bf(S[nt], ql, &kh[sub*2]);
                }
            }
        }

        #pragma unroll
        for (int nt = 0; nt < 8; ++nt) {
            int col0 = c * 64 + nt * 8 + 2 * (lane & 3);
            #pragma unroll
            for (int e = 0; e < 4; ++e) {
                int col = col0 + (e & 1);
                float v = S[nt][e] * ATTN_SCALE;
                S[nt][e] = (col < Skv) ? v : -1e30f;
            }
        }

        float mx[2] = {-1e30f, -1e30f};
        #pragma unroll
        for (int nt = 0; nt < 8; ++nt) {
            mx[0] = fmaxf(mx[0], fmaxf(S[nt][0], S[nt][1]));
            mx[1] = fmaxf(mx[1], fmaxf(S[nt][2], S[nt][3]));
        }
        #pragma unroll
        for (int off = 1; off <= 2; off <<= 1) {
            mx[0] = fmaxf(mx[0], __shfl_xor_sync(0xffffffffu, mx[0], off));
            mx[1] = fmaxf(mx[1], __shfl_xor_sync(0xffffffffu, mx[1], off));
        }
        float mnew0 = fmaxf(mrow[0], mx[0]);
        float mnew1 = fmaxf(mrow[1], mx[1]);
        float corr0 = __expf(mrow[0] - mnew0);
        float corr1 = __expf(mrow[1] - mnew1);

        float ls[2] = {0.f, 0.f};
        #pragma unroll
        for (int nt = 0; nt < 8; ++nt) {
            S[nt][0] = __expf(S[nt][0] - mnew0); ls[0] += S[nt][0];
            S[nt][1] = __expf(S[nt][1] - mnew0); ls[0] += S[nt][1];
            S[nt][2] = __expf(S[nt][2] - mnew1); ls[1] += S[nt][2];
            S[nt][3] = __expf(S[nt][3] - mnew1); ls[1] += S[nt][3];
        }
        #pragma unroll
        for (int off = 1; off <= 2; off <<= 1) {
            ls[0] += __shfl_xor_sync(0xffffffffu, ls[0], off);
            ls[1] += __shfl_xor_sync(0xffffffffu, ls[1], off);
        }
        lrow[0] = lrow[0] * corr0 + ls[0];
        lrow[1] = lrow[1] * corr1 + ls[1];
        mrow[0] = mnew0; mrow[1] = mnew1;
        #pragma unroll
        for (int nt = 0; nt < 8; ++nt) {
            O[nt][0] *= corr0; O[nt][1] *= corr0;
            O[nt][2] *= corr1; O[nt][3] *= corr1;
        }

        #pragma unroll
        for (int ks = 0; ks < 4; ++ks) {
            uint32_t aph[4], apl[4];
            {
                int T0 = 2 * ks, T1 = 2 * ks + 1;
                float p0 = S[T0][0], p1 = S[T0][1], p2 = S[T0][2], p3 = S[T0][3];
                float r0 = S[T1][0], r1 = S[T1][1], r2 = S[T1][2], r3 = S[T1][3];
                float h0 = __bfloat162float(__float2bfloat16_rn(p0));
                float h1 = __bfloat162float(__float2bfloat16_rn(p1));
                float h2 = __bfloat162float(__float2bfloat16_rn(p2));
                float h3 = __bfloat162float(__float2bfloat16_rn(p3));
                float g0 = __bfloat162float(__float2bfloat16_rn(r0));
                float g1 = __bfloat162float(__float2bfloat16_rn(r1));
                float g2 = __bfloat162float(__float2bfloat16_rn(r2));
                float g3 = __bfloat162float(__float2bfloat16_rn(r3));
                aph[0] = pack_bf16(h0, h1); aph[1] = pack_bf16(h2, h3);
                aph[2] = pack_bf16(g0, g1); aph[3] = pack_bf16(g2, g3);
                apl[0] = pack_bf16(p0 - h0, p1 - h1);
                apl[1] = pack_bf16(p2 - h2, p3 - h3);
                apl[2] = pack_bf16(r0 - g0, r1 - g1);
                apl[3] = pack_bf16(r2 - g2, r3 - g3);
            }
            #pragma unroll
            for (int nt2 = 0; nt2 < 4; ++nt2) {
                uint32_t vh[4], vl[4];
                int vrow = nt2 * 16 + ((lane >> 4) & 1) * 8 + (lane & 7);
                int vch  = c * 8 + 2 * ks + ((lane >> 3) & 1);
                uint32_t voff = (uint32_t)vrow * 512u
                              + (uint32_t)(((vch ^ (vrow & 7))) * 16);
                ldm4(vh[0], vh[1], vh[2], vh[3], sm + AVH + voff);
                ldm4(vl[0], vl[1], vl[2], vl[3], sm + AVL + voff);
                #pragma unroll
                for (int sub = 0; sub < 2; ++sub) {
                    int nt = nt2 * 2 + sub;
                    mma_bf(O[nt], aph, &vh[sub*2]);
                    mma_bf(O[nt], aph, &vl[sub*2]);
                    mma_bf(O[nt], apl, &vh[sub*2]);
                }
            }
        }
    }
}

// attn2+attn3 merged: X += softmax(X Kc^T) Vc  for X in {bk, bv}
__global__ __launch_bounds__(256)
void attn_pair(float* __restrict__ bk, float* __restrict__ bv,
               const float* __restrict__ ck, const float* __restrict__ cv)
{
    extern __shared__ char smem[];
    char* smc = smem;
    const uint32_t sm = smem_u32(smem);

    const int t  = threadIdx.x;
    const int z  = blockIdx.z;
    const int b  = z >> 1;
    float* Xg = (z & 1) ? bv : bk;
    const int h  = blockIdx.y;
    const int q0 = blockIdx.x * 128;

    const float* Qb = Xg + ((long long)b * NTOK) * CDIM + h * HD;
    const float* Kb = ck + ((long long)b * NTOK) * CDIM + h * HD;
    const float* Vb = cv + ((long long)b * NTOK) * CDIM + h * HD;
    float*       Ob = Xg + ((long long)b * NTOK) * CDIM + h * HD;

    att_stage_q(smc, Qb, NTOK, q0, t);
    att_stage_kv(smc, Kb, Vb, NTOK, 256, t);
    __syncthreads();

    const int lane  = t & 31;
    const int wid   = t >> 5;
    const int qbase = wid * 16;

    float O[8][4];
    #pragma unroll
    for (int nt = 0; nt < 8; ++nt)
        #pragma unroll
        for (int e = 0; e < 4; ++e) O[nt][e] = 0.f;
    float mrow[2] = {-1e30f, -1e30f};
    float lrow[2] = {0.f, 0.f};

    att_phase(sm, NTOK, lane, qbase, mrow, lrow, O);

    float inv0 = 1.f / lrow[0];
    float inv1 = 1.f / lrow[1];
    #pragma unroll
    for (int halfq = 0; halfq < 2; ++halfq) {
        int row = q0 + qbase + (lane >> 2) + halfq * 8;
        if (row < NTOK) {
            float inv = halfq ? inv1 : inv0;
            float* op = Ob + (long long)row * CDIM;
            #pragma unroll
            for (int nt = 0; nt < 8; ++nt) {
                int d = nt * 8 + 2 * (lane & 3);
                float2 old = *(float2*)&op[d];
                float2 v;
                v.x = old.x + O[nt][halfq*2+0] * inv;
                v.y = old.y + O[nt][halfq*2+1] * inv;
                *(float2*)&op[d] = v;
            }
        }
    }
}

// fused main attention: writes fp16 (softmax(QK^T)V + softmax(Q bK^T) bV)
__global__ __launch_bounds__(256)
void attn_fused(const float* __restrict__ Qg, const float* __restrict__ Kg,
                const float* __restrict__ Vg, const float* __restrict__ bKg,
                const float* __restrict__ bVg, __half* __restrict__ Og)
{
    extern __shared__ char smem[];
    char* smc = smem;
    const uint32_t sm = smem_u32(smem);

    const int t  = threadIdx.x;
    const int b  = blockIdx.z;
    const int h  = blockIdx.y;
    const int q0 = blockIdx.x * 128;

    const float* Qb  = Qg  + ((long long)b * QLEN)    * CDIM + h * HD;
    const float* Kb  = Kg  + ((long long)b * EHS_LEN) * CDIM + h * HD;
    const float* Vb  = Vg  + ((long long)b * EHS_LEN) * CDIM + h * HD;
    const float* bKb = bKg + ((long long)b * NTOK)    * CDIM + h * HD;
    const float* bVb = bVg + ((long long)b * NTOK)    * CDIM + h * HD;
    __half*      Ob  = Og  + ((long long)b * QLEN)    * CDIM + h * HD;

    att_stage_q(smc, Qb, QLEN, q0, t);
    att_stage_kv(smc, Kb, Vb, EHS_LEN, 128, t);
    __syncthreads();

    const int lane  = t & 31;
    const int wid   = t >> 5;
    const int qbase = wid * 16;

    float O[8][4];
    float mrow[2], lrow[2];
    #pragma unroll
    for (int nt = 0; nt < 8; ++nt)
        #pragma unroll
        for (int e = 0; e < 4; ++e) O[nt][e] = 0.f;
    mrow[0] = mrow[1] = -1e30f;
    lrow[0] = lrow[1] = 0.f;

    att_phase(sm, EHS_LEN, lane, qbase, mrow, lrow, O);

    float Oacc[8][4];
    {
        float inv0 = 1.f / lrow[0];
        float inv1 = 1.f / lrow[1];
        #pragma unroll
        for (int nt = 0; nt < 8; ++nt) {
            Oacc[nt][0] = O[nt][0] * inv0;
            Oacc[nt][1] = O[nt][1] * inv0;
            Oacc[nt][2] = O[nt][2] * inv1;
            Oacc[nt][3] = O[nt][3] * inv1;
            O[nt][0] = O[nt][1] = O[nt][2] = O[nt][3] = 0.f;
        }
        mrow[0] = mrow[1] = -1e30f;
        lrow[0] = lrow[1] = 0.f;
    }

    __syncthreads();
    att_stage_kv(smc, bKb, bVb, NTOK, 256, t);
    __syncthreads();
    att_phase(sm, NTOK, lane, qbase, mrow, lrow, O);

    float inv0 = 1.f / lrow[0];
    float inv1 = 1.f / lrow[1];
    #pragma unroll
    for (int halfq = 0; halfq < 2; ++halfq) {
        int row = q0 + qbase + (lane >> 2) + halfq * 8;
        if (row < QLEN) {
            float inv = halfq ? inv1 : inv0;
            __half* op = Ob + (long long)row * CDIM;
            #pragma unroll
            for (int nt = 0; nt < 8; ++nt) {
                int d = nt * 8 + 2 * (lane & 3);
                float vx = Oacc[nt][halfq*2+0] + O[nt][halfq*2+0] * inv;
                float vy = Oacc[nt][halfq*2+1] + O[nt][halfq*2+1] * inv;
                *(__half2*)&op[d] = __floats2half2_rn(vx, vy);
            }
        }
    }
}

// ---------------- host orchestration ---------------------------------------
static inline void launch_cvt(const float* x, __half* h, long long n)
{
    int n4 = (int)(n / 4);
    int blocks = (n4 + 255) / 256;
    if (blocks > 4096) blocks = 4096;
    cvt_half_kernel<<<blocks, 256>>>((const float4*)x, (__half2*)h, n4);
}

template <typename T>
static inline T* sym(const void* s) { void* p; cudaGetSymbolAddress(&p, s); return (T*)p; }

extern "C" void kernel_launch(void* const* d_in, const int* in_sizes, int n_in,
                              void* d_out, int out_size)
{
    const float* hidden = (const float*)d_in[0];
    const float* enc    = (const float*)d_in[1];
    const float* w_q    = (const float*)d_in[2];
    const float* w_k    = (const float*)d_in[3];
    const float* w_v    = (const float*)d_in[4];
    const float* w_kb   = (const float*)d_in[5];
    const float* w_vb   = (const float*)d_in[6];
    const float* w_kc   = (const float*)d_in[7];
    const float* w_vc   = (const float*)d_in[8];
    const float* w_out  = (const float*)d_in[9];
    const float* b_out  = (const float*)d_in[10];
    float* out = (float*)d_out;

    float* pq  = sym<float>(&g_q);
    float* pk  = sym<float>(&g_k);
    float* pv  = sym<float>(&g_v);
    float* pbk = sym<float>(&g_bk);
    float* pbv = sym<float>(&g_bv);
    float* pck = sym<float>(&g_ck);
    float* pcv = sym<float>(&g_cv);

    __half* hidh = sym<__half>(&a_hid);
    __half* ench = sym<__half>(&a_enc);
    __half* poh  = sym<__half>(&a_po);
    __half* wqh  = sym<__half>(&w_q_h);
    __half* wkh  = sym<__half>(&w_k_h);
    __half* wvh  = sym<__half>(&w_v_h);
    __half* wkbh = sym<__half>(&w_kb_h);
    __half* wvbh = sym<__half>(&w_vb_h);
    __half* wkch = sym<__half>(&w_kc_h);
    __half* wvch = sym<__half>(&w_vc_h);
    __half* woh  = sym<__half>(&w_o_h);

    const long long bsEnc = (long long)LLEN * CROSSD;
    const long long encN  = (long long)B_ * LLEN * CROSSD;
    const long long hidN  = (long long)B_ * QLEN * CDIM;
    const long long boxOff = (long long)EHS_LEN * CROSSD;
    const long long clsOff = (long long)(EHS_LEN + NTOK) * CROSSD;

    cudaFuncSetAttribute(gemm_one,  cudaFuncAttributeMaxDynamicSharedMemorySize, GEMM_SMEM);
    cudaFuncSetAttribute(gemm_pack, cudaFuncAttributeMaxDynamicSharedMemorySize, GEMM_SMEM);
    cudaFuncSetAttribute(attn_pair, cudaFuncAttributeMaxDynamicSharedMemorySize, ATT_SMEM);
    cudaFuncSetAttribute(attn_fused, cudaFuncAttributeMaxDynamicSharedMemorySize, ATT_SMEM);

    // conversions
    launch_cvt(hidden, hidh, hidN);
    launch_cvt(enc, ench, encN);
    launch_cvt(w_q, wqh, (long long)CDIM*CDIM);
    {
        CPack6 cp;
        cp.d[0] = { (const float4*)w_k,  (__half2*)wkh  };
        cp.d[1] = { (const float4*)w_v,  (__half2*)wvh  };
        cp.d[2] = { (const float4*)w_kb, (__half2*)wkbh };
        cp.d[3] = { (const float4*)w_vb, (__half2*)wvbh };
        cp.d[4] = { (const float4*)w_kc, (__half2*)wkch };
        cp.d[5] = { (const float4*)w_vc, (__half2*)wvch };
        dim3 grid(1024, 1, 6);
        cvt_multi<<<grid, 256>>>(cp, CDIM * CROSSD / 4);
    }
    launch_cvt(w_out, woh, (long long)CDIM*CDIM);

    // packed 7-way GEMM (128x256 tiles)
    {
        GPack p;
        const long long sEk = (long long)EHS_LEN*CDIM;
        const long long sNk = (long long)NTOK*CDIM;
        p.d[0] = { hidh,          wqh,  nullptr, pq,  B_*QLEN,    B_*QLEN, 0,     0,   CDIM, CDIM   };
        p.d[1] = { ench,          wkh,  nullptr, pk,  B_*EHS_LEN, EHS_LEN, bsEnc, sEk, CDIM, CROSSD };
        p.d[2] = { ench,          wvh,  nullptr, pv,  B_*EHS_LEN, EHS_LEN, bsEnc, sEk, CDIM, CROSSD };
        p.d[3] = { ench + boxOff, wkbh, nullptr, pbk, B_*NTOK,    NTOK,    bsEnc, sNk, CDIM, CROSSD };
        p.d[4] = { ench + boxOff, wvbh, nullptr, pbv, B_*NTOK,    NTOK,    bsEnc, sNk, CDIM, CROSSD };
        p.d[5] = { ench + clsOff, wkch, nullptr, pck, B_*NTOK,    NTOK,    bsEnc, sNk, CDIM, CROSSD };
        p.d[6] = { ench + clsOff, wvch, nullptr, pcv, B_*NTOK,    NTOK,    bsEnc, sNk, CDIM, CROSSD };
        int acc = 0;
        for (int i = 0; i < 7; ++i) {
            p.start[i] = acc;
            int mt = (p.d[i].Mtot + 127) / 128;
            acc += mt * 5;               // N/256 = 5 tile-pairs
        }
        p.start[7] = acc;
        gemm_pack<<<acc, 256, GEMM_SMEM>>>(p);
    }

    // merged cls attention updates
    {
        dim3 grid((NTOK + 127) / 128, HEADS, 2 * B_);
        attn_pair<<<grid, 256, ATT_SMEM>>>(pbk, pbv, pck, pcv);
    }

    // fused main + box attention -> fp16 a_po
    {
        dim3 grid(QLEN / 128, HEADS, B_);
        attn_fused<<<grid, 256, ATT_SMEM>>>(pq, pk, pv, pbk, pbv, poh);
    }

    // out-projection (1-pass fp16, +bias) into d_out
    {
        GDesc g = { poh, woh, b_out, out, B_*QLEN, B_*QLEN, 0, 0, CDIM, CDIM };
        dim3 grid(CDIM / 256, (B_*QLEN + 127) / 128, 1);
        gemm_one<<<grid, 256, GEMM_SMEM>>>(g);
    }
}